// round 2
// baseline (speedup 1.0000x reference)
#include <cuda_runtime.h>
#include <math.h>

#define B       8192
#define INP     64
#define HID     1024
#define KA      1088          // INP + HID
#define NG      4096          // 4 gates * HID, interleaved n = j*4 + g
#define OMID    128
#define NHEAD   129           // OMID + 1 (halt)
#define MAX_IT  8

#define BM 128
#define BN 128
#define BK 16

// ---------------- device scratch (no runtime allocation allowed) -------------
__device__ float g_A0[B * KA];          // [B][KA]: cols 0..63 = x, 64.. = state
__device__ float g_A1[B * KA];
__device__ float g_cell[B * HID];
__device__ float g_W[KA * NG];          // packed [k][n], n = j*4+g
__device__ float g_bias[NG];            // bx+bh interleaved
__device__ float g_W1t[NHEAD * HID];    // head weights [n][k] (n<128: W1, n=128: W_halt)
__device__ float g_b1h[NHEAD];
__device__ float g_psum[B];
__device__ int   g_active[B];
__device__ int   g_active_count;
__device__ int   g_tile_active[B / BM];

__device__ __forceinline__ float sigf(float z) { return 1.0f / (1.0f + expf(-z)); }

// ---------------- init: zero state/cell/psum, copy x, reset flags ------------
__global__ void k_init(const float* __restrict__ x, float* __restrict__ out) {
    const int row = blockIdx.x;
    const int t = threadIdx.x;                 // 128 threads
    float* a0 = g_A0 + row * KA;
    float* a1 = g_A1 + row * KA;
    if (t < INP) {
        float v = x[row * INP + t];
        a0[t] = v;
        a1[t] = v;
    }
    for (int j = t; j < HID; j += 128) {
        a0[INP + j] = 0.0f;                    // A1 state fully written at t=0
        g_cell[row * HID + j] = 0.0f;
    }
    if (t == 0) {
        g_psum[row] = 0.0f;
        g_active[row] = 1;
        out[row] = 0.0f;
    }
    if (row == 0 && t == 0) g_active_count = B;
    if ((row & (BM - 1)) == 0 && t == 0) g_tile_active[row / BM] = BM;
}

// ---------------- pack weights into fused layouts ----------------------------
__global__ void k_pack(
    const float* __restrict__ Wxi, const float* __restrict__ Whi,
    const float* __restrict__ bxi, const float* __restrict__ bhi,
    const float* __restrict__ Wxf, const float* __restrict__ Whf,
    const float* __restrict__ bxf, const float* __restrict__ bhf,
    const float* __restrict__ Wxc, const float* __restrict__ Whc,
    const float* __restrict__ bxc, const float* __restrict__ bhc,
    const float* __restrict__ Wxo, const float* __restrict__ Who,
    const float* __restrict__ bxo, const float* __restrict__ bho,
    const float* __restrict__ W1,  const float* __restrict__ b1,
    const float* __restrict__ Whalt, const float* __restrict__ bhalt)
{
    int idx = blockIdx.x * blockDim.x + threadIdx.x;
    if (idx < KA * NG) {
        const int n = idx % NG;
        const int k = idx / NG;
        const int g = n & 3;
        const int j = n >> 2;
        const float* Wx = (g == 0) ? Wxi : (g == 1) ? Wxf : (g == 2) ? Wxc : Wxo;
        const float* Wh = (g == 0) ? Whi : (g == 1) ? Whf : (g == 2) ? Whc : Who;
        g_W[idx] = (k < INP) ? Wx[j * INP + k] : Wh[j * HID + (k - INP)];
        return;
    }
    idx -= KA * NG;
    if (idx < NG) {
        const int g = idx & 3;
        const int j = idx >> 2;
        const float* bx = (g == 0) ? bxi : (g == 1) ? bxf : (g == 2) ? bxc : bxo;
        const float* bh = (g == 0) ? bhi : (g == 1) ? bhf : (g == 2) ? bhc : bho;
        g_bias[idx] = bx[j] + bh[j];
        return;
    }
    idx -= NG;
    if (idx < NHEAD * HID) {
        const int n = idx / HID;
        const int k = idx % HID;
        g_W1t[idx] = (n < OMID) ? W1[n * HID + k] : Whalt[k];
        return;
    }
    idx -= NHEAD * HID;
    if (idx < NHEAD) {
        g_b1h[idx] = (idx < OMID) ? b1[idx] : bhalt[0];
    }
}

// ---------------- fused gate GEMM + LSTM pointwise epilogue ------------------
// C[B, NG] = A[B, KA] @ g_W[KA, NG]; epilogue computes cell/state in place.
__global__ __launch_bounds__(256) void k_gates(int t) {
    if (g_active_count == 0) return;
    const int mt = blockIdx.y;
    if (g_tile_active[mt] == 0) return;

    const float* __restrict__ A    = (t & 1) ? g_A1 : g_A0;
    float* __restrict__       Aout = (t & 1) ? g_A0 : g_A1;

    const int m0 = mt * BM;
    const int n0 = blockIdx.x * BN;

    __shared__ float As[BK][BM];
    __shared__ float Ws[BK][BN];

    const int tid = threadIdx.x;
    const int tm = (tid >> 4) << 3;      // 0..120
    const int tn = (tid & 15) << 3;      // 0..120
    const int la_m = tid >> 1;           // 0..127
    const int la_k = (tid & 1) << 3;     // 0 or 8
    const int lw_k = tid >> 4;           // 0..15
    const int lw_n = (tid & 15) << 3;    // 0..120

    float acc[8][8];
#pragma unroll
    for (int i = 0; i < 8; i++)
#pragma unroll
        for (int j = 0; j < 8; j++) acc[i][j] = 0.0f;

    const float* Aptr = A + (m0 + la_m) * KA + la_k;
    const float* Wptr = g_W + lw_k * NG + n0 + lw_n;

    for (int kt = 0; kt < KA; kt += BK) {
        float4 av0 = *(const float4*)(Aptr + kt);
        float4 av1 = *(const float4*)(Aptr + kt + 4);
        float4 wv0 = *(const float4*)(Wptr + (size_t)kt * NG);
        float4 wv1 = *(const float4*)(Wptr + (size_t)kt * NG + 4);

        As[la_k + 0][la_m] = av0.x;
        As[la_k + 1][la_m] = av0.y;
        As[la_k + 2][la_m] = av0.z;
        As[la_k + 3][la_m] = av0.w;
        As[la_k + 4][la_m] = av1.x;
        As[la_k + 5][la_m] = av1.y;
        As[la_k + 6][la_m] = av1.z;
        As[la_k + 7][la_m] = av1.w;
        *(float4*)&Ws[lw_k][lw_n]     = wv0;
        *(float4*)&Ws[lw_k][lw_n + 4] = wv1;
        __syncthreads();

#pragma unroll
        for (int k = 0; k < BK; k++) {
            float ra[8], rb[8];
            *(float4*)&ra[0] = *(const float4*)&As[k][tm];
            *(float4*)&ra[4] = *(const float4*)&As[k][tm + 4];
            *(float4*)&rb[0] = *(const float4*)&Ws[k][tn];
            *(float4*)&rb[4] = *(const float4*)&Ws[k][tn + 4];
#pragma unroll
            for (int i = 0; i < 8; i++)
#pragma unroll
                for (int j = 0; j < 8; j++)
                    acc[i][j] = fmaf(ra[i], rb[j], acc[i][j]);
        }
        __syncthreads();
    }

    // epilogue: this thread's 8 n-columns = hidden units j0, j0+1 (4 gates each)
    float bb[8];
#pragma unroll
    for (int q = 0; q < 8; q++) bb[q] = g_bias[n0 + tn + q];
    const int j0 = (n0 + tn) >> 2;

#pragma unroll
    for (int im = 0; im < 8; im++) {
        const int m = m0 + tm + im;
        if (!g_active[m]) continue;          // inactive rows keep state/cell
#pragma unroll
        for (int jj = 0; jj < 2; jj++) {
            const int j = j0 + jj;
            float ig = sigf (acc[im][jj * 4 + 0] + bb[jj * 4 + 0]);
            float fg = sigf (acc[im][jj * 4 + 1] + bb[jj * 4 + 1]);
            float cg = tanhf(acc[im][jj * 4 + 2] + bb[jj * 4 + 2]);
            float og = sigf (acc[im][jj * 4 + 3] + bb[jj * 4 + 3]);
            float c = fg * g_cell[m * HID + j] + ig * cg;
            g_cell[m * HID + j] = c;
            Aout[m * KA + INP + j] = og * tanhf(c);
        }
    }
}

// ---------------- head: W1/relu/W2/sigmoid + halt logic + accumulate ---------
__global__ __launch_bounds__(128) void k_head(int t,
                                              const float* __restrict__ W2,
                                              const float* __restrict__ b2,
                                              float* __restrict__ out) {
    if (g_active_count == 0) return;
    const int row = blockIdx.x;
    if (!g_active[row]) return;

    // state written by k_gates at iteration t lives in the "other" buffer
    const float* __restrict__ S = ((t & 1) ? g_A0 : g_A1) + row * KA + INP;

    __shared__ float s_state[HID];
    __shared__ float s_m[OMID];
    __shared__ float s_halt;

    const int tid = threadIdx.x;       // 128
    const int lane = tid & 31;
    const int w = tid >> 5;

    for (int j = tid; j < HID; j += 128) s_state[j] = S[j];
    __syncthreads();

    for (int n = w; n < NHEAD; n += 4) {
        const float* Wr = g_W1t + n * HID;
        float a0 = 0.f, a1 = 0.f, a2 = 0.f, a3 = 0.f;
#pragma unroll
        for (int k0 = 0; k0 < HID; k0 += 128) {
            const int k = k0 + lane;
            a0 = fmaf(s_state[k],      Wr[k],      a0);
            a1 = fmaf(s_state[k + 32], Wr[k + 32], a1);
            a2 = fmaf(s_state[k + 64], Wr[k + 64], a2);
            a3 = fmaf(s_state[k + 96], Wr[k + 96], a3);
        }
        float acc = (a0 + a1) + (a2 + a3);
#pragma unroll
        for (int off = 16; off; off >>= 1)
            acc += __shfl_xor_sync(0xffffffffu, acc, off);
        if (lane == 0) {
            acc += g_b1h[n];
            if (n < OMID) s_m[n] = fmaxf(acc, 0.0f);
            else          s_halt = acc;
        }
    }
    __syncthreads();

    if (w == 0) {
        float acc = 0.0f;
#pragma unroll
        for (int k0 = 0; k0 < OMID; k0 += 32)
            acc = fmaf(s_m[k0 + lane], W2[k0 + lane], acc);
#pragma unroll
        for (int off = 16; off; off >>= 1)
            acc += __shfl_xor_sync(0xffffffffu, acc, off);
        if (lane == 0) {
            const float o = sigf(acc + b2[0]);
            const float h = sigf(s_halt);
            const float p = g_psum[row];
            const float pn = p + h;
            const bool fin = (pn >= 1.0f - 0.001f) || (t == MAX_IT - 1);
            const float hr = fin ? (1.0f - p) : h;
            out[row] += o * hr;
            g_psum[row] = fin ? 1.0f : pn;
            if (fin) {
                g_active[row] = 0;
                atomicSub(&g_active_count, 1);
                atomicSub(&g_tile_active[row / BM], 1);
            }
        }
    }
}

// ---------------- launch ------------------------------------------------------
extern "C" void kernel_launch(void* const* d_in, const int* in_sizes, int n_in,
                              void* d_out, int out_size) {
    const float* x     = (const float*)d_in[0];
    const float* Wxi   = (const float*)d_in[1];
    const float* bxi   = (const float*)d_in[2];
    const float* Whi   = (const float*)d_in[3];
    const float* bhi   = (const float*)d_in[4];
    const float* Wxf   = (const float*)d_in[5];
    const float* bxf   = (const float*)d_in[6];
    const float* Whf   = (const float*)d_in[7];
    const float* bhf   = (const float*)d_in[8];
    const float* Wxc   = (const float*)d_in[9];
    const float* bxc   = (const float*)d_in[10];
    const float* Whc   = (const float*)d_in[11];
    const float* bhc   = (const float*)d_in[12];
    const float* Wxo   = (const float*)d_in[13];
    const float* bxo   = (const float*)d_in[14];
    const float* Who   = (const float*)d_in[15];
    const float* bho   = (const float*)d_in[16];
    const float* Whalt = (const float*)d_in[17];
    const float* bhalt = (const float*)d_in[18];
    const float* W1    = (const float*)d_in[19];
    const float* b1    = (const float*)d_in[20];
    const float* W2    = (const float*)d_in[21];
    const float* b2    = (const float*)d_in[22];
    float* out = (float*)d_out;

    k_init<<<B, 128>>>(x, out);

    const int tot = KA * NG + NG + NHEAD * HID + NHEAD;
    k_pack<<<(tot + 255) / 256, 256>>>(Wxi, Whi, bxi, bhi,
                                       Wxf, Whf, bxf, bhf,
                                       Wxc, Whc, bxc, bhc,
                                       Wxo, Who, bxo, bho,
                                       W1, b1, Whalt, bhalt);

    for (int t = 0; t < MAX_IT; t++) {
        k_gates<<<dim3(NG / BN, B / BM), 256>>>(t);
        k_head<<<B, 128>>>(t, W2, b2, out);
    }
}

// round 5
// speedup vs baseline: 1.2309x; 1.2309x over previous
#include <cuda_runtime.h>
#include <math.h>

#define B       8192
#define INP     64
#define HID     1024
#define KA      1088          // INP + HID
#define NG      4096          // 4 gates * HID, interleaved n = j*4 + g
#define OMID    128
#define MAX_IT  8

#define BM 128
#define BN 128
#define BK 16

// ---------------- device scratch (no runtime allocation allowed) -------------
__device__ float g_A0[B * KA];          // [B][KA]: cols 0..63 = x, 64.. = state
__device__ float g_A1[B * KA];
__device__ float g_cell[B * HID];
__device__ float g_W[KA * NG];          // packed [k][n], n = j*4+g
__device__ float g_bias[NG];            // bx+bh interleaved
__device__ float g_W1kn[HID * OMID];    // W1 repacked [k][n]
__device__ float g_Whalt[HID];
__device__ float g_b1h[OMID + 2];       // [0..127]=b1, [128]=b_halt
__device__ float g_psum[B];
__device__ int   g_mapA[B];             // compact active-row maps (ping-pong)
__device__ int   g_mapB[B];
__device__ int   g_cnt[MAX_IT + 1];     // active count entering iteration t

__device__ __forceinline__ float sigf(float z) { return 1.0f / (1.0f + expf(-z)); }

// ---------------- init: zero state/cell/psum, copy x, reset maps -------------
__global__ void k_init(const float* __restrict__ x, float* __restrict__ out) {
    const int row = blockIdx.x;
    const int t = threadIdx.x;                 // 128 threads
    float* a0 = g_A0 + (size_t)row * KA;
    float* a1 = g_A1 + (size_t)row * KA;
    if (t < INP) {
        float v = x[row * INP + t];
        a0[t] = v;
        a1[t] = v;
    }
    for (int j = t; j < HID; j += 128) {
        a0[INP + j] = 0.0f;
        g_cell[(size_t)row * HID + j] = 0.0f;
    }
    if (t == 0) {
        g_psum[row] = 0.0f;
        g_mapA[row] = row;
        out[row] = 0.0f;
    }
    if (row == 0 && t <= MAX_IT) g_cnt[t] = (t == 0) ? B : 0;
}

// ---------------- pack weights into fused layouts ----------------------------
__global__ void k_pack(
    const float* __restrict__ Wxi, const float* __restrict__ Whi,
    const float* __restrict__ bxi, const float* __restrict__ bhi,
    const float* __restrict__ Wxf, const float* __restrict__ Whf,
    const float* __restrict__ bxf, const float* __restrict__ bhf,
    const float* __restrict__ Wxc, const float* __restrict__ Whc,
    const float* __restrict__ bxc, const float* __restrict__ bhc,
    const float* __restrict__ Wxo, const float* __restrict__ Who,
    const float* __restrict__ bxo, const float* __restrict__ bho,
    const float* __restrict__ W1,  const float* __restrict__ b1,
    const float* __restrict__ Whalt, const float* __restrict__ bhalt)
{
    int idx = blockIdx.x * blockDim.x + threadIdx.x;
    if (idx < KA * NG) {
        const int n = idx % NG;
        const int k = idx / NG;
        const int g = n & 3;
        const int j = n >> 2;
        const float* Wx = (g == 0) ? Wxi : (g == 1) ? Wxf : (g == 2) ? Wxc : Wxo;
        const float* Wh = (g == 0) ? Whi : (g == 1) ? Whf : (g == 2) ? Whc : Who;
        g_W[idx] = (k < INP) ? Wx[j * INP + k] : Wh[j * HID + (k - INP)];
        return;
    }
    idx -= KA * NG;
    if (idx < NG) {
        const int g = idx & 3;
        const int j = idx >> 2;
        const float* bx = (g == 0) ? bxi : (g == 1) ? bxf : (g == 2) ? bxc : bxo;
        const float* bh = (g == 0) ? bhi : (g == 1) ? bhf : (g == 2) ? bhc : bho;
        g_bias[idx] = bx[j] + bh[j];
        return;
    }
    idx -= NG;
    if (idx < HID * OMID) {
        const int k = idx / OMID;
        const int n = idx % OMID;
        g_W1kn[idx] = W1[n * HID + k];
        return;
    }
    idx -= HID * OMID;
    if (idx < HID) {
        g_Whalt[idx] = Whalt[idx];
        return;
    }
    idx -= HID;
    if (idx < OMID) { g_b1h[idx] = b1[idx]; return; }
    idx -= OMID;
    if (idx == 0) g_b1h[OMID] = bhalt[0];
}

// ---------------- fused gate GEMM + LSTM pointwise epilogue ------------------
// Operates on compacted active rows via g_map; C = A[rows, KA] @ g_W[KA, NG].
__global__ __launch_bounds__(256) void k_gates(int t) {
    const int count = g_cnt[t];
    const int mt = blockIdx.y;
    const int m0 = mt * BM;
    if (m0 >= count) return;

    const float* __restrict__ A    = (t & 1) ? g_A1 : g_A0;
    float* __restrict__       Aout = (t & 1) ? g_A0 : g_A1;
    const int* __restrict__   map  = (t & 1) ? g_mapB : g_mapA;

    const int n0 = blockIdx.x * BN;

    __shared__ float As[BK][BM];
    __shared__ float Ws[BK][BN];
    __shared__ int   sRow[BM];

    const int tid = threadIdx.x;
    if (tid < BM) sRow[tid] = map[min(m0 + tid, count - 1)];
    __syncthreads();

    const int tm = (tid >> 4) << 3;      // 0..120
    const int tn = (tid & 15) << 3;      // 0..120
    const int la_m = tid >> 1;           // 0..127
    const int la_k = (tid & 1) << 3;     // 0 or 8
    const int lw_k = tid >> 4;           // 0..15
    const int lw_n = (tid & 15) << 3;    // 0..120

    float acc[8][8];
#pragma unroll
    for (int i = 0; i < 8; i++)
#pragma unroll
        for (int j = 0; j < 8; j++) acc[i][j] = 0.0f;

    const float* Aptr = A + (size_t)sRow[la_m] * KA + la_k;
    const float* Wptr = g_W + lw_k * NG + n0 + lw_n;

    for (int kt = 0; kt < KA; kt += BK) {
        float4 av0 = *(const float4*)(Aptr + kt);
        float4 av1 = *(const float4*)(Aptr + kt + 4);
        float4 wv0 = *(const float4*)(Wptr + (size_t)kt * NG);
        float4 wv1 = *(const float4*)(Wptr + (size_t)kt * NG + 4);

        As[la_k + 0][la_m] = av0.x;
        As[la_k + 1][la_m] = av0.y;
        As[la_k + 2][la_m] = av0.z;
        As[la_k + 3][la_m] = av0.w;
        As[la_k + 4][la_m] = av1.x;
        As[la_k + 5][la_m] = av1.y;
        As[la_k + 6][la_m] = av1.z;
        As[la_k + 7][la_m] = av1.w;
        *(float4*)&Ws[lw_k][lw_n]     = wv0;
        *(float4*)&Ws[lw_k][lw_n + 4] = wv1;
        __syncthreads();

#pragma unroll
        for (int k = 0; k < BK; k++) {
            float ra[8], rb[8];
            *(float4*)&ra[0] = *(const float4*)&As[k][tm];
            *(float4*)&ra[4] = *(const float4*)&As[k][tm + 4];
            *(float4*)&rb[0] = *(const float4*)&Ws[k][tn];
            *(float4*)&rb[4] = *(const float4*)&Ws[k][tn + 4];
#pragma unroll
            for (int i = 0; i < 8; i++)
#pragma unroll
                for (int j = 0; j < 8; j++)
                    acc[i][j] = fmaf(ra[i], rb[j], acc[i][j]);
        }
        __syncthreads();
    }

    float bb[8];
#pragma unroll
    for (int q = 0; q < 8; q++) bb[q] = g_bias[n0 + tn + q];
    const int j0 = (n0 + tn) >> 2;

#pragma unroll
    for (int im = 0; im < 8; im++) {
        const int mm = m0 + tm + im;
        if (mm >= count) continue;
        const int rowg = sRow[tm + im];
#pragma unroll
        for (int jj = 0; jj < 2; jj++) {
            const int j = j0 + jj;
            float ig = sigf (acc[im][jj * 4 + 0] + bb[jj * 4 + 0]);
            float fg = sigf (acc[im][jj * 4 + 1] + bb[jj * 4 + 1]);
            float cg = tanhf(acc[im][jj * 4 + 2] + bb[jj * 4 + 2]);
            float og = sigf (acc[im][jj * 4 + 3] + bb[jj * 4 + 3]);
            float c = fg * g_cell[(size_t)rowg * HID + j] + ig * cg;
            g_cell[(size_t)rowg * HID + j] = c;
            Aout[(size_t)rowg * KA + INP + j] = og * tanhf(c);
        }
    }
}

// ---------------- head: 64 rows/block GEMM + W2/halt finalize + compaction ---
#define HM 64
__global__ __launch_bounds__(256) void k_head(int t,
                                              const float* __restrict__ W2,
                                              const float* __restrict__ b2,
                                              float* __restrict__ out) {
    const int count = g_cnt[t];
    const int base = blockIdx.x * HM;
    if (base >= count) return;

    const float* __restrict__ Abuf = (t & 1) ? g_A0 : g_A1;  // state after k_gates(t)
    const int* __restrict__ map    = (t & 1) ? g_mapB : g_mapA;
    int* __restrict__ map_next     = (t & 1) ? g_mapA : g_mapB;

    __shared__ float sA[BK][HM + 4];
    __shared__ float sW[BK][OMID];
    __shared__ float sMid[HM][OMID];
    __shared__ int   sRow[HM];

    const int tid = threadIdx.x;      // 256
    if (tid < HM) sRow[tid] = map[min(base + tid, count - 1)];
    __syncthreads();

    // ---- phase 1: mid = relu(state @ W1^T + b1), tiled GEMM 64x128xK ----
    const int lr = tid >> 2;          // 0..63  (A row)
    const int lk = (tid & 3) << 2;    // 0,4,8,12
    const int wk = tid >> 4;          // 0..15  (W k)
    const int wn = (tid & 15) << 3;   // 0..120
    const int tm = (tid >> 4) << 2;   // 0..60
    const int tn = (tid & 15) << 3;   // 0..120

    float acc[4][8];
#pragma unroll
    for (int i = 0; i < 4; i++)
#pragma unroll
        for (int j = 0; j < 8; j++) acc[i][j] = 0.0f;

    const float* Arow = Abuf + (size_t)sRow[lr] * KA + INP + lk;

    for (int k0 = 0; k0 < HID; k0 += BK) {
        float4 a = *(const float4*)(Arow + k0);
        float4 w0 = *(const float4*)(g_W1kn + (k0 + wk) * OMID + wn);
        float4 w1 = *(const float4*)(g_W1kn + (k0 + wk) * OMID + wn + 4);
        sA[lk + 0][lr] = a.x;
        sA[lk + 1][lr] = a.y;
        sA[lk + 2][lr] = a.z;
        sA[lk + 3][lr] = a.w;
        *(float4*)&sW[wk][wn]     = w0;
        *(float4*)&sW[wk][wn + 4] = w1;
        __syncthreads();
#pragma unroll
        for (int k = 0; k < BK; k++) {
            float ra[4], rb[8];
            *(float4*)&ra[0] = *(const float4*)&sA[k][tm];
            *(float4*)&rb[0] = *(const float4*)&sW[k][tn];
            *(float4*)&rb[4] = *(const float4*)&sW[k][tn + 4];
#pragma unroll
            for (int i = 0; i < 4; i++)
#pragma unroll
                for (int j = 0; j < 8; j++)
                    acc[i][j] = fmaf(ra[i], rb[j], acc[i][j]);
        }
        __syncthreads();
    }

#pragma unroll
    for (int i = 0; i < 4; i++) {
        float4 v0, v1;
        v0.x = fmaxf(acc[i][0] + g_b1h[tn + 0], 0.0f);
        v0.y = fmaxf(acc[i][1] + g_b1h[tn + 1], 0.0f);
        v0.z = fmaxf(acc[i][2] + g_b1h[tn + 2], 0.0f);
        v0.w = fmaxf(acc[i][3] + g_b1h[tn + 3], 0.0f);
        v1.x = fmaxf(acc[i][4] + g_b1h[tn + 4], 0.0f);
        v1.y = fmaxf(acc[i][5] + g_b1h[tn + 5], 0.0f);
        v1.z = fmaxf(acc[i][6] + g_b1h[tn + 6], 0.0f);
        v1.w = fmaxf(acc[i][7] + g_b1h[tn + 7], 0.0f);
        *(float4*)&sMid[tm + i][tn]     = v0;
        *(float4*)&sMid[tm + i][tn + 4] = v1;
    }
    __syncthreads();

    // ---- phase 2: per-row W2 dot + halt dot + halting state machine ----
    const int w = tid >> 5;
    const int lane = tid & 31;
    const float4 w2v = *(const float4*)(W2 + lane * 4);

#pragma unroll
    for (int i = 0; i < 8; i++) {
        const int r = w * 8 + i;
        const int mm = base + r;
        if (mm >= count) continue;
        const int rowg = sRow[r];

        float4 mv = *(const float4*)&sMid[r][lane * 4];
        float acc2 = mv.x * w2v.x + mv.y * w2v.y + mv.z * w2v.z + mv.w * w2v.w;

        const float* S = Abuf + (size_t)rowg * KA + INP;
        float h0 = 0.f, h1 = 0.f, h2 = 0.f, h3 = 0.f;
#pragma unroll
        for (int k0 = 0; k0 < HID; k0 += 128) {
            const int k = k0 + lane;
            h0 = fmaf(S[k],      g_Whalt[k],      h0);
            h1 = fmaf(S[k + 32], g_Whalt[k + 32], h1);
            h2 = fmaf(S[k + 64], g_Whalt[k + 64], h2);
            h3 = fmaf(S[k + 96], g_Whalt[k + 96], h3);
        }
        float hacc = (h0 + h1) + (h2 + h3);
#pragma unroll
        for (int off = 16; off; off >>= 1) {
            acc2 += __shfl_xor_sync(0xffffffffu, acc2, off);
            hacc += __shfl_xor_sync(0xffffffffu, hacc, off);
        }
        if (lane == 0) {
            const float o = sigf(acc2 + b2[0]);
            const float h = sigf(hacc + g_b1h[OMID]);
            const float p = g_psum[rowg];
            const float pn = p + h;
            const bool fin = (pn >= 1.0f - 0.001f) || (t == MAX_IT - 1);
            const float hr = fin ? (1.0f - p) : h;
            out[rowg] += o * hr;
            g_psum[rowg] = fin ? 1.0f : pn;
            if (!fin) {
                int slot = atomicAdd(&g_cnt[t + 1], 1);
                map_next[slot] = rowg;
            }
        }
    }
}

// ---------------- launch ------------------------------------------------------
extern "C" void kernel_launch(void* const* d_in, const int* in_sizes, int n_in,
                              void* d_out, int out_size) {
    const float* x     = (const float*)d_in[0];
    const float* Wxi   = (const float*)d_in[1];
    const float* bxi   = (const float*)d_in[2];
    const float* Whi   = (const float*)d_in[3];
    const float* bhi   = (const float*)d_in[4];
    const float* Wxf   = (const float*)d_in[5];
    const float* bxf   = (const float*)d_in[6];
    const float* Whf   = (const float*)d_in[7];
    const float* bhf   = (const float*)d_in[8];
    const float* Wxc   = (const float*)d_in[9];
    const float* bxc   = (const float*)d_in[10];
    const float* Whc   = (const float*)d_in[11];
    const float* bhc   = (const float*)d_in[12];
    const float* Wxo   = (const float*)d_in[13];
    const float* bxo   = (const float*)d_in[14];
    const float* Who   = (const float*)d_in[15];
    const float* bho   = (const float*)d_in[16];
    const float* Whalt = (const float*)d_in[17];
    const float* bhalt = (const float*)d_in[18];
    const float* W1    = (const float*)d_in[19];
    const float* b1    = (const float*)d_in[20];
    const float* W2    = (const float*)d_in[21];
    const float* b2    = (const float*)d_in[22];
    float* out = (float*)d_out;

    k_init<<<B, 128>>>(x, out);

    const int tot = KA * NG + NG + HID * OMID + HID + OMID + 1;
    k_pack<<<(tot + 255) / 256, 256>>>(Wxi, Whi, bxi, bhi,
                                       Wxf, Whf, bxf, bhf,
                                       Wxc, Whc, bxc, bhc,
                                       Wxo, Who, bxo, bho,
                                       W1, b1, Whalt, bhalt);

    for (int t = 0; t < MAX_IT; t++) {
        k_gates<<<dim3(NG / BN, B / BM), 256>>>(t);
        k_head<<<B / HM, 256>>>(t, W2, b2, out);
    }
}

// round 7
// speedup vs baseline: 1.9191x; 1.5591x over previous
#include <cuda_runtime.h>
#include <cuda_bf16.h>
#include <math.h>
#include <stdint.h>

#define B       8192
#define INP     64
#define HID     1024
#define KA      1088          // INP + HID
#define NG      4096          // 4 gates * HID, interleaved n = j*4 + g
#define OMID    128
#define MAX_IT  8

#define BM 128
#define BN 128
#define CHUNKS 17             // K chunks of 64
#define NTILES (NG / BN)      // 32
#define IMG_BLK 8192          // bf16 elements per (ntile, chunk) image block (128x64)
#define STAGE_STRIDE 65536    // Ah/Al/Wh/Wl = 4 x 16KB per stage
#define SMEM_DYN 133120
#define CSTRIDE 132           // fp32 C tile row stride (conflict-free)

// ---------------- device scratch ---------------------------------------------
__device__ __nv_bfloat16 g_A0hi[B * KA];
__device__ __nv_bfloat16 g_A0lo[B * KA];
__device__ __nv_bfloat16 g_A1hi[B * KA];
__device__ __nv_bfloat16 g_A1lo[B * KA];
__device__ float         g_cell[B * HID];
__device__ __nv_bfloat16 g_Whi_img[NTILES * CHUNKS * IMG_BLK];
__device__ __nv_bfloat16 g_Wlo_img[NTILES * CHUNKS * IMG_BLK];
__device__ float         g_bias[NG];
__device__ float         g_W1kn[HID * OMID];
__device__ float         g_Whalt[HID];
__device__ float         g_b1h[OMID + 2];
__device__ float         g_psum[B];
__device__ int           g_mapA[B];
__device__ int           g_mapB[B];
__device__ int           g_cnt[MAX_IT + 1];

__device__ __forceinline__ float sigf(float z) { return 1.0f / (1.0f + expf(-z)); }

// ---------------- PTX helpers (base ISA only, no 'a'-target features) ---------
__device__ __forceinline__ uint32_t smem_u32(const void* p) {
    uint32_t a;
    asm("{ .reg .u64 t; cvta.to.shared.u64 t, %1; cvt.u32.u64 %0, t; }" : "=r"(a) : "l"(p));
    return a;
}
__device__ __forceinline__ void cp16(uint32_t dst, const void* src) {
    asm volatile("cp.async.cg.shared.global [%0], [%1], 16;" :: "r"(dst), "l"(src));
}
#define CP_COMMIT() asm volatile("cp.async.commit_group;" ::: "memory")
#define CP_WAIT(n)  asm volatile("cp.async.wait_group %0;" :: "n"(n) : "memory")

#define LDM4(r, addr) \
    asm volatile("ldmatrix.sync.aligned.m8n8.x4.shared.b16 {%0,%1,%2,%3}, [%4];" \
        : "=r"((r)[0]), "=r"((r)[1]), "=r"((r)[2]), "=r"((r)[3]) : "r"(addr))

#define MMA16816(acc, a, b0v, b1v) \
    asm volatile("mma.sync.aligned.m16n8k16.row.col.f32.bf16.bf16.f32 " \
        "{%0,%1,%2,%3}, {%4,%5,%6,%7}, {%8,%9}, {%0,%1,%2,%3};" \
        : "+f"((acc)[0]), "+f"((acc)[1]), "+f"((acc)[2]), "+f"((acc)[3]) \
        : "r"((a)[0]), "r"((a)[1]), "r"((a)[2]), "r"((a)[3]), "r"(b0v), "r"(b1v))

__device__ __forceinline__ unsigned short bfu(__nv_bfloat16 v) {
    return *reinterpret_cast<unsigned short*>(&v);
}

// ---------------- init --------------------------------------------------------
__global__ void k_init(const float* __restrict__ x, float* __restrict__ out) {
    const int row = blockIdx.x;
    const int t = threadIdx.x;                 // 128 threads
    const size_t ra = (size_t)row * KA;
    const __nv_bfloat16 z = __float2bfloat16(0.0f);
    if (t < INP) {
        float v = x[row * INP + t];
        __nv_bfloat16 hi = __float2bfloat16(v);
        __nv_bfloat16 lo = __float2bfloat16(v - __bfloat162float(hi));
        g_A0hi[ra + t] = hi; g_A0lo[ra + t] = lo;
        g_A1hi[ra + t] = hi; g_A1lo[ra + t] = lo;
    }
    for (int j = t; j < HID; j += 128) {
        g_A0hi[ra + INP + j] = z;
        g_A0lo[ra + INP + j] = z;
        g_cell[(size_t)row * HID + j] = 0.0f;
    }
    if (t == 0) {
        g_psum[row] = 0.0f;
        g_mapA[row] = row;
        out[row] = 0.0f;
    }
    if (row == 0 && t <= MAX_IT) g_cnt[t] = (t == 0) ? B : 0;
}

// ---------------- pack weights ------------------------------------------------
__global__ void k_pack(
    const float* __restrict__ Wxi, const float* __restrict__ Whi,
    const float* __restrict__ bxi, const float* __restrict__ bhi,
    const float* __restrict__ Wxf, const float* __restrict__ Whf,
    const float* __restrict__ bxf, const float* __restrict__ bhf,
    const float* __restrict__ Wxc, const float* __restrict__ Whc,
    const float* __restrict__ bxc, const float* __restrict__ bhc,
    const float* __restrict__ Wxo, const float* __restrict__ Who,
    const float* __restrict__ bxo, const float* __restrict__ bho,
    const float* __restrict__ W1,  const float* __restrict__ b1,
    const float* __restrict__ Whalt, const float* __restrict__ bhalt)
{
    int idx = blockIdx.x * blockDim.x + threadIdx.x;
    if (idx < KA * NG) {
        const int n = idx / KA;
        const int k = idx % KA;
        const int g = n & 3;
        const int j = n >> 2;
        const float* Wx = (g == 0) ? Wxi : (g == 1) ? Wxf : (g == 2) ? Wxc : Wxo;
        const float* Wh = (g == 0) ? Whi : (g == 1) ? Whf : (g == 2) ? Whc : Who;
        const float w = (k < INP) ? Wx[j * INP + k] : Wh[j * HID + (k - INP)];
        __nv_bfloat16 hi = __float2bfloat16(w);
        __nv_bfloat16 lo = __float2bfloat16(w - __bfloat162float(hi));
        // image layout: [tile][chunk] blocks of 128 n-rows x 64 k, 128B rows,
        // XOR-swizzled so 8 consecutive n-rows hit distinct 16B banks.
        const int T = n >> 7, nr = n & 127, C = k >> 6, kc = k & 63;
        const unsigned byte = (unsigned)(nr * 128 + kc * 2);
        const unsigned off = (unsigned)((T * CHUNKS + C) * IMG_BLK)
                           + ((byte ^ (((unsigned)(nr & 7)) << 4)) >> 1);
        g_Whi_img[off] = hi;
        g_Wlo_img[off] = lo;
        return;
    }
    idx -= KA * NG;
    if (idx < NG) {
        const int g = idx & 3;
        const int j = idx >> 2;
        const float* bx = (g == 0) ? bxi : (g == 1) ? bxf : (g == 2) ? bxc : bxo;
        const float* bh = (g == 0) ? bhi : (g == 1) ? bhf : (g == 2) ? bhc : bho;
        g_bias[idx] = bx[j] + bh[j];
        return;
    }
    idx -= NG;
    if (idx < HID * OMID) {
        const int k = idx / OMID;
        const int n = idx % OMID;
        g_W1kn[idx] = W1[n * HID + k];
        return;
    }
    idx -= HID * OMID;
    if (idx < HID) { g_Whalt[idx] = Whalt[idx]; return; }
    idx -= HID;
    if (idx < OMID) { g_b1h[idx] = b1[idx]; return; }
    idx -= OMID;
    if (idx == 0) g_b1h[OMID] = bhalt[0];
}

// ---------------- mma.sync bf16-split gate GEMM + LSTM epilogue ---------------
__global__ __launch_bounds__(256, 1) void k_gates(int t) {
    extern __shared__ char smem[];
    __shared__ int sRow[BM];

    const int count = g_cnt[t];
    const int m0 = blockIdx.y * BM;
    if (m0 >= count) return;
    const int n0 = blockIdx.x * BN;
    const int tid = threadIdx.x;
    const int wrp = tid >> 5;
    const int lane = tid & 31;

    const uint32_t sb0 = smem_u32(smem);
    const uint32_t tiles = (sb0 + 1023) & ~1023u;
    char* tilesPtr = smem + (tiles - sb0);

    const int* map = (t & 1) ? g_mapB : g_mapA;
    if (tid < BM) sRow[tid] = map[min(m0 + tid, count - 1)];
    __syncthreads();

    const __nv_bfloat16* Ahi = (t & 1) ? g_A1hi : g_A0hi;
    const __nv_bfloat16* Alo = (t & 1) ? g_A1lo : g_A0lo;
    __nv_bfloat16* Aout_hi = (t & 1) ? g_A0hi : g_A1hi;
    __nv_bfloat16* Aout_lo = (t & 1) ? g_A0lo : g_A1lo;

    // ---- load indexing: thread loads one A row (hi or lo) + 8 W chunks ----
    const int arow = tid & 127;
    const int asel = tid >> 7;              // 0 = hi, 1 = lo
    const int myArowG = sRow[arow];
    const char* pA = (const char*)((asel ? Alo : Ahi) + (size_t)myArowG * KA);
    const uint32_t aswz = (uint32_t)(arow & 7) << 4;
    const uint32_t aDstRow = (uint32_t)arow * 128 + (asel ? 16384u : 0u);
    const char* pWh = (const char*)g_Whi_img + (size_t)blockIdx.x * (CHUNKS * IMG_BLK * 2);
    const char* pWl = (const char*)g_Wlo_img + (size_t)blockIdx.x * (CHUNKS * IMG_BLK * 2);

    auto load_chunk = [&](int c, int stage) {
        const uint32_t tb = tiles + (uint32_t)stage * STAGE_STRIDE;
        const char* src = pA + c * 128;
#pragma unroll
        for (int u = 0; u < 8; u++)
            cp16(tb + aDstRow + (((uint32_t)(u * 16)) ^ aswz), src + u * 16);
        const char* wh = pWh + c * 16384;
        const char* wl = pWl + c * 16384;
#pragma unroll
        for (int q = 0; q < 4; q++) {
            const uint32_t o = (uint32_t)(tid + q * 256) << 4;
            cp16(tb + 32768 + o, wh + o);
            cp16(tb + 49152 + o, wl + o);
        }
        CP_COMMIT();
    };

    // ---- mma fragment addressing (per-thread constants) ----
    const int wm = (wrp & 1) * 64;          // warp tile m (2 x 64)
    const int wn = (wrp >> 1) * 32;         // warp tile n (4 x 32)
    const uint32_t fswz = (uint32_t)(lane & 7) << 4;
    const uint32_t aRowOff = (uint32_t)(wm + (lane & 15)) * 128;
    const uint32_t aKsel = (uint32_t)(lane >> 4) * 16;              // bytes
    const uint32_t bRowOff = (uint32_t)(wn + (lane & 7) + ((lane >> 4) << 3)) * 128;
    const uint32_t bKsel = (uint32_t)((lane >> 3) & 1) * 16;        // bytes

    float acc[4][4][4];
#pragma unroll
    for (int mi = 0; mi < 4; mi++)
#pragma unroll
        for (int nj = 0; nj < 4; nj++)
#pragma unroll
            for (int e = 0; e < 4; e++) acc[mi][nj][e] = 0.0f;

    load_chunk(0, 0);
    for (int c = 0; c < CHUNKS; c++) {
        const int stage = c & 1;
        if (c + 1 < CHUNKS) { load_chunk(c + 1, stage ^ 1); CP_WAIT(1); }
        else                { CP_WAIT(0); }
        __syncthreads();

        const uint32_t tb = tiles + (uint32_t)stage * STAGE_STRIDE;
        const uint32_t ahB = tb + aRowOff;
        const uint32_t alB = tb + 16384 + aRowOff;
        const uint32_t whB = tb + 32768 + bRowOff;
        const uint32_t wlB = tb + 49152 + bRowOff;

#pragma unroll
        for (int ks = 0; ks < 4; ks++) {
            const uint32_t ak = ((uint32_t)(ks * 32) + aKsel) ^ fswz;
            const uint32_t bk = ((uint32_t)(ks * 32) + bKsel) ^ fswz;
            uint32_t ah[4][4], al[4][4], bh[2][4], bl[2][4];
#pragma unroll
            for (int mi = 0; mi < 4; mi++) {
                LDM4(ah[mi], ahB + mi * 2048 + ak);
                LDM4(al[mi], alB + mi * 2048 + ak);
            }
#pragma unroll
            for (int ni = 0; ni < 2; ni++) {
                LDM4(bh[ni], whB + ni * 2048 + bk);
                LDM4(bl[ni], wlB + ni * 2048 + bk);
            }
#pragma unroll
            for (int mi = 0; mi < 4; mi++)
#pragma unroll
                for (int nj = 0; nj < 4; nj++) {
                    const int ni = nj >> 1, pr = (nj & 1) * 2;
                    MMA16816(acc[mi][nj], ah[mi], bh[ni][pr], bh[ni][pr + 1]);
                    MMA16816(acc[mi][nj], ah[mi], bl[ni][pr], bl[ni][pr + 1]);
                    MMA16816(acc[mi][nj], al[mi], bh[ni][pr], bh[ni][pr + 1]);
                }
        }
        __syncthreads();
    }

    // ---- spill accumulators to smem C tile (overlays stage buffers) ----
    float* C = (float*)tilesPtr;
    {
        const int r0 = wm + (lane >> 2);
        const int c0 = wn + 2 * (lane & 3);
#pragma unroll
        for (int mi = 0; mi < 4; mi++)
#pragma unroll
            for (int nj = 0; nj < 4; nj++) {
                float* p = C + (r0 + mi * 16) * CSTRIDE + c0 + nj * 8;
                p[0] = acc[mi][nj][0];
                p[1] = acc[mi][nj][1];
                p[8 * CSTRIDE]     = acc[mi][nj][2];
                p[8 * CSTRIDE + 1] = acc[mi][nj][3];
            }
    }
    __syncthreads();

    // ---- LSTM pointwise epilogue: thread = (row, half of 32 units) ----
    const int row = tid & 127;
    const int hlf = tid >> 7;
    if (m0 + row < count) {
        const int rowg = sRow[row];
        const float* Crow = C + row * CSTRIDE + hlf * 64;
        const float* bb = g_bias + n0 + hlf * 64;
        const int j0 = (n0 >> 2) + hlf * 16;
        float* cellp = g_cell + (size_t)rowg * HID + j0;
        uint32_t hp[8], lp[8];
#pragma unroll
        for (int u = 0; u < 16; u++) {
            const float4 gv = *(const float4*)(Crow + u * 4);
            const float ig = sigf (gv.x + bb[u * 4 + 0]);
            const float fg = sigf (gv.y + bb[u * 4 + 1]);
            const float cg = tanhf(gv.z + bb[u * 4 + 2]);
            const float og = sigf (gv.w + bb[u * 4 + 3]);
            const float c2 = fg * cellp[u] + ig * cg;
            cellp[u] = c2;
            const float s = og * tanhf(c2);
            const __nv_bfloat16 hi = __float2bfloat16(s);
            const __nv_bfloat16 lo = __float2bfloat16(s - __bfloat162float(hi));
            const uint32_t hu = bfu(hi), lu = bfu(lo);
            if (u & 1) { hp[u >> 1] |= hu << 16; lp[u >> 1] |= lu << 16; }
            else       { hp[u >> 1] = hu;        lp[u >> 1] = lu; }
        }
        uint4* sh = (uint4*)(Aout_hi + (size_t)rowg * KA + INP + j0);
        uint4* sl = (uint4*)(Aout_lo + (size_t)rowg * KA + INP + j0);
        sh[0] = make_uint4(hp[0], hp[1], hp[2], hp[3]);
        sh[1] = make_uint4(hp[4], hp[5], hp[6], hp[7]);
        sl[0] = make_uint4(lp[0], lp[1], lp[2], lp[3]);
        sl[1] = make_uint4(lp[4], lp[5], lp[6], lp[7]);
    }
}

// ---------------- head: 32 rows/block GEMM + W2/halt + compaction -------------
#define HM 32
__global__ __launch_bounds__(256) void k_head(int t,
                                              const float* __restrict__ W2,
                                              const float* __restrict__ b2,
                                              float* __restrict__ out) {
    const int count = g_cnt[t];
    const int base = blockIdx.x * HM;
    if (base >= count) return;

    const __nv_bfloat16* Ahi = (t & 1) ? g_A0hi : g_A1hi;  // state after k_gates(t)
    const __nv_bfloat16* Alo = (t & 1) ? g_A0lo : g_A1lo;
    const int* map = (t & 1) ? g_mapB : g_mapA;
    int* map_next  = (t & 1) ? g_mapA : g_mapB;

    __shared__ float sA[16][HM + 4];
    __shared__ float sW[16][OMID];
    __shared__ float sMid[HM][OMID];
    __shared__ int   sRow[HM];

    const int tid = threadIdx.x;      // 256
    if (tid < HM) sRow[tid] = map[min(base + tid, count - 1)];
    __syncthreads();

    const int ar = tid >> 3;          // 0..31
    const int ak = (tid & 7) << 1;    // 0..14
    const int wk = tid >> 4;          // 0..15
    const int wn = (tid & 15) << 3;
    const int tm = (tid >> 4) << 1;   // 0..30
    const int tn = (tid & 15) << 3;

    float acc[2][8];
#pragma unroll
    for (int i = 0; i < 2; i++)
#pragma unroll
        for (int j = 0; j < 8; j++) acc[i][j] = 0.0f;

    const char* pAh = (const char*)(Ahi + (size_t)sRow[ar] * KA + INP + ak);
    const char* pAl = (const char*)(Alo + (size_t)sRow[ar] * KA + INP + ak);

    for (int k0 = 0; k0 < HID; k0 += 16) {
        const uint32_t uh = *(const uint32_t*)(pAh + k0 * 2);
        const uint32_t ul = *(const uint32_t*)(pAl + k0 * 2);
        const float2 fh = __bfloat1622float2(*(const __nv_bfloat162*)&uh);
        const float2 fl = __bfloat1622float2(*(const __nv_bfloat162*)&ul);
        const float4 w0 = *(const float4*)(g_W1kn + (k0 + wk) * OMID + wn);
        const float4 w1 = *(const float4*)(g_W1kn + (k0 + wk) * OMID + wn + 4);
        sA[ak][ar]     = fh.x + fl.x;
        sA[ak + 1][ar] = fh.y + fl.y;
        *(float4*)&sW[wk][wn]     = w0;
        *(float4*)&sW[wk][wn + 4] = w1;
        __syncthreads();
#pragma unroll
        for (int k = 0; k < 16; k++) {
            const float ra0 = sA[k][tm], ra1 = sA[k][tm + 1];
            float rb[8];
            *(float4*)&rb[0] = *(const float4*)&sW[k][tn];
            *(float4*)&rb[4] = *(const float4*)&sW[k][tn + 4];
#pragma unroll
            for (int j = 0; j < 8; j++) {
                acc[0][j] = fmaf(ra0, rb[j], acc[0][j]);
                acc[1][j] = fmaf(ra1, rb[j], acc[1][j]);
            }
        }
        __syncthreads();
    }

#pragma unroll
    for (int i = 0; i < 2; i++) {
        float4 v0, v1;
        v0.x = fmaxf(acc[i][0] + g_b1h[tn + 0], 0.0f);
        v0.y = fmaxf(acc[i][1] + g_b1h[tn + 1], 0.0f);
        v0.z = fmaxf(acc[i][2] + g_b1h[tn + 2], 0.0f);
        v0.w = fmaxf(acc[i][3] + g_b1h[tn + 3], 0.0f);
        v1.x = fmaxf(acc[i][4] + g_b1h[tn + 4], 0.0f);
        v1.y = fmaxf(acc[i][5] + g_b1h[tn + 5], 0.0f);
        v1.z = fmaxf(acc[i][6] + g_b1h[tn + 6], 0.0f);
        v1.w = fmaxf(acc[i][7] + g_b1h[tn + 7], 0.0f);
        *(float4*)&sMid[tm + i][tn]     = v0;
        *(float4*)&sMid[tm + i][tn + 4] = v1;
    }
    __syncthreads();

    const int w = tid >> 5;
    const int lane = tid & 31;
    const float4 w2v = *(const float4*)(W2 + lane * 4);

#pragma unroll
    for (int i = 0; i < 4; i++) {
        const int r = w * 4 + i;
        const int mm = base + r;
        if (mm >= count) continue;
        const int rowg = sRow[r];

        const float4 mv = *(const float4*)&sMid[r][lane * 4];
        float acc2 = mv.x * w2v.x + mv.y * w2v.y + mv.z * w2v.z + mv.w * w2v.w;

        const __nv_bfloat16* Sh = Ahi + (size_t)rowg * KA + INP;
        const __nv_bfloat16* Sl = Alo + (size_t)rowg * KA + INP;
        float hacc = 0.0f;
#pragma unroll
        for (int k0 = 0; k0 < HID; k0 += 32) {
            const int k = k0 + lane;
            const float s = __bfloat162float(Sh[k]) + __bfloat162float(Sl[k]);
            hacc = fmaf(s, g_Whalt[k], hacc);
        }
#pragma unroll
        for (int off = 16; off; off >>= 1) {
            acc2 += __shfl_xor_sync(0xffffffffu, acc2, off);
            hacc += __shfl_xor_sync(0xffffffffu, hacc, off);
        }
        if (lane == 0) {
            const float o = sigf(acc2 + b2[0]);
            const float h = sigf(hacc + g_b1h[OMID]);
            const float p = g_psum[rowg];
            const float pn = p + h;
            const bool fin = (pn >= 1.0f - 0.001f) || (t == MAX_IT - 1);
            const float hr = fin ? (1.0f - p) : h;
            out[rowg] += o * hr;
            g_psum[rowg] = fin ? 1.0f : pn;
            if (!fin) {
                int slot = atomicAdd(&g_cnt[t + 1], 1);
                map_next[slot] = rowg;
            }
        }
    }
}

// ---------------- launch ------------------------------------------------------
extern "C" void kernel_launch(void* const* d_in, const int* in_sizes, int n_in,
                              void* d_out, int out_size) {
    const float* x     = (const float*)d_in[0];
    const float* Wxi   = (const float*)d_in[1];
    const float* bxi   = (const float*)d_in[2];
    const float* Whi   = (const float*)d_in[3];
    const float* bhi   = (const float*)d_in[4];
    const float* Wxf   = (const float*)d_in[5];
    const float* bxf   = (const float*)d_in[6];
    const float* Whf   = (const float*)d_in[7];
    const float* bhf   = (const float*)d_in[8];
    const float* Wxc   = (const float*)d_in[9];
    const float* bxc   = (const float*)d_in[10];
    const float* Whc   = (const float*)d_in[11];
    const float* bhc   = (const float*)d_in[12];
    const float* Wxo   = (const float*)d_in[13];
    const float* bxo   = (const float*)d_in[14];
    const float* Who   = (const float*)d_in[15];
    const float* bho   = (const float*)d_in[16];
    const float* Whalt = (const float*)d_in[17];
    const float* bhalt = (const float*)d_in[18];
    const float* W1    = (const float*)d_in[19];
    const float* b1    = (const float*)d_in[20];
    const float* W2    = (const float*)d_in[21];
    const float* b2    = (const float*)d_in[22];
    float* out = (float*)d_out;

    cudaFuncSetAttribute(k_gates, cudaFuncAttributeMaxDynamicSharedMemorySize, SMEM_DYN);

    k_init<<<B, 128>>>(x, out);

    const int tot = KA * NG + NG + HID * OMID + HID + OMID + 1;
    k_pack<<<(tot + 255) / 256, 256>>>(Wxi, Whi, bxi, bhi,
                                       Wxf, Whf, bxf, bhf,
                                       Wxc, Whc, bxc, bhc,
                                       Wxo, Who, bxo, bho,
                                       W1, b1, Whalt, bhalt);

    for (int t = 0; t < MAX_IT; t++) {
        k_gates<<<dim3(NTILES, B / BM), 256, SMEM_DYN>>>(t);
        k_head<<<B / HM, 256>>>(t, W2, b2, out);
    }
}

// round 9
// speedup vs baseline: 2.1189x; 1.1041x over previous
#include <cuda_runtime.h>
#include <cuda_bf16.h>
#include <math.h>
#include <stdint.h>

#define B       8192
#define INP     64
#define HID     1024
#define KA      1088          // INP + HID
#define NG      4096          // 4 gates * HID, interleaved n = j*4 + g
#define OMID    128
#define MAX_IT  8

#define BM 128
#define BN 128
#define CHUNKS 17             // K chunks of 64
#define NTILES (NG / BN)      // 32
#define STAGE_STRIDE 65536    // Ah/Al/Wh/Wl = 4 x 16KB per stage
#define SMEM_DYN_G (3 * STAGE_STRIDE + 1024)
#define CSTRIDE 132           // gates fp32 C tile row stride

// head (mma) geometry
#define NH_PAD 144            // 129 -> 144 (zeros)
#define H_CHUNKS 16           // K = HID only
#define H_STAGE 69632         // 16K Ah + 16K Al + 18K Bh + 18K Bl
#define SMEM_DYN_H (2 * H_STAGE + 1024)
#define HCS 148               // head C stride

// ---------------- device scratch ---------------------------------------------
__device__ __nv_bfloat16 g_A0hi[B * KA];
__device__ __nv_bfloat16 g_A0lo[B * KA];
__device__ __nv_bfloat16 g_A1hi[B * KA];
__device__ __nv_bfloat16 g_A1lo[B * KA];
__device__ float         g_cell[B * HID];
__device__ __nv_bfloat16 g_Whi_img[NTILES * CHUNKS * 8192];
__device__ __nv_bfloat16 g_Wlo_img[NTILES * CHUNKS * 8192];
__device__ __nv_bfloat16 g_W1img[H_CHUNKS * 2 * (NH_PAD * 64)];  // hi block + lo block per chunk
__device__ float         g_bias[NG];
__device__ float         g_b1h[OMID + 2];
__device__ float         g_psum[B];
__device__ int           g_mapA[B];
__device__ int           g_mapB[B];
__device__ int           g_cnt[MAX_IT + 1];

__device__ __forceinline__ float sigf(float z) { return 1.0f / (1.0f + expf(-z)); }

// ---------------- PTX helpers (base ISA only) ---------------------------------
__device__ __forceinline__ uint32_t smem_u32(const void* p) {
    uint32_t a;
    asm("{ .reg .u64 t; cvta.to.shared.u64 t, %1; cvt.u32.u64 %0, t; }" : "=r"(a) : "l"(p));
    return a;
}
__device__ __forceinline__ void cp16(uint32_t dst, const void* src) {
    asm volatile("cp.async.cg.shared.global [%0], [%1], 16;" :: "r"(dst), "l"(src));
}
#define CP_COMMIT() asm volatile("cp.async.commit_group;" ::: "memory")
#define CP_WAIT(n)  asm volatile("cp.async.wait_group %0;" :: "n"(n) : "memory")

#define LDM4(r, addr) \
    asm volatile("ldmatrix.sync.aligned.m8n8.x4.shared.b16 {%0,%1,%2,%3}, [%4];" \
        : "=r"((r)[0]), "=r"((r)[1]), "=r"((r)[2]), "=r"((r)[3]) : "r"(addr))

#define MMA16816(acc, a, b0v, b1v) \
    asm volatile("mma.sync.aligned.m16n8k16.row.col.f32.bf16.bf16.f32 " \
        "{%0,%1,%2,%3}, {%4,%5,%6,%7}, {%8,%9}, {%0,%1,%2,%3};" \
        : "+f"((acc)[0]), "+f"((acc)[1]), "+f"((acc)[2]), "+f"((acc)[3]) \
        : "r"((a)[0]), "r"((a)[1]), "r"((a)[2]), "r"((a)[3]), "r"(b0v), "r"(b1v))

__device__ __forceinline__ unsigned short bfu(__nv_bfloat16 v) {
    return *reinterpret_cast<unsigned short*>(&v);
}
__device__ __forceinline__ void split8(const float* w, uint4& hv, uint4& lv) {
    unsigned short hs[8], ls[8];
#pragma unroll
    for (int u = 0; u < 8; u++) {
        __nv_bfloat16 hi = __float2bfloat16(w[u]);
        __nv_bfloat16 lo = __float2bfloat16(w[u] - __bfloat162float(hi));
        hs[u] = bfu(hi); ls[u] = bfu(lo);
    }
    hv = make_uint4((uint32_t)hs[0] | ((uint32_t)hs[1] << 16),
                    (uint32_t)hs[2] | ((uint32_t)hs[3] << 16),
                    (uint32_t)hs[4] | ((uint32_t)hs[5] << 16),
                    (uint32_t)hs[6] | ((uint32_t)hs[7] << 16));
    lv = make_uint4((uint32_t)ls[0] | ((uint32_t)ls[1] << 16),
                    (uint32_t)ls[2] | ((uint32_t)ls[3] << 16),
                    (uint32_t)ls[4] | ((uint32_t)ls[5] << 16),
                    (uint32_t)ls[6] | ((uint32_t)ls[7] << 16));
}

// ---------------- init --------------------------------------------------------
__global__ void k_init(const float* __restrict__ x, float* __restrict__ out) {
    const int row = blockIdx.x;
    const int t = threadIdx.x;                 // 128 threads
    const size_t ra = (size_t)row * KA;
    const __nv_bfloat16 z = __float2bfloat16(0.0f);
    if (t < INP) {
        float v = x[row * INP + t];
        __nv_bfloat16 hi = __float2bfloat16(v);
        __nv_bfloat16 lo = __float2bfloat16(v - __bfloat162float(hi));
        g_A0hi[ra + t] = hi; g_A0lo[ra + t] = lo;
        g_A1hi[ra + t] = hi; g_A1lo[ra + t] = lo;
    }
    for (int j = t; j < HID; j += 128) {
        g_A0hi[ra + INP + j] = z;
        g_A0lo[ra + INP + j] = z;
        g_cell[(size_t)row * HID + j] = 0.0f;
    }
    if (t == 0) {
        g_psum[row] = 0.0f;
        g_mapA[row] = row;
        out[row] = 0.0f;
    }
    if (row == 0 && t <= MAX_IT) g_cnt[t] = (t == 0) ? B : 0;
}

// ---------------- pack weights (vectorized: 8 bf16 per thread) ----------------
__global__ void k_pack(
    const float* __restrict__ Wxi, const float* __restrict__ Whi,
    const float* __restrict__ bxi, const float* __restrict__ bhi,
    const float* __restrict__ Wxf, const float* __restrict__ Whf,
    const float* __restrict__ bxf, const float* __restrict__ bhf,
    const float* __restrict__ Wxc, const float* __restrict__ Whc,
    const float* __restrict__ bxc, const float* __restrict__ bhc,
    const float* __restrict__ Wxo, const float* __restrict__ Who,
    const float* __restrict__ bxo, const float* __restrict__ bho,
    const float* __restrict__ W1,  const float* __restrict__ b1,
    const float* __restrict__ Whalt, const float* __restrict__ bhalt)
{
    int idx = blockIdx.x * blockDim.x + threadIdx.x;
    if (idx < NG * (KA / 8)) {
        const int n = idx / (KA / 8);
        const int kb = idx % (KA / 8);         // 8-elem k block
        const int g = n & 3;
        const int j = n >> 2;
        const float* Wx = (g == 0) ? Wxi : (g == 1) ? Wxf : (g == 2) ? Wxc : Wxo;
        const float* Wh = (g == 0) ? Whi : (g == 1) ? Whf : (g == 2) ? Whc : Who;
        float w[8];
        if (kb < 8) {
            const float* s = Wx + j * INP + kb * 8;
#pragma unroll
            for (int u = 0; u < 8; u++) w[u] = s[u];
        } else {
            const float* s = Wh + j * HID + (kb - 8) * 8;
#pragma unroll
            for (int u = 0; u < 8; u++) w[u] = s[u];
        }
        uint4 hv, lv;
        split8(w, hv, lv);
        const int T = n >> 7, nr = n & 127, C = kb >> 3;
        const unsigned byte = ((unsigned)(nr * 128 + (kb & 7) * 16)) ^ (((unsigned)(nr & 7)) << 4);
        const unsigned off_b = (unsigned)((T * CHUNKS + C) * 16384) + byte;
        *(uint4*)((char*)g_Whi_img + off_b) = hv;
        *(uint4*)((char*)g_Wlo_img + off_b) = lv;
        return;
    }
    idx -= NG * (KA / 8);
    if (idx < NH_PAD * (HID / 8)) {            // head W1/Whalt image
        const int n = idx / (HID / 8);
        const int kb = idx % (HID / 8);
        float w[8];
#pragma unroll
        for (int u = 0; u < 8; u++) {
            const int k = kb * 8 + u;
            w[u] = (n < OMID) ? W1[n * HID + k] : (n == OMID ? Whalt[k] : 0.0f);
        }
        uint4 hv, lv;
        split8(w, hv, lv);
        const int C = kb >> 3;
        const unsigned byte = ((unsigned)(n * 128 + (kb & 7) * 16)) ^ (((unsigned)(n & 7)) << 4);
        const unsigned off_b = (unsigned)(C * 36864) + byte;
        *(uint4*)((char*)g_W1img + off_b) = hv;
        *(uint4*)((char*)g_W1img + off_b + 18432) = lv;
        return;
    }
    idx -= NH_PAD * (HID / 8);
    if (idx < NG) {
        const int g = idx & 3;
        const int j = idx >> 2;
        const float* bx = (g == 0) ? bxi : (g == 1) ? bxf : (g == 2) ? bxc : bxo;
        const float* bh = (g == 0) ? bhi : (g == 1) ? bhf : (g == 2) ? bhc : bho;
        g_bias[idx] = bx[j] + bh[j];
        return;
    }
    idx -= NG;
    if (idx < OMID) { g_b1h[idx] = b1[idx]; return; }
    idx -= OMID;
    if (idx == 0) g_b1h[OMID] = bhalt[0];
}

// ---------------- mma.sync bf16-split gate GEMM + LSTM epilogue ---------------
__global__ __launch_bounds__(256, 1) void k_gates(int t) {
    extern __shared__ char smem[];
    __shared__ int sRow[BM];

    const int count = g_cnt[t];
    const int m0 = blockIdx.y * BM;
    if (m0 >= count) return;
    const int n0 = blockIdx.x * BN;
    const int tid = threadIdx.x;
    const int wrp = tid >> 5;
    const int lane = tid & 31;

    const uint32_t sb0 = smem_u32(smem);
    const uint32_t tiles = (sb0 + 1023) & ~1023u;
    char* tilesPtr = smem + (tiles - sb0);

    const int* map = (t & 1) ? g_mapB : g_mapA;
    if (tid < BM) sRow[tid] = map[min(m0 + tid, count - 1)];
    __syncthreads();

    const __nv_bfloat16* Ahi = (t & 1) ? g_A1hi : g_A0hi;
    const __nv_bfloat16* Alo = (t & 1) ? g_A1lo : g_A0lo;
    __nv_bfloat16* Aout_hi = (t & 1) ? g_A0hi : g_A1hi;
    __nv_bfloat16* Aout_lo = (t & 1) ? g_A0lo : g_A1lo;

    // ---- load indexing: thread loads one A row (hi or lo) + W chunks ----
    const int arow = tid & 127;
    const int asel = tid >> 7;              // 0 = hi, 1 = lo
    const int myArowG = sRow[arow];
    const char* pA = (const char*)((asel ? Alo : Ahi) + (size_t)myArowG * KA);
    const uint32_t aswz = (uint32_t)(arow & 7) << 4;
    const uint32_t aDstRow = (uint32_t)arow * 128 + (asel ? 16384u : 0u);
    const char* pWh = (const char*)g_Whi_img + (size_t)blockIdx.x * (CHUNKS * 16384);
    const char* pWl = (const char*)g_Wlo_img + (size_t)blockIdx.x * (CHUNKS * 16384);

    auto load_chunk = [&](int c, int stage) {
        const uint32_t tb = tiles + (uint32_t)stage * STAGE_STRIDE;
        const char* src = pA + c * 128;
#pragma unroll
        for (int u = 0; u < 8; u++)
            cp16(tb + aDstRow + (((uint32_t)(u * 16)) ^ aswz), src + u * 16);
        const char* wh = pWh + c * 16384;
        const char* wl = pWl + c * 16384;
#pragma unroll
        for (int q = 0; q < 4; q++) {
            const uint32_t o = (uint32_t)(tid + q * 256) << 4;
            cp16(tb + 32768 + o, wh + o);
            cp16(tb + 49152 + o, wl + o);
        }
        CP_COMMIT();
    };

    // ---- mma fragment addressing ----
    const int wm = (wrp & 1) * 64;          // warp tile m (2 x 64)
    const int wn = (wrp >> 1) * 32;         // warp tile n (4 x 32)
    const uint32_t fswz = (uint32_t)(lane & 7) << 4;
    const uint32_t aRowOff = (uint32_t)(wm + (lane & 15)) * 128;
    const uint32_t aKsel = (uint32_t)(lane >> 4) * 16;
    const uint32_t bRowOff = (uint32_t)(wn + (lane & 7) + ((lane >> 4) << 3)) * 128;
    const uint32_t bKsel = (uint32_t)((lane >> 3) & 1) * 16;

    float acc[4][4][4];
#pragma unroll
    for (int mi = 0; mi < 4; mi++)
#pragma unroll
        for (int nj = 0; nj < 4; nj++)
#pragma unroll
            for (int e = 0; e < 4; e++) acc[mi][nj][e] = 0.0f;

    // 3-stage pipeline, single sync per chunk
    load_chunk(0, 0);
    load_chunk(1, 1);
    int st = 0, stl = 2;
    for (int c = 0; c < CHUNKS; c++) {
        if (c == CHUNKS - 1) { CP_WAIT(0); } else { CP_WAIT(1); }
        __syncthreads();
        if (c + 2 < CHUNKS) load_chunk(c + 2, stl);

        const uint32_t tb = tiles + (uint32_t)st * STAGE_STRIDE;
        const uint32_t ahB = tb + aRowOff;
        const uint32_t alB = tb + 16384 + aRowOff;
        const uint32_t whB = tb + 32768 + bRowOff;
        const uint32_t wlB = tb + 49152 + bRowOff;

#pragma unroll
        for (int ks = 0; ks < 4; ks++) {
            const uint32_t ak = ((uint32_t)(ks * 32) + aKsel) ^ fswz;
            const uint32_t bk = ((uint32_t)(ks * 32) + bKsel) ^ fswz;
            uint32_t ah[4][4], al[4][4], bh[2][4], bl[2][4];
#pragma unroll
            for (int mi = 0; mi < 4; mi++) {
                LDM4(ah[mi], ahB + mi * 2048 + ak);
                LDM4(al[mi], alB + mi * 2048 + ak);
            }
#pragma unroll
            for (int ni = 0; ni < 2; ni++) {
                LDM4(bh[ni], whB + ni * 2048 + bk);
                LDM4(bl[ni], wlB + ni * 2048 + bk);
            }
#pragma unroll
            for (int mi = 0; mi < 4; mi++)
#pragma unroll
                for (int nj = 0; nj < 4; nj++) {
                    const int ni = nj >> 1, pr = (nj & 1) * 2;
                    MMA16816(acc[mi][nj], ah[mi], bh[ni][pr], bh[ni][pr + 1]);
                    MMA16816(acc[mi][nj], ah[mi], bl[ni][pr], bl[ni][pr + 1]);
                    MMA16816(acc[mi][nj], al[mi], bh[ni][pr], bh[ni][pr + 1]);
                }
        }
        st = (st == 2) ? 0 : st + 1;
        stl = (stl == 2) ? 0 : stl + 1;
    }
    __syncthreads();   // protect stage overlay before C spill

    // ---- spill accumulators to smem C tile ----
    float* C = (float*)tilesPtr;
    {
        const int r0 = wm + (lane >> 2);
        const int c0 = wn + 2 * (lane & 3);
#pragma unroll
        for (int mi = 0; mi < 4; mi++)
#pragma unroll
            for (int nj = 0; nj < 4; nj++) {
                float* p = C + (r0 + mi * 16) * CSTRIDE + c0 + nj * 8;
                p[0] = acc[mi][nj][0];
                p[1] = acc[mi][nj][1];
                p[8 * CSTRIDE]     = acc[mi][nj][2];
                p[8 * CSTRIDE + 1] = acc[mi][nj][3];
            }
    }
    __syncthreads();

    // ---- LSTM pointwise epilogue ----
    const int row = tid & 127;
    const int hlf = tid >> 7;
    if (m0 + row < count) {
        const int rowg = sRow[row];
        const float* Crow = C + row * CSTRIDE + hlf * 64;
        const float* bb = g_bias + n0 + hlf * 64;
        const int j0 = (n0 >> 2) + hlf * 16;
        float* cellp = g_cell + (size_t)rowg * HID + j0;
        uint32_t hp[8], lp[8];
#pragma unroll
        for (int u = 0; u < 16; u++) {
            const float4 gv = *(const float4*)(Crow + u * 4);
            const float ig = sigf (gv.x + bb[u * 4 + 0]);
            const float fg = sigf (gv.y + bb[u * 4 + 1]);
            const float cg = tanhf(gv.z + bb[u * 4 + 2]);
            const float og = sigf (gv.w + bb[u * 4 + 3]);
            const float c2 = fg * cellp[u] + ig * cg;
            cellp[u] = c2;
            const float s = og * tanhf(c2);
            const __nv_bfloat16 hi = __float2bfloat16(s);
            const __nv_bfloat16 lo = __float2bfloat16(s - __bfloat162float(hi));
            const uint32_t hu = bfu(hi), lu = bfu(lo);
            if (u & 1) { hp[u >> 1] |= hu << 16; lp[u >> 1] |= lu << 16; }
            else       { hp[u >> 1] = hu;        lp[u >> 1] = lu; }
        }
        uint4* sh = (uint4*)(Aout_hi + (size_t)rowg * KA + INP + j0);
        uint4* sl = (uint4*)(Aout_lo + (size_t)rowg * KA + INP + j0);
        sh[0] = make_uint4(hp[0], hp[1], hp[2], hp[3]);
        sh[1] = make_uint4(hp[4], hp[5], hp[6], hp[7]);
        sl[0] = make_uint4(lp[0], lp[1], lp[2], lp[3]);
        sl[1] = make_uint4(lp[4], lp[5], lp[6], lp[7]);
    }
}

// ---------------- head: mma.sync GEMM (state @ [W1;Whalt]^T) + finalize -------
__global__ __launch_bounds__(256, 1) void k_head(int t,
                                                 const float* __restrict__ W2,
                                                 const float* __restrict__ b2,
                                                 float* __restrict__ out) {
    extern __shared__ char smem[];
    __shared__ int sRow[BM];

    const int count = g_cnt[t];
    const int base = blockIdx.x * BM;
    if (base >= count) return;
    const int tid = threadIdx.x;
    const int wrp = tid >> 5;
    const int lane = tid & 31;

    const uint32_t sb0 = smem_u32(smem);
    const uint32_t tiles = (sb0 + 1023) & ~1023u;
    char* tilesPtr = smem + (tiles - sb0);

    const int* map = (t & 1) ? g_mapB : g_mapA;
    int* map_next  = (t & 1) ? g_mapA : g_mapB;
    if (tid < BM) sRow[tid] = map[min(base + tid, count - 1)];
    __syncthreads();

    const __nv_bfloat16* Ahi = (t & 1) ? g_A0hi : g_A1hi;  // state after k_gates(t)
    const __nv_bfloat16* Alo = (t & 1) ? g_A0lo : g_A1lo;

    const int arow = tid & 127;
    const int asel = tid >> 7;
    const char* pA = (const char*)((asel ? Alo : Ahi) + (size_t)sRow[arow] * KA + INP);
    const uint32_t aswz = (uint32_t)(arow & 7) << 4;
    const uint32_t aDstRow = (uint32_t)arow * 128 + (asel ? 16384u : 0u);
    const char* pW = (const char*)g_W1img;

    auto load_chunk = [&](int c, int stage) {
        const uint32_t tb = tiles + (uint32_t)stage * H_STAGE;
        const char* src = pA + c * 128;
#pragma unroll
        for (int u = 0; u < 8; u++)
            cp16(tb + aDstRow + (((uint32_t)(u * 16)) ^ aswz), src + u * 16);
        const char* w = pW + c * 36864;     // hi 18432 B then lo 18432 B
#pragma unroll
        for (int q = 0; q < 9; q++) {       // 2304 lines = 9 * 256  (R8 bug: was 5)
            const uint32_t i = (uint32_t)(tid + q * 256);
            cp16(tb + 32768 + i * 16, w + (size_t)i * 16);
        }
        CP_COMMIT();
    };

    // warp tile: 16 rows x 144 n
    const int wm = wrp * 16;
    const uint32_t fswz = (uint32_t)(lane & 7) << 4;
    const uint32_t aRowOff = (uint32_t)(wm + (lane & 15)) * 128;
    const uint32_t aKsel = (uint32_t)(lane >> 4) * 16;
    const uint32_t bRowOff = (uint32_t)((lane & 7) + ((lane >> 4) << 3)) * 128;
    const uint32_t bKsel = (uint32_t)((lane >> 3) & 1) * 16;

    float acc[18][4];
#pragma unroll
    for (int nj = 0; nj < 18; nj++)
#pragma unroll
        for (int e = 0; e < 4; e++) acc[nj][e] = 0.0f;

    load_chunk(0, 0);
    for (int c = 0; c < H_CHUNKS; c++) {
        const int stage = c & 1;
        CP_WAIT(0);
        __syncthreads();
        if (c + 1 < H_CHUNKS) load_chunk(c + 1, stage ^ 1);

        const uint32_t tb = tiles + (uint32_t)stage * H_STAGE;
        const uint32_t ahB = tb + aRowOff;
        const uint32_t alB = tb + 16384 + aRowOff;
        const uint32_t whB = tb + 32768 + bRowOff;
        const uint32_t wlB = tb + 51200 + bRowOff;

#pragma unroll
        for (int ks = 0; ks < 4; ks++) {
            const uint32_t ak = ((uint32_t)(ks * 32) + aKsel) ^ fswz;
            const uint32_t bk = ((uint32_t)(ks * 32) + bKsel) ^ fswz;
            uint32_t ah[4], al[4], bh[9][4], bl[9][4];
            LDM4(ah, ahB + ak);
            LDM4(al, alB + ak);
#pragma unroll
            for (int ni = 0; ni < 9; ni++) {
                LDM4(bh[ni], whB + ni * 2048 + bk);
                LDM4(bl[ni], wlB + ni * 2048 + bk);
            }
#pragma unroll
            for (int nj = 0; nj < 18; nj++) {
                const int ni = nj >> 1, pr = (nj & 1) * 2;
                MMA16816(acc[nj], ah, bh[ni][pr], bh[ni][pr + 1]);
                MMA16816(acc[nj], ah, bl[ni][pr], bl[ni][pr + 1]);
                MMA16816(acc[nj], al, bh[ni][pr], bh[ni][pr + 1]);
            }
        }
    }
    __syncthreads();

    // ---- spill C (128 x 144, cols 0..127 = mid pre-bias, col 128 = halt) ----
    float* C = (float*)tilesPtr;
    {
        const int r0 = wm + (lane >> 2);
        const int c0 = 2 * (lane & 3);
#pragma unroll
        for (int nj = 0; nj < 18; nj++) {
            float* p = C + r0 * HCS + c0 + nj * 8;
            p[0] = acc[nj][0];
            p[1] = acc[nj][1];
            p[8 * HCS]     = acc[nj][2];
            p[8 * HCS + 1] = acc[nj][3];
        }
    }
    __syncthreads();

    // ---- finalize: relu+b1, W2 dot, halting state machine, compaction ----
    const float4 w2v = *(const float4*)(W2 + lane * 4);
    const float4 b1v = *(const float4*)(g_b1h + lane * 4);
    const float bhalt = g_b1h[OMID];

    for (int i = 0; i < 16; i++) {
        const int r = wm + i;
        const int mm = base + r;
        if (mm >= count) continue;
        const int rowg = sRow[r];

        const float4 mv = *(const float4*)&C[r * HCS + lane * 4];
        float acc2 = fmaxf(mv.x + b1v.x, 0.0f) * w2v.x
                   + fmaxf(mv.y + b1v.y, 0.0f) * w2v.y
                   + fmaxf(mv.z + b1v.z, 0.0f) * w2v.z
                   + fmaxf(mv.w + b1v.w, 0.0f) * w2v.w;
#pragma unroll
        for (int off = 16; off; off >>= 1)
            acc2 += __shfl_xor_sync(0xffffffffu, acc2, off);

        if (lane == 0) {
            const float o = sigf(acc2 + b2[0]);
            const float h = sigf(C[r * HCS + OMID] + bhalt);
            const float p = g_psum[rowg];
            const float pn = p + h;
            const bool fin = (pn >= 1.0f - 0.001f) || (t == MAX_IT - 1);
            const float hr = fin ? (1.0f - p) : h;
            out[rowg] += o * hr;
            g_psum[rowg] = fin ? 1.0f : pn;
            if (!fin) {
                int slot = atomicAdd(&g_cnt[t + 1], 1);
                map_next[slot] = rowg;
            }
        }
    }
}

// ---------------- launch ------------------------------------------------------
extern "C" void kernel_launch(void* const* d_in, const int* in_sizes, int n_in,
                              void* d_out, int out_size) {
    const float* x     = (const float*)d_in[0];
    const float* Wxi   = (const float*)d_in[1];
    const float* bxi   = (const float*)d_in[2];
    const float* Whi   = (const float*)d_in[3];
    const float* bhi   = (const float*)d_in[4];
    const float* Wxf   = (const float*)d_in[5];
    const float* bxf   = (const float*)d_in[6];
    const float* Whf   = (const float*)d_in[7];
    const float* bhf   = (const float*)d_in[8];
    const float* Wxc   = (const float*)d_in[9];
    const float* bxc   = (const float*)d_in[10];
    const float* Whc   = (const float*)d_in[11];
    const float* bhc   = (const float*)d_in[12];
    const float* Wxo   = (const float*)d_in[13];
    const float* bxo   = (const float*)d_in[14];
    const float* Who   = (const float*)d_in[15];
    const float* bho   = (const float*)d_in[16];
    const float* Whalt = (const float*)d_in[17];
    const float* bhalt = (const float*)d_in[18];
    const float* W1    = (const float*)d_in[19];
    const float* b1    = (const float*)d_in[20];
    const float* W2    = (const float*)d_in[21];
    const float* b2    = (const float*)d_in[22];
    float* out = (float*)d_out;

    cudaFuncSetAttribute(k_gates, cudaFuncAttributeMaxDynamicSharedMemorySize, SMEM_DYN_G);
    cudaFuncSetAttribute(k_head,  cudaFuncAttributeMaxDynamicSharedMemorySize, SMEM_DYN_H);

    k_init<<<B, 128>>>(x, out);

    const int tot = NG * (KA / 8) + NH_PAD * (HID / 8) + NG + OMID + 1;
    k_pack<<<(tot + 255) / 256, 256>>>(Wxi, Whi, bxi, bhi,
                                       Wxf, Whf, bxf, bhf,
                                       Wxc, Whc, bxc, bhc,
                                       Wxo, Who, bxo, bho,
                                       W1, b1, Whalt, bhalt);

    for (int t = 0; t < MAX_IT; t++) {
        k_gates<<<dim3(NTILES, B / BM), 256, SMEM_DYN_G>>>(t);
        k_head<<<B / BM, 256, SMEM_DYN_H>>>(t, W2, b2, out);
    }
}

// round 10
// speedup vs baseline: 2.3815x; 1.1239x over previous
#include <cuda_runtime.h>
#include <cuda_bf16.h>
#include <math.h>
#include <stdint.h>

#define B       8192
#define INP     64
#define HID     1024
#define KA      1088          // INP + HID
#define NG      4096          // 4 gates * HID, interleaved n = j*4 + g
#define OMID    128
#define MAX_IT  8

#define BM 256
#define BN 128
#define CHUNKS 17             // K chunks of 64
#define NTILES (NG / BN)      // 32
#define G_STAGE 98304         // Ah 32K + Al 32K + Wh 16K + Wl 16K
#define SMEM_DYN_G (2 * G_STAGE + 1024)
#define CSTRIDE 132           // gates fp32 C tile row stride

// head (mma) geometry
#define HBM 128
#define NH_PAD 144            // 129 -> 144 (zeros)
#define H_CHUNKS 16           // K = HID only
#define H_STAGE 69632         // 16K Ah + 16K Al + 18K Bh + 18K Bl
#define SMEM_DYN_H (2 * H_STAGE + 1024)
#define HCS 148               // head C stride

// ---------------- device scratch ---------------------------------------------
__device__ __nv_bfloat16 g_A0hi[B * KA];
__device__ __nv_bfloat16 g_A0lo[B * KA];
__device__ __nv_bfloat16 g_A1hi[B * KA];
__device__ __nv_bfloat16 g_A1lo[B * KA];
__device__ float         g_cell[B * HID];
__device__ __nv_bfloat16 g_Whi_img[NTILES * CHUNKS * 8192];
__device__ __nv_bfloat16 g_Wlo_img[NTILES * CHUNKS * 8192];
__device__ __nv_bfloat16 g_W1img[H_CHUNKS * 2 * (NH_PAD * 64)];  // hi block + lo block per chunk
__device__ float         g_bias[NG];
__device__ float         g_b1h[OMID + 2];
__device__ float         g_psum[B];
__device__ int           g_mapA[B];
__device__ int           g_mapB[B];
__device__ int           g_cnt[MAX_IT + 1];

__device__ __forceinline__ float sigf(float z) { return 1.0f / (1.0f + expf(-z)); }

// ---------------- PTX helpers (base ISA only) ---------------------------------
__device__ __forceinline__ uint32_t smem_u32(const void* p) {
    uint32_t a;
    asm("{ .reg .u64 t; cvta.to.shared.u64 t, %1; cvt.u32.u64 %0, t; }" : "=r"(a) : "l"(p));
    return a;
}
__device__ __forceinline__ void cp16(uint32_t dst, const void* src) {
    asm volatile("cp.async.cg.shared.global [%0], [%1], 16;" :: "r"(dst), "l"(src));
}
#define CP_COMMIT() asm volatile("cp.async.commit_group;" ::: "memory")
#define CP_WAIT(n)  asm volatile("cp.async.wait_group %0;" :: "n"(n) : "memory")

#define LDM4(r, addr) \
    asm volatile("ldmatrix.sync.aligned.m8n8.x4.shared.b16 {%0,%1,%2,%3}, [%4];" \
        : "=r"((r)[0]), "=r"((r)[1]), "=r"((r)[2]), "=r"((r)[3]) : "r"(addr))

#define MMA16816(acc, a, b0v, b1v) \
    asm volatile("mma.sync.aligned.m16n8k16.row.col.f32.bf16.bf16.f32 " \
        "{%0,%1,%2,%3}, {%4,%5,%6,%7}, {%8,%9}, {%0,%1,%2,%3};" \
        : "+f"((acc)[0]), "+f"((acc)[1]), "+f"((acc)[2]), "+f"((acc)[3]) \
        : "r"((a)[0]), "r"((a)[1]), "r"((a)[2]), "r"((a)[3]), "r"(b0v), "r"(b1v))

__device__ __forceinline__ unsigned short bfu(__nv_bfloat16 v) {
    return *reinterpret_cast<unsigned short*>(&v);
}
__device__ __forceinline__ void split8(const float* w, uint4& hv, uint4& lv) {
    unsigned short hs[8], ls[8];
#pragma unroll
    for (int u = 0; u < 8; u++) {
        __nv_bfloat16 hi = __float2bfloat16(w[u]);
        __nv_bfloat16 lo = __float2bfloat16(w[u] - __bfloat162float(hi));
        hs[u] = bfu(hi); ls[u] = bfu(lo);
    }
    hv = make_uint4((uint32_t)hs[0] | ((uint32_t)hs[1] << 16),
                    (uint32_t)hs[2] | ((uint32_t)hs[3] << 16),
                    (uint32_t)hs[4] | ((uint32_t)hs[5] << 16),
                    (uint32_t)hs[6] | ((uint32_t)hs[7] << 16));
    lv = make_uint4((uint32_t)ls[0] | ((uint32_t)ls[1] << 16),
                    (uint32_t)ls[2] | ((uint32_t)ls[3] << 16),
                    (uint32_t)ls[4] | ((uint32_t)ls[5] << 16),
                    (uint32_t)ls[6] | ((uint32_t)ls[7] << 16));
}

// ---------------- init --------------------------------------------------------
__global__ void k_init(const float* __restrict__ x, float* __restrict__ out) {
    const int row = blockIdx.x;
    const int t = threadIdx.x;                 // 128 threads
    const size_t ra = (size_t)row * KA;
    const __nv_bfloat16 z = __float2bfloat16(0.0f);
    if (t < INP) {
        float v = x[row * INP + t];
        __nv_bfloat16 hi = __float2bfloat16(v);
        __nv_bfloat16 lo = __float2bfloat16(v - __bfloat162float(hi));
        g_A0hi[ra + t] = hi; g_A0lo[ra + t] = lo;
        g_A1hi[ra + t] = hi; g_A1lo[ra + t] = lo;
    }
    for (int j = t; j < HID; j += 128) {
        g_A0hi[ra + INP + j] = z;
        g_A0lo[ra + INP + j] = z;
        g_cell[(size_t)row * HID + j] = 0.0f;
    }
    if (t == 0) {
        g_psum[row] = 0.0f;
        g_mapA[row] = row;
        out[row] = 0.0f;
    }
    if (row == 0 && t <= MAX_IT) g_cnt[t] = (t == 0) ? B : 0;
}

// ---------------- pack weights (vectorized: 8 bf16 per thread) ----------------
__global__ void k_pack(
    const float* __restrict__ Wxi, const float* __restrict__ Whi,
    const float* __restrict__ bxi, const float* __restrict__ bhi,
    const float* __restrict__ Wxf, const float* __restrict__ Whf,
    const float* __restrict__ bxf, const float* __restrict__ bhf,
    const float* __restrict__ Wxc, const float* __restrict__ Whc,
    const float* __restrict__ bxc, const float* __restrict__ bhc,
    const float* __restrict__ Wxo, const float* __restrict__ Who,
    const float* __restrict__ bxo, const float* __restrict__ bho,
    const float* __restrict__ W1,  const float* __restrict__ b1,
    const float* __restrict__ Whalt, const float* __restrict__ bhalt)
{
    int idx = blockIdx.x * blockDim.x + threadIdx.x;
    if (idx < NG * (KA / 8)) {
        const int n = idx / (KA / 8);
        const int kb = idx % (KA / 8);         // 8-elem k block
        const int g = n & 3;
        const int j = n >> 2;
        const float* Wx = (g == 0) ? Wxi : (g == 1) ? Wxf : (g == 2) ? Wxc : Wxo;
        const float* Wh = (g == 0) ? Whi : (g == 1) ? Whf : (g == 2) ? Whc : Who;
        float w[8];
        if (kb < 8) {
            const float* s = Wx + j * INP + kb * 8;
#pragma unroll
            for (int u = 0; u < 8; u++) w[u] = s[u];
        } else {
            const float* s = Wh + j * HID + (kb - 8) * 8;
#pragma unroll
            for (int u = 0; u < 8; u++) w[u] = s[u];
        }
        uint4 hv, lv;
        split8(w, hv, lv);
        const int T = n >> 7, nr = n & 127, C = kb >> 3;
        const unsigned byte = ((unsigned)(nr * 128 + (kb & 7) * 16)) ^ (((unsigned)(nr & 7)) << 4);
        const unsigned off_b = (unsigned)((T * CHUNKS + C) * 16384) + byte;
        *(uint4*)((char*)g_Whi_img + off_b) = hv;
        *(uint4*)((char*)g_Wlo_img + off_b) = lv;
        return;
    }
    idx -= NG * (KA / 8);
    if (idx < NH_PAD * (HID / 8)) {            // head W1/Whalt image
        const int n = idx / (HID / 8);
        const int kb = idx % (HID / 8);
        float w[8];
#pragma unroll
        for (int u = 0; u < 8; u++) {
            const int k = kb * 8 + u;
            w[u] = (n < OMID) ? W1[n * HID + k] : (n == OMID ? Whalt[k] : 0.0f);
        }
        uint4 hv, lv;
        split8(w, hv, lv);
        const int C = kb >> 3;
        const unsigned byte = ((unsigned)(n * 128 + (kb & 7) * 16)) ^ (((unsigned)(n & 7)) << 4);
        const unsigned off_b = (unsigned)(C * 36864) + byte;
        *(uint4*)((char*)g_W1img + off_b) = hv;
        *(uint4*)((char*)g_W1img + off_b + 18432) = lv;
        return;
    }
    idx -= NH_PAD * (HID / 8);
    if (idx < NG) {
        const int g = idx & 3;
        const int j = idx >> 2;
        const float* bx = (g == 0) ? bxi : (g == 1) ? bxf : (g == 2) ? bxc : bxo;
        const float* bh = (g == 0) ? bhi : (g == 1) ? bhf : (g == 2) ? bhc : bho;
        g_bias[idx] = bx[j] + bh[j];
        return;
    }
    idx -= NG;
    if (idx < OMID) { g_b1h[idx] = b1[idx]; return; }
    idx -= OMID;
    if (idx == 0) g_b1h[OMID] = bhalt[0];
}

// ---------------- mma.sync bf16-split gate GEMM (256x128 tile) + epilogue -----
__global__ __launch_bounds__(256, 1) void k_gates(int t) {
    extern __shared__ char smem[];
    __shared__ int sRow[BM];

    const int count = g_cnt[t];
    const int m0 = blockIdx.y * BM;
    if (m0 >= count) return;
    const int n0 = blockIdx.x * BN;
    const int tid = threadIdx.x;
    const int wrp = tid >> 5;
    const int lane = tid & 31;

    const uint32_t sb0 = smem_u32(smem);
    const uint32_t tiles = (sb0 + 1023) & ~1023u;
    char* tilesPtr = smem + (tiles - sb0);

    const int* map = (t & 1) ? g_mapB : g_mapA;
    sRow[tid] = map[min(m0 + tid, count - 1)];
    __syncthreads();

    const __nv_bfloat16* Ahi = (t & 1) ? g_A1hi : g_A0hi;
    const __nv_bfloat16* Alo = (t & 1) ? g_A1lo : g_A0lo;
    __nv_bfloat16* Aout_hi = (t & 1) ? g_A0hi : g_A1hi;
    __nv_bfloat16* Aout_lo = (t & 1) ? g_A0lo : g_A1lo;

    // ---- load indexing: thread tid owns row tid of BOTH Ah and Al ----
    const int myrow = sRow[tid];
    const char* pAh = (const char*)(Ahi + (size_t)myrow * KA);
    const char* pAl = (const char*)(Alo + (size_t)myrow * KA);
    const uint32_t aswz = (uint32_t)(tid & 7) << 4;
    const uint32_t aDstRow = (uint32_t)tid * 128;
    const char* pWh = (const char*)g_Whi_img + (size_t)blockIdx.x * (CHUNKS * 16384);
    const char* pWl = (const char*)g_Wlo_img + (size_t)blockIdx.x * (CHUNKS * 16384);

    auto load_chunk = [&](int c, int stage) {
        const uint32_t tb = tiles + (uint32_t)stage * G_STAGE;
        const char* sh = pAh + c * 128;
        const char* sl = pAl + c * 128;
#pragma unroll
        for (int u = 0; u < 8; u++) {
            const uint32_t d = aDstRow + (((uint32_t)(u * 16)) ^ aswz);
            cp16(tb + d, sh + u * 16);
            cp16(tb + 32768 + d, sl + u * 16);
        }
        const char* wh = pWh + c * 16384;
        const char* wl = pWl + c * 16384;
#pragma unroll
        for (int q = 0; q < 4; q++) {
            const uint32_t o = (uint32_t)(tid + q * 256) << 4;
            cp16(tb + 65536 + o, wh + o);
            cp16(tb + 81920 + o, wl + o);
        }
        CP_COMMIT();
    };

    // ---- mma fragment addressing: warp tile 64m x 64n, warps 4x2 ----
    const int wm = (wrp & 3) * 64;
    const int wn = (wrp >> 2) * 64;
    const uint32_t fswz = (uint32_t)(lane & 7) << 4;
    const uint32_t aRowOff = (uint32_t)(wm + (lane & 15)) * 128;
    const uint32_t aKsel = (uint32_t)(lane >> 4) * 16;
    const uint32_t bRowOff = (uint32_t)(wn + (lane & 7) + ((lane >> 4) << 3)) * 128;
    const uint32_t bKsel = (uint32_t)((lane >> 3) & 1) * 16;

    float acc[4][8][4];
#pragma unroll
    for (int mi = 0; mi < 4; mi++)
#pragma unroll
        for (int nj = 0; nj < 8; nj++)
#pragma unroll
            for (int e = 0; e < 4; e++) acc[mi][nj][e] = 0.0f;

    load_chunk(0, 0);
    for (int c = 0; c < CHUNKS; c++) {
        const int stage = c & 1;
        CP_WAIT(0);
        __syncthreads();
        if (c + 1 < CHUNKS) load_chunk(c + 1, stage ^ 1);

        const uint32_t tb = tiles + (uint32_t)stage * G_STAGE;
        const uint32_t ahB = tb + aRowOff;
        const uint32_t alB = tb + 32768 + aRowOff;
        const uint32_t whB = tb + 65536 + bRowOff;
        const uint32_t wlB = tb + 81920 + bRowOff;

#pragma unroll
        for (int ks = 0; ks < 4; ks++) {
            const uint32_t ak = ((uint32_t)(ks * 32) + aKsel) ^ fswz;
            const uint32_t bk = ((uint32_t)(ks * 32) + bKsel) ^ fswz;
            uint32_t bh[4][4], bl[4][4];
#pragma unroll
            for (int ni = 0; ni < 4; ni++) {
                LDM4(bh[ni], whB + ni * 2048 + bk);
                LDM4(bl[ni], wlB + ni * 2048 + bk);
            }
#pragma unroll
            for (int mi = 0; mi < 4; mi++) {
                uint32_t ah[4], al[4];
                LDM4(ah, ahB + mi * 2048 + ak);
                LDM4(al, alB + mi * 2048 + ak);
#pragma unroll
                for (int nj = 0; nj < 8; nj++) {
                    const int ni = nj >> 1, pr = (nj & 1) * 2;
                    MMA16816(acc[mi][nj], ah, bh[ni][pr], bh[ni][pr + 1]);
                    MMA16816(acc[mi][nj], ah, bl[ni][pr], bl[ni][pr + 1]);
                    MMA16816(acc[mi][nj], al, bh[ni][pr], bh[ni][pr + 1]);
                }
            }
        }
    }
    __syncthreads();   // protect stage overlay before C spill

    // ---- spill accumulators to smem C tile (256 x 128, stride 132) ----
    float* C = (float*)tilesPtr;
    {
        const int r0 = wm + (lane >> 2);
        const int c0 = wn + 2 * (lane & 3);
#pragma unroll
        for (int mi = 0; mi < 4; mi++)
#pragma unroll
            for (int nj = 0; nj < 8; nj++) {
                float* p = C + (r0 + mi * 16) * CSTRIDE + c0 + nj * 8;
                p[0] = acc[mi][nj][0];
                p[1] = acc[mi][nj][1];
                p[8 * CSTRIDE]     = acc[mi][nj][2];
                p[8 * CSTRIDE + 1] = acc[mi][nj][3];
            }
    }
    __syncthreads();

    // ---- LSTM pointwise epilogue: thread tid owns row tid (32 units) ----
    if (m0 + tid < count) {
        const int rowg = sRow[tid];
        const float* Crow = C + tid * CSTRIDE;
        const float* bb = g_bias + n0;
        const int j0 = n0 >> 2;                 // 32 hidden units
        float* cellp = g_cell + (size_t)rowg * HID + j0;
        uint32_t hp[16], lp[16];
#pragma unroll
        for (int u = 0; u < 32; u++) {
            const float4 gv = *(const float4*)(Crow + u * 4);
            const float ig = sigf (gv.x + bb[u * 4 + 0]);
            const float fg = sigf (gv.y + bb[u * 4 + 1]);
            const float cg = tanhf(gv.z + bb[u * 4 + 2]);
            const float og = sigf (gv.w + bb[u * 4 + 3]);
            const float c2 = fg * cellp[u] + ig * cg;
            cellp[u] = c2;
            const float s = og * tanhf(c2);
            const __nv_bfloat16 hi = __float2bfloat16(s);
            const __nv_bfloat16 lo = __float2bfloat16(s - __bfloat162float(hi));
            const uint32_t hu = bfu(hi), lu = bfu(lo);
            if (u & 1) { hp[u >> 1] |= hu << 16; lp[u >> 1] |= lu << 16; }
            else       { hp[u >> 1] = hu;        lp[u >> 1] = lu; }
        }
        uint4* sh = (uint4*)(Aout_hi + (size_t)rowg * KA + INP + j0);
        uint4* sl = (uint4*)(Aout_lo + (size_t)rowg * KA + INP + j0);
#pragma unroll
        for (int v = 0; v < 4; v++) {
            sh[v] = make_uint4(hp[v * 4], hp[v * 4 + 1], hp[v * 4 + 2], hp[v * 4 + 3]);
            sl[v] = make_uint4(lp[v * 4], lp[v * 4 + 1], lp[v * 4 + 2], lp[v * 4 + 3]);
        }
    }
}

// ---------------- head: mma.sync GEMM (state @ [W1;Whalt]^T) + finalize -------
__global__ __launch_bounds__(256, 1) void k_head(int t,
                                                 const float* __restrict__ W2,
                                                 const float* __restrict__ b2,
                                                 float* __restrict__ out) {
    extern __shared__ char smem[];
    __shared__ int sRow[HBM];

    const int count = g_cnt[t];
    const int base = blockIdx.x * HBM;
    if (base >= count) return;
    const int tid = threadIdx.x;
    const int wrp = tid >> 5;
    const int lane = tid & 31;

    const uint32_t sb0 = smem_u32(smem);
    const uint32_t tiles = (sb0 + 1023) & ~1023u;
    char* tilesPtr = smem + (tiles - sb0);

    const int* map = (t & 1) ? g_mapB : g_mapA;
    int* map_next  = (t & 1) ? g_mapA : g_mapB;
    if (tid < HBM) sRow[tid] = map[min(base + tid, count - 1)];
    __syncthreads();

    const __nv_bfloat16* Ahi = (t & 1) ? g_A0hi : g_A1hi;  // state after k_gates(t)
    const __nv_bfloat16* Alo = (t & 1) ? g_A0lo : g_A1lo;

    const int arow = tid & 127;
    const int asel = tid >> 7;
    const char* pA = (const char*)((asel ? Alo : Ahi) + (size_t)sRow[arow] * KA + INP);
    const uint32_t aswz = (uint32_t)(arow & 7) << 4;
    const uint32_t aDstRow = (uint32_t)arow * 128 + (asel ? 16384u : 0u);
    const char* pW = (const char*)g_W1img;

    auto load_chunk = [&](int c, int stage) {
        const uint32_t tb = tiles + (uint32_t)stage * H_STAGE;
        const char* src = pA + c * 128;
#pragma unroll
        for (int u = 0; u < 8; u++)
            cp16(tb + aDstRow + (((uint32_t)(u * 16)) ^ aswz), src + u * 16);
        const char* w = pW + c * 36864;     // hi 18432 B then lo 18432 B
#pragma unroll
        for (int q = 0; q < 9; q++) {       // 2304 lines = 9 * 256
            const uint32_t i = (uint32_t)(tid + q * 256);
            cp16(tb + 32768 + i * 16, w + (size_t)i * 16);
        }
        CP_COMMIT();
    };

    // warp tile: 16 rows x 144 n
    const int wm = wrp * 16;
    const uint32_t fswz = (uint32_t)(lane & 7) << 4;
    const uint32_t aRowOff = (uint32_t)(wm + (lane & 15)) * 128;
    const uint32_t aKsel = (uint32_t)(lane >> 4) * 16;
    const uint32_t bRowOff = (uint32_t)((lane & 7) + ((lane >> 4) << 3)) * 128;
    const uint32_t bKsel = (uint32_t)((lane >> 3) & 1) * 16;

    float acc[18][4];
#pragma unroll
    for (int nj = 0; nj < 18; nj++)
#pragma unroll
        for (int e = 0; e < 4; e++) acc[nj][e] = 0.0f;

    load_chunk(0, 0);
    for (int c = 0; c < H_CHUNKS; c++) {
        const int stage = c & 1;
        CP_WAIT(0);
        __syncthreads();
        if (c + 1 < H_CHUNKS) load_chunk(c + 1, stage ^ 1);

        const uint32_t tb = tiles + (uint32_t)stage * H_STAGE;
        const uint32_t ahB = tb + aRowOff;
        const uint32_t alB = tb + 16384 + aRowOff;
        const uint32_t whB = tb + 32768 + bRowOff;
        const uint32_t wlB = tb + 51200 + bRowOff;

#pragma unroll
        for (int ks = 0; ks < 4; ks++) {
            const uint32_t ak = ((uint32_t)(ks * 32) + aKsel) ^ fswz;
            const uint32_t bk = ((uint32_t)(ks * 32) + bKsel) ^ fswz;
            uint32_t ah[4], al[4], bh[9][4], bl[9][4];
            LDM4(ah, ahB + ak);
            LDM4(al, alB + ak);
#pragma unroll
            for (int ni = 0; ni < 9; ni++) {
                LDM4(bh[ni], whB + ni * 2048 + bk);
                LDM4(bl[ni], wlB + ni * 2048 + bk);
            }
#pragma unroll
            for (int nj = 0; nj < 18; nj++) {
                const int ni = nj >> 1, pr = (nj & 1) * 2;
                MMA16816(acc[nj], ah, bh[ni][pr], bh[ni][pr + 1]);
                MMA16816(acc[nj], ah, bl[ni][pr], bl[ni][pr + 1]);
                MMA16816(acc[nj], al, bh[ni][pr], bh[ni][pr + 1]);
            }
        }
    }
    __syncthreads();

    // ---- spill C (128 x 144, cols 0..127 = mid pre-bias, col 128 = halt) ----
    float* C = (float*)tilesPtr;
    {
        const int r0 = wm + (lane >> 2);
        const int c0 = 2 * (lane & 3);
#pragma unroll
        for (int nj = 0; nj < 18; nj++) {
            float* p = C + r0 * HCS + c0 + nj * 8;
            p[0] = acc[nj][0];
            p[1] = acc[nj][1];
            p[8 * HCS]     = acc[nj][2];
            p[8 * HCS + 1] = acc[nj][3];
        }
    }
    __syncthreads();

    // ---- finalize: relu+b1, W2 dot, halting state machine, compaction ----
    const float4 w2v = *(const float4*)(W2 + lane * 4);
    const float4 b1v = *(const float4*)(g_b1h + lane * 4);
    const float bhalt = g_b1h[OMID];

    for (int i = 0; i < 16; i++) {
        const int r = wm + i;
        const int mm = base + r;
        if (mm >= count) continue;
        const int rowg = sRow[r];

        const float4 mv = *(const float4*)&C[r * HCS + lane * 4];
        float acc2 = fmaxf(mv.x + b1v.x, 0.0f) * w2v.x
                   + fmaxf(mv.y + b1v.y, 0.0f) * w2v.y
                   + fmaxf(mv.z + b1v.z, 0.0f) * w2v.z
                   + fmaxf(mv.w + b1v.w, 0.0f) * w2v.w;
#pragma unroll
        for (int off = 16; off; off >>= 1)
            acc2 += __shfl_xor_sync(0xffffffffu, acc2, off);

        if (lane == 0) {
            const float o = sigf(acc2 + b2[0]);
            const float h = sigf(C[r * HCS + OMID] + bhalt);
            const float p = g_psum[rowg];
            const float pn = p + h;
            const bool fin = (pn >= 1.0f - 0.001f) || (t == MAX_IT - 1);
            const float hr = fin ? (1.0f - p) : h;
            out[rowg] += o * hr;
            g_psum[rowg] = fin ? 1.0f : pn;
            if (!fin) {
                int slot = atomicAdd(&g_cnt[t + 1], 1);
                map_next[slot] = rowg;
            }
        }
    }
}

// ---------------- launch ------------------------------------------------------
extern "C" void kernel_launch(void* const* d_in, const int* in_sizes, int n_in,
                              void* d_out, int out_size) {
    const float* x     = (const float*)d_in[0];
    const float* Wxi   = (const float*)d_in[1];
    const float* bxi   = (const float*)d_in[2];
    const float* Whi   = (const float*)d_in[3];
    const float* bhi   = (const float*)d_in[4];
    const float* Wxf   = (const float*)d_in[5];
    const float* bxf   = (const float*)d_in[6];
    const float* Whf   = (const float*)d_in[7];
    const float* bhf   = (const float*)d_in[8];
    const float* Wxc   = (const float*)d_in[9];
    const float* bxc   = (const float*)d_in[10];
    const float* Whc   = (const float*)d_in[11];
    const float* bhc   = (const float*)d_in[12];
    const float* Wxo   = (const float*)d_in[13];
    const float* bxo   = (const float*)d_in[14];
    const float* Who   = (const float*)d_in[15];
    const float* bho   = (const float*)d_in[16];
    const float* Whalt = (const float*)d_in[17];
    const float* bhalt = (const float*)d_in[18];
    const float* W1    = (const float*)d_in[19];
    const float* b1    = (const float*)d_in[20];
    const float* W2    = (const float*)d_in[21];
    const float* b2    = (const float*)d_in[22];
    float* out = (float*)d_out;

    cudaFuncSetAttribute(k_gates, cudaFuncAttributeMaxDynamicSharedMemorySize, SMEM_DYN_G);
    cudaFuncSetAttribute(k_head,  cudaFuncAttributeMaxDynamicSharedMemorySize, SMEM_DYN_H);

    k_init<<<B, 128>>>(x, out);

    const int tot = NG * (KA / 8) + NH_PAD * (HID / 8) + NG + OMID + 1;
    k_pack<<<(tot + 255) / 256, 256>>>(Wxi, Whi, bxi, bhi,
                                       Wxf, Whf, bxf, bhf,
                                       Wxc, Whc, bxc, bhc,
                                       Wxo, Who, bxo, bho,
                                       W1, b1, Whalt, bhalt);

    for (int t = 0; t < MAX_IT; t++) {
        k_gates<<<dim3(NTILES, B / BM), 256, SMEM_DYN_G>>>(t);
        k_head<<<B / HBM, 256, SMEM_DYN_H>>>(t, W2, b2, out);
    }
}

// round 12
// speedup vs baseline: 3.2052x; 1.3459x over previous
#include <cuda_runtime.h>
#include <cuda_bf16.h>
#include <math.h>
#include <stdint.h>

#define B       8192
#define INP     64
#define HID     1024
#define KA      1088
#define NG      4096          // 4 gates * HID, interleaved n = j*4 + g
#define OMID    128
#define MAX_IT  8

#define BM 256
#define BN 128
#define CHUNKS 16             // state K chunks of 64 (K=1024)
#define NTILES (NG / BN)      // 32
#define G_STAGE 98304         // Ah 32K + Al 32K + Wh 16K + Wl 16K
#define SMEM_DYN_G (2 * G_STAGE + 1024)
#define CSTRIDE 132

// head geometry
#define HBM 128
#define NH_PAD 144
#define H_CHUNKS 16
#define H_STAGE 69632
#define SMEM_DYN_H (2 * H_STAGE + 1024)
#define HCS 148

// ---------------- device scratch ---------------------------------------------
__device__ __nv_bfloat16 g_A0hi[B * HID];
__device__ __nv_bfloat16 g_A0lo[B * HID];
__device__ __nv_bfloat16 g_A1hi[B * HID];
__device__ __nv_bfloat16 g_A1lo[B * HID];
__device__ __nv_bfloat16 g_xhi[B * INP];
__device__ __nv_bfloat16 g_xlo[B * INP];
__device__ float         g_cell[B * HID];
__device__ __nv_bfloat16 g_Wimg[NTILES * CHUNKS * 16384];   // state-K image: [T][C][hi 8K | lo 8K elems]
__device__ __nv_bfloat16 g_Wx_img[NTILES * 16384];          // x-K image: [T][hi|lo]
__device__ __nv_bfloat16 g_W1img[H_CHUNKS * 2 * (NH_PAD * 64)];
__device__ float         g_gx[(size_t)B * NG];              // x @ Wx^T (raw, fp32)
__device__ float         g_bias[NG];
__device__ float         g_b1h[OMID + 2];
__device__ float         g_psum[B];
__device__ int           g_mapA[B];
__device__ int           g_mapB[B];
__device__ int           g_cnt[MAX_IT + 1];

__device__ __forceinline__ float sigf(float z) { return 1.0f / (1.0f + expf(-z)); }

// ---------------- PTX helpers (base ISA only) ---------------------------------
__device__ __forceinline__ uint32_t smem_u32(const void* p) {
    uint32_t a;
    asm("{ .reg .u64 t; cvta.to.shared.u64 t, %1; cvt.u32.u64 %0, t; }" : "=r"(a) : "l"(p));
    return a;
}
__device__ __forceinline__ void cp16(uint32_t dst, const void* src) {
    asm volatile("cp.async.cg.shared.global [%0], [%1], 16;" :: "r"(dst), "l"(src));
}
#define CP_COMMIT() asm volatile("cp.async.commit_group;" ::: "memory")
#define CP_WAIT(n)  asm volatile("cp.async.wait_group %0;" :: "n"(n) : "memory")

#define LDM4(r, addr) \
    asm volatile("ldmatrix.sync.aligned.m8n8.x4.shared.b16 {%0,%1,%2,%3}, [%4];" \
        : "=r"((r)[0]), "=r"((r)[1]), "=r"((r)[2]), "=r"((r)[3]) : "r"(addr))

#define MMA16816(acc, a, b0v, b1v) \
    asm volatile("mma.sync.aligned.m16n8k16.row.col.f32.bf16.bf16.f32 " \
        "{%0,%1,%2,%3}, {%4,%5,%6,%7}, {%8,%9}, {%0,%1,%2,%3};" \
        : "+f"((acc)[0]), "+f"((acc)[1]), "+f"((acc)[2]), "+f"((acc)[3]) \
        : "r"((a)[0]), "r"((a)[1]), "r"((a)[2]), "r"((a)[3]), "r"(b0v), "r"(b1v))

__device__ __forceinline__ unsigned short bfu(__nv_bfloat16 v) {
    return *reinterpret_cast<unsigned short*>(&v);
}
__device__ __forceinline__ void split8(const float* w, uint4& hv, uint4& lv) {
    unsigned short hs[8], ls[8];
#pragma unroll
    for (int u = 0; u < 8; u++) {
        __nv_bfloat16 hi = __float2bfloat16(w[u]);
        __nv_bfloat16 lo = __float2bfloat16(w[u] - __bfloat162float(hi));
        hs[u] = bfu(hi); ls[u] = bfu(lo);
    }
    hv = make_uint4((uint32_t)hs[0] | ((uint32_t)hs[1] << 16),
                    (uint32_t)hs[2] | ((uint32_t)hs[3] << 16),
                    (uint32_t)hs[4] | ((uint32_t)hs[5] << 16),
                    (uint32_t)hs[6] | ((uint32_t)hs[7] << 16));
    lv = make_uint4((uint32_t)ls[0] | ((uint32_t)ls[1] << 16),
                    (uint32_t)ls[2] | ((uint32_t)ls[3] << 16),
                    (uint32_t)ls[4] | ((uint32_t)ls[5] << 16),
                    (uint32_t)ls[6] | ((uint32_t)ls[7] << 16));
}

// ---------------- init: split x, reset maps/psum/out --------------------------
__global__ void k_init(const float* __restrict__ x, float* __restrict__ out) {
    const int row = blockIdx.x;
    const int t = threadIdx.x;                 // 64 threads
    float v = x[row * INP + t];
    __nv_bfloat16 hi = __float2bfloat16(v);
    __nv_bfloat16 lo = __float2bfloat16(v - __bfloat162float(hi));
    g_xhi[row * INP + t] = hi;
    g_xlo[row * INP + t] = lo;
    if (t == 0) {
        g_psum[row] = 0.0f;
        g_mapA[row] = row;
        out[row] = 0.0f;
    }
    if (row == 0 && t <= MAX_IT) g_cnt[t] = (t == 0) ? B : 0;
}

// ---------------- pack weights ------------------------------------------------
__global__ void k_pack(
    const float* __restrict__ Wxi, const float* __restrict__ Whi,
    const float* __restrict__ bxi, const float* __restrict__ bhi,
    const float* __restrict__ Wxf, const float* __restrict__ Whf,
    const float* __restrict__ bxf, const float* __restrict__ bhf,
    const float* __restrict__ Wxc, const float* __restrict__ Whc,
    const float* __restrict__ bxc, const float* __restrict__ bhc,
    const float* __restrict__ Wxo, const float* __restrict__ Who,
    const float* __restrict__ bxo, const float* __restrict__ bho,
    const float* __restrict__ W1,  const float* __restrict__ b1,
    const float* __restrict__ Whalt, const float* __restrict__ bhalt)
{
    int idx = blockIdx.x * blockDim.x + threadIdx.x;
    if (idx < NG * (KA / 8)) {
        const int n = idx / (KA / 8);
        const int kb = idx % (KA / 8);         // 8-elem k block (0..135)
        const int g = n & 3;
        const int j = n >> 2;
        const float* Wx = (g == 0) ? Wxi : (g == 1) ? Wxf : (g == 2) ? Wxc : Wxo;
        const float* Wh = (g == 0) ? Whi : (g == 1) ? Whf : (g == 2) ? Whc : Who;
        float w[8];
        if (kb < 8) {
            const float* s = Wx + j * INP + kb * 8;
#pragma unroll
            for (int u = 0; u < 8; u++) w[u] = s[u];
        } else {
            const float* s = Wh + j * HID + (kb - 8) * 8;
#pragma unroll
            for (int u = 0; u < 8; u++) w[u] = s[u];
        }
        uint4 hv, lv;
        split8(w, hv, lv);
        const int T = n >> 7, nr = n & 127;
        if (kb < 8) {   // x-part image
            const unsigned byte = ((unsigned)(nr * 128 + kb * 16)) ^ (((unsigned)(nr & 7)) << 4);
            const unsigned off_b = (unsigned)(T * 32768) + byte;
            *(uint4*)((char*)g_Wx_img + off_b) = hv;
            *(uint4*)((char*)g_Wx_img + off_b + 16384) = lv;
        } else {        // state-part image
            const int C = (kb - 8) >> 3, kq = (kb - 8) & 7;
            const unsigned byte = ((unsigned)(nr * 128 + kq * 16)) ^ (((unsigned)(nr & 7)) << 4);
            const unsigned off_b = (unsigned)((T * CHUNKS + C) * 32768) + byte;
            *(uint4*)((char*)g_Wimg + off_b) = hv;
            *(uint4*)((char*)g_Wimg + off_b + 16384) = lv;
        }
        return;
    }
    idx -= NG * (KA / 8);
    if (idx < NH_PAD * (HID / 8)) {            // head W1/Whalt image
        const int n = idx / (HID / 8);
        const int kb = idx % (HID / 8);
        float w[8];
#pragma unroll
        for (int u = 0; u < 8; u++) {
            const int k = kb * 8 + u;
            w[u] = (n < OMID) ? W1[n * HID + k] : (n == OMID ? Whalt[k] : 0.0f);
        }
        uint4 hv, lv;
        split8(w, hv, lv);
        const int C = kb >> 3;
        const unsigned byte = ((unsigned)(n * 128 + (kb & 7) * 16)) ^ (((unsigned)(n & 7)) << 4);
        const unsigned off_b = (unsigned)(C * 36864) + byte;
        *(uint4*)((char*)g_W1img + off_b) = hv;
        *(uint4*)((char*)g_W1img + off_b + 18432) = lv;
        return;
    }
    idx -= NH_PAD * (HID / 8);
    if (idx < NG) {
        const int g = idx & 3;
        const int j = idx >> 2;
        const float* bx = (g == 0) ? bxi : (g == 1) ? bxf : (g == 2) ? bxc : bxo;
        const float* bh = (g == 0) ? bhi : (g == 1) ? bhf : (g == 2) ? bhc : bho;
        g_bias[idx] = bx[j] + bh[j];
        return;
    }
    idx -= NG;
    if (idx < OMID) { g_b1h[idx] = b1[idx]; return; }
    idx -= OMID;
    if (idx == 0) g_b1h[OMID] = bhalt[0];
}

// ---------------- k_gx: gx = x @ Wx^T (K=64, one chunk, bf16 split) -----------
__global__ __launch_bounds__(256, 1) void k_gx() {
    extern __shared__ char smem[];
    const int m0 = blockIdx.y * BM;
    const int n0 = blockIdx.x * BN;
    const int tid = threadIdx.x;
    const int wrp = tid >> 5;
    const int lane = tid & 31;

    const uint32_t sb0 = smem_u32(smem);
    const uint32_t tiles = (sb0 + 1023) & ~1023u;
    char* tilesPtr = smem + (tiles - sb0);

    const int myrow = m0 + tid;
    const char* pAh = (const char*)(g_xhi + (size_t)myrow * INP);
    const char* pAl = (const char*)(g_xlo + (size_t)myrow * INP);
    const uint32_t aswz = (uint32_t)(tid & 7) << 4;
    const uint32_t aDstRow = (uint32_t)tid * 128;
    const char* pW = (const char*)g_Wx_img + (size_t)blockIdx.x * 32768;

    {
        const uint32_t tb = tiles;
#pragma unroll
        for (int u = 0; u < 8; u++) {
            const uint32_t d = aDstRow + (((uint32_t)(u * 16)) ^ aswz);
            cp16(tb + d, pAh + u * 16);
            cp16(tb + 32768 + d, pAl + u * 16);
        }
#pragma unroll
        for (int q = 0; q < 4; q++) {
            const uint32_t o = (uint32_t)(tid + q * 256) << 4;
            cp16(tb + 65536 + o, pW + o);
            cp16(tb + 81920 + o, pW + 16384 + o);
        }
        CP_COMMIT();
    }

    const int wm = (wrp & 3) * 64;
    const int wn = (wrp >> 2) * 64;
    const uint32_t fswz = (uint32_t)(lane & 7) << 4;
    const uint32_t aRowOff = (uint32_t)(wm + (lane & 15)) * 128;
    const uint32_t aKsel = (uint32_t)(lane >> 4) * 16;
    const uint32_t bRowOff = (uint32_t)(wn + (lane & 7) + ((lane >> 4) << 3)) * 128;
    const uint32_t bKsel = (uint32_t)((lane >> 3) & 1) * 16;

    float acc[4][8][4];
#pragma unroll
    for (int mi = 0; mi < 4; mi++)
#pragma unroll
        for (int nj = 0; nj < 8; nj++)
#pragma unroll
            for (int e = 0; e < 4; e++) acc[mi][nj][e] = 0.0f;

    CP_WAIT(0);
    __syncthreads();
    {
        const uint32_t ahB = tiles + aRowOff;
        const uint32_t alB = tiles + 32768 + aRowOff;
        const uint32_t whB = tiles + 65536 + bRowOff;
        const uint32_t wlB = tiles + 81920 + bRowOff;
#pragma unroll
        for (int ks = 0; ks < 4; ks++) {
            const uint32_t ak = ((uint32_t)(ks * 32) + aKsel) ^ fswz;
            const uint32_t bk = ((uint32_t)(ks * 32) + bKsel) ^ fswz;
            uint32_t bh[4][4], bl[4][4];
#pragma unroll
            for (int ni = 0; ni < 4; ni++) {
                LDM4(bh[ni], whB + ni * 2048 + bk);
                LDM4(bl[ni], wlB + ni * 2048 + bk);
            }
#pragma unroll
            for (int mi = 0; mi < 4; mi++) {
                uint32_t ah[4], al[4];
                LDM4(ah, ahB + mi * 2048 + ak);
                LDM4(al, alB + mi * 2048 + ak);
#pragma unroll
                for (int nj = 0; nj < 8; nj++) {
                    const int ni = nj >> 1, pr = (nj & 1) * 2;
                    MMA16816(acc[mi][nj], ah, bh[ni][pr], bh[ni][pr + 1]);
                    MMA16816(acc[mi][nj], ah, bl[ni][pr], bl[ni][pr + 1]);
                    MMA16816(acc[mi][nj], al, bh[ni][pr], bh[ni][pr + 1]);
                }
            }
        }
    }
    __syncthreads();

    float* C = (float*)tilesPtr;
    {
        const int r0 = wm + (lane >> 2);
        const int c0 = wn + 2 * (lane & 3);
#pragma unroll
        for (int mi = 0; mi < 4; mi++)
#pragma unroll
            for (int nj = 0; nj < 8; nj++) {
                float* p = C + (r0 + mi * 16) * CSTRIDE + c0 + nj * 8;
                p[0] = acc[mi][nj][0];
                p[1] = acc[mi][nj][1];
                p[8 * CSTRIDE]     = acc[mi][nj][2];
                p[8 * CSTRIDE + 1] = acc[mi][nj][3];
            }
    }
    __syncthreads();

    float* gxo = g_gx + (size_t)myrow * NG + n0;
    const float* Crow = C + tid * CSTRIDE;
#pragma unroll
    for (int u = 0; u < 32; u++)
        *(float4*)(gxo + u * 4) = *(const float4*)(Crow + u * 4);
}

// ---------------- k_t0: pointwise t=0 LSTM (state=cell=0 in) ------------------
__global__ __launch_bounds__(256) void k_t0() {
    const int row = blockIdx.x;
    const int q = threadIdx.x;          // 256 threads, 4 units each
    const int j0 = q * 4;
    const float* gx = g_gx + (size_t)row * NG + j0 * 4;
    const float* bb = g_bias + j0 * 4;
    float cc[4];
    uint32_t hp[2], lp[2];
#pragma unroll
    for (int u = 0; u < 4; u++) {
        const float4 gv = *(const float4*)(gx + u * 4);
        const float4 bv = *(const float4*)(bb + u * 4);
        const float ig = sigf (gv.x + bv.x);
        const float cg = tanhf(gv.z + bv.z);
        const float og = sigf (gv.w + bv.w);
        const float c2 = ig * cg;       // f * 0 + i * c
        cc[u] = c2;
        const float s = og * tanhf(c2);
        const __nv_bfloat16 hi = __float2bfloat16(s);
        const __nv_bfloat16 lo = __float2bfloat16(s - __bfloat162float(hi));
        const uint32_t hu = bfu(hi), lu = bfu(lo);
        if (u & 1) { hp[u >> 1] |= hu << 16; lp[u >> 1] |= lu << 16; }
        else       { hp[u >> 1] = hu;        lp[u >> 1] = lu; }
    }
    *(float4*)(g_cell + (size_t)row * HID + j0) = make_float4(cc[0], cc[1], cc[2], cc[3]);
    *(uint2*)((char*)g_A1hi + ((size_t)row * HID + j0) * 2) = make_uint2(hp[0], hp[1]);
    *(uint2*)((char*)g_A1lo + ((size_t)row * HID + j0) * 2) = make_uint2(lp[0], lp[1]);
}

// ---------------- gates (t>=1): K=1024 state GEMM + gx-folded epilogue --------
__global__ __launch_bounds__(256, 1) void k_gates(int t) {
    extern __shared__ char smem[];
    __shared__ int sRow[BM];

    const int count = g_cnt[t];
    const int m0 = blockIdx.y * BM;
    if (m0 >= count) return;
    const int n0 = blockIdx.x * BN;
    const int tid = threadIdx.x;
    const int wrp = tid >> 5;
    const int lane = tid & 31;

    const uint32_t sb0 = smem_u32(smem);
    const uint32_t tiles = (sb0 + 1023) & ~1023u;
    char* tilesPtr = smem + (tiles - sb0);

    const int* map = (t & 1) ? g_mapB : g_mapA;
    sRow[tid] = map[min(m0 + tid, count - 1)];
    __syncthreads();

    const __nv_bfloat16* Ahi = (t & 1) ? g_A1hi : g_A0hi;
    const __nv_bfloat16* Alo = (t & 1) ? g_A1lo : g_A0lo;
    __nv_bfloat16* Aout_hi = (t & 1) ? g_A0hi : g_A1hi;
    __nv_bfloat16* Aout_lo = (t & 1) ? g_A0lo : g_A1lo;

    const int myrow = sRow[tid];
    const char* pAh = (const char*)(Ahi + (size_t)myrow * HID);
    const char* pAl = (const char*)(Alo + (size_t)myrow * HID);
    const uint32_t aswz = (uint32_t)(tid & 7) << 4;
    const uint32_t aDstRow = (uint32_t)tid * 128;
    const char* pW = (const char*)g_Wimg + (size_t)blockIdx.x * (CHUNKS * 32768);

    auto load_chunk = [&](int c, int stage) {
        const uint32_t tb = tiles + (uint32_t)stage * G_STAGE;
        const char* sh = pAh + c * 128;
        const char* sl = pAl + c * 128;
#pragma unroll
        for (int u = 0; u < 8; u++) {
            const uint32_t d = aDstRow + (((uint32_t)(u * 16)) ^ aswz);
            cp16(tb + d, sh + u * 16);
            cp16(tb + 32768 + d, sl + u * 16);
        }
        const char* wc = pW + c * 32768;
#pragma unroll
        for (int q = 0; q < 4; q++) {
            const uint32_t o = (uint32_t)(tid + q * 256) << 4;
            cp16(tb + 65536 + o, wc + o);
            cp16(tb + 81920 + o, wc + 16384 + o);
        }
        CP_COMMIT();
    };

    const int wm = (wrp & 3) * 64;
    const int wn = (wrp >> 2) * 64;
    const uint32_t fswz = (uint32_t)(lane & 7) << 4;
    const uint32_t aRowOff = (uint32_t)(wm + (lane & 15)) * 128;
    const uint32_t aKsel = (uint32_t)(lane >> 4) * 16;
    const uint32_t bRowOff = (uint32_t)(wn + (lane & 7) + ((lane >> 4) << 3)) * 128;
    const uint32_t bKsel = (uint32_t)((lane >> 3) & 1) * 16;

    float acc[4][8][4];
#pragma unroll
    for (int mi = 0; mi < 4; mi++)
#pragma unroll
        for (int nj = 0; nj < 8; nj++)
#pragma unroll
            for (int e = 0; e < 4; e++) acc[mi][nj][e] = 0.0f;

    load_chunk(0, 0);
    for (int c = 0; c < CHUNKS; c++) {
        const int stage = c & 1;
        CP_WAIT(0);
        __syncthreads();
        if (c + 1 < CHUNKS) load_chunk(c + 1, stage ^ 1);

        const uint32_t tb = tiles + (uint32_t)stage * G_STAGE;
        const uint32_t ahB = tb + aRowOff;
        const uint32_t alB = tb + 32768 + aRowOff;
        const uint32_t whB = tb + 65536 + bRowOff;
        const uint32_t wlB = tb + 81920 + bRowOff;

#pragma unroll
        for (int ks = 0; ks < 4; ks++) {
            const uint32_t ak = ((uint32_t)(ks * 32) + aKsel) ^ fswz;
            const uint32_t bk = ((uint32_t)(ks * 32) + bKsel) ^ fswz;
            uint32_t bh[4][4], bl[4][4];
#pragma unroll
            for (int ni = 0; ni < 4; ni++) {
                LDM4(bh[ni], whB + ni * 2048 + bk);
                LDM4(bl[ni], wlB + ni * 2048 + bk);
            }
#pragma unroll
            for (int mi = 0; mi < 4; mi++) {
                uint32_t ah[4], al[4];
                LDM4(ah, ahB + mi * 2048 + ak);
                LDM4(al, alB + mi * 2048 + ak);
#pragma unroll
                for (int nj = 0; nj < 8; nj++) {
                    const int ni = nj >> 1, pr = (nj & 1) * 2;
                    MMA16816(acc[mi][nj], ah, bh[ni][pr], bh[ni][pr + 1]);
                    MMA16816(acc[mi][nj], ah, bl[ni][pr], bl[ni][pr + 1]);
                    MMA16816(acc[mi][nj], al, bh[ni][pr], bh[ni][pr + 1]);
                }
            }
        }
    }
    __syncthreads();

    float* C = (float*)tilesPtr;
    {
        const int r0 = wm + (lane >> 2);
        const int c0 = wn + 2 * (lane & 3);
#pragma unroll
        for (int mi = 0; mi < 4; mi++)
#pragma unroll
            for (int nj = 0; nj < 8; nj++) {
                float* p = C + (r0 + mi * 16) * CSTRIDE + c0 + nj * 8;
                p[0] = acc[mi][nj][0];
                p[1] = acc[mi][nj][1];
                p[8 * CSTRIDE]     = acc[mi][nj][2];
                p[8 * CSTRIDE + 1] = acc[mi][nj][3];
            }
    }
    __syncthreads();

    // ---- LSTM epilogue: logits = acc + gx + bias ----
    if (m0 + tid < count) {
        const int rowg = sRow[tid];
        const float* Crow = C + tid * CSTRIDE;
        const float* bb = g_bias + n0;
        const float* gxp = g_gx + (size_t)rowg * NG + n0;
        const int j0 = n0 >> 2;
        float* cellp = g_cell + (size_t)rowg * HID + j0;
        uint32_t hp[16], lp[16];
#pragma unroll
        for (int u = 0; u < 32; u++) {
            const float4 gv = *(const float4*)(Crow + u * 4);
            const float4 xv = *(const float4*)(gxp + u * 4);
            const float ig = sigf (gv.x + xv.x + bb[u * 4 + 0]);
            const float fg = sigf (gv.y + xv.y + bb[u * 4 + 1]);
            const float cg = tanhf(gv.z + xv.z + bb[u * 4 + 2]);
            const float og = sigf (gv.w + xv.w + bb[u * 4 + 3]);
            const float c2 = fg * cellp[u] + ig * cg;
            cellp[u] = c2;
            const float s = og * tanhf(c2);
            const __nv_bfloat16 hi = __float2bfloat16(s);
            const __nv_bfloat16 lo = __float2bfloat16(s - __bfloat162float(hi));
            const uint32_t hu = bfu(hi), lu = bfu(lo);
            if (u & 1) { hp[u >> 1] |= hu << 16; lp[u >> 1] |= lu << 16; }
            else       { hp[u >> 1] = hu;        lp[u >> 1] = lu; }
        }
        uint4* sh = (uint4*)(Aout_hi + (size_t)rowg * HID + j0);
        uint4* sl = (uint4*)(Aout_lo + (size_t)rowg * HID + j0);
#pragma unroll
        for (int v = 0; v < 4; v++) {
            sh[v] = make_uint4(hp[v * 4], hp[v * 4 + 1], hp[v * 4 + 2], hp[v * 4 + 3]);
            sl[v] = make_uint4(lp[v * 4], lp[v * 4 + 1], lp[v * 4 + 2], lp[v * 4 + 3]);
        }
    }
}

// ---------------- head: mma.sync GEMM (state @ [W1;Whalt]^T) + finalize -------
__global__ __launch_bounds__(256, 1) void k_head(int t,
                                                 const float* __restrict__ W2,
                                                 const float* __restrict__ b2,
                                                 float* __restrict__ out) {
    extern __shared__ char smem[];
    __shared__ int sRow[HBM];

    const int count = g_cnt[t];
    const int base = blockIdx.x * HBM;
    if (base >= count) return;
    const int tid = threadIdx.x;
    const int wrp = tid >> 5;
    const int lane = tid & 31;

    const uint32_t sb0 = smem_u32(smem);
    const uint32_t tiles = (sb0 + 1023) & ~1023u;
    char* tilesPtr = smem + (tiles - sb0);

    const int* map = (t & 1) ? g_mapB : g_mapA;
    int* map_next  = (t & 1) ? g_mapA : g_mapB;
    if (tid < HBM) sRow[tid] = map[min(base + tid, count - 1)];
    __syncthreads();

    // state after iter t: t even -> A1 (k_t0 / even k_gates write A1), t odd -> A0
    const __nv_bfloat16* Ahi = (t & 1) ? g_A0hi : g_A1hi;
    const __nv_bfloat16* Alo = (t & 1) ? g_A0lo : g_A1lo;

    const int arow = tid & 127;
    const int asel = tid >> 7;
    const char* pA = (const char*)((asel ? Alo : Ahi) + (size_t)sRow[arow] * HID);
    const uint32_t aswz = (uint32_t)(arow & 7) << 4;
    const uint32_t aDstRow = (uint32_t)arow * 128 + (asel ? 16384u : 0u);
    const char* pW = (const char*)g_W1img;

    auto load_chunk = [&](int c, int stage) {
        const uint32_t tb = tiles + (uint32_t)stage * H_STAGE;
        const char* src = pA + c * 128;
#pragma unroll
        for (int u = 0; u < 8; u++)
            cp16(tb + aDstRow + (((uint32_t)(u * 16)) ^ aswz), src + u * 16);
        const char* w = pW + c * 36864;
#pragma unroll
        for (int q = 0; q < 9; q++) {
            const uint32_t i = (uint32_t)(tid + q * 256);
            cp16(tb + 32768 + i * 16, w + (size_t)i * 16);
        }
        CP_COMMIT();
    };

    const int wm = wrp * 16;
    const uint32_t fswz = (uint32_t)(lane & 7) << 4;
    const uint32_t aRowOff = (uint32_t)(wm + (lane & 15)) * 128;
    const uint32_t aKsel = (uint32_t)(lane >> 4) * 16;
    const uint32_t bRowOff = (uint32_t)((lane & 7) + ((lane >> 4) << 3)) * 128;
    const uint32_t bKsel = (uint32_t)((lane >> 3) & 1) * 16;

    float acc[18][4];
#pragma unroll
    for (int nj = 0; nj < 18; nj++)
#pragma unroll
        for (int e = 0; e < 4; e++) acc[nj][e] = 0.0f;

    load_chunk(0, 0);
    for (int c = 0; c < H_CHUNKS; c++) {
        const int stage = c & 1;
        CP_WAIT(0);
        __syncthreads();
        if (c + 1 < H_CHUNKS) load_chunk(c + 1, stage ^ 1);

        const uint32_t tb = tiles + (uint32_t)stage * H_STAGE;
        const uint32_t ahB = tb + aRowOff;
        const uint32_t alB = tb + 16384 + aRowOff;
        const uint32_t whB = tb + 32768 + bRowOff;
        const uint32_t wlB = tb + 51200 + bRowOff;

#pragma unroll
        for (int ks = 0; ks < 4; ks++) {
            const uint32_t ak = ((uint32_t)(ks * 32) + aKsel) ^ fswz;
            const uint32_t bk = ((uint32_t)(ks * 32) + bKsel) ^ fswz;
            uint32_t ah[4], al[4], bh[9][4], bl[9][4];
            LDM4(ah, ahB + ak);
            LDM4(al, alB + ak);
#pragma unroll
            for (int ni = 0; ni < 9; ni++) {
                LDM4(bh[ni], whB + ni * 2048 + bk);
                LDM4(bl[ni], wlB + ni * 2048 + bk);
            }
#pragma unroll
            for (int nj = 0; nj < 18; nj++) {
                const int ni = nj >> 1, pr = (nj & 1) * 2;
                MMA16816(acc[nj], ah, bh[ni][pr], bh[ni][pr + 1]);
                MMA16816(acc[nj], ah, bl[ni][pr], bl[ni][pr + 1]);
                MMA16816(acc[nj], al, bh[ni][pr], bh[ni][pr + 1]);
            }
        }
    }
    __syncthreads();

    float* C = (float*)tilesPtr;
    {
        const int r0 = wm + (lane >> 2);
        const int c0 = 2 * (lane & 3);
#pragma unroll
        for (int nj = 0; nj < 18; nj++) {
            float* p = C + r0 * HCS + c0 + nj * 8;
            p[0] = acc[nj][0];
            p[1] = acc[nj][1];
            p[8 * HCS]     = acc[nj][2];
            p[8 * HCS + 1] = acc[nj][3];
        }
    }
    __syncthreads();

    const float4 w2v = *(const float4*)(W2 + lane * 4);
    const float4 b1v = *(const float4*)(g_b1h + lane * 4);
    const float bhalt = g_b1h[OMID];

    for (int i = 0; i < 16; i++) {
        const int r = wm + i;
        const int mm = base + r;
        if (mm >= count) continue;
        const int rowg = sRow[r];

        const float4 mv = *(const float4*)&C[r * HCS + lane * 4];
        float acc2 = fmaxf(mv.x + b1v.x, 0.0f) * w2v.x
                   + fmaxf(mv.y + b1v.y, 0.0f) * w2v.y
                   + fmaxf(mv.z + b1v.z, 0.0f) * w2v.z
                   + fmaxf(mv.w + b1v.w, 0.0f) * w2v.w;
#pragma unroll
        for (int off = 16; off; off >>= 1)
            acc2 += __shfl_xor_sync(0xffffffffu, acc2, off);

        if (lane == 0) {
            const float o = sigf(acc2 + b2[0]);
            const float h = sigf(C[r * HCS + OMID] + bhalt);
            const float p = g_psum[rowg];
            const float pn = p + h;
            const bool fin = (pn >= 1.0f - 0.001f) || (t == MAX_IT - 1);
            const float hr = fin ? (1.0f - p) : h;
            out[rowg] += o * hr;
            g_psum[rowg] = fin ? 1.0f : pn;
            if (!fin) {
                int slot = atomicAdd(&g_cnt[t + 1], 1);
                map_next[slot] = rowg;
            }
        }
    }
}

// ---------------- launch ------------------------------------------------------
extern "C" void kernel_launch(void* const* d_in, const int* in_sizes, int n_in,
                              void* d_out, int out_size) {
    const float* x     = (const float*)d_in[0];
    const float* Wxi   = (const float*)d_in[1];
    const float* bxi   = (const float*)d_in[2];
    const float* Whi   = (const float*)d_in[3];
    const float* bhi   = (const float*)d_in[4];
    const float* Wxf   = (const float*)d_in[5];
    const float* bxf   = (const float*)d_in[6];
    const float* Whf   = (const float*)d_in[7];
    const float* bhf   = (const float*)d_in[8];
    const float* Wxc   = (const float*)d_in[9];
    const float* bxc   = (const float*)d_in[10];
    const float* Whc   = (const float*)d_in[11];
    const float* bhc   = (const float*)d_in[12];
    const float* Wxo   = (const float*)d_in[13];
    const float* bxo   = (const float*)d_in[14];
    const float* Who   = (const float*)d_in[15];
    const float* bho   = (const float*)d_in[16];
    const float* Whalt = (const float*)d_in[17];
    const float* bhalt = (const float*)d_in[18];
    const float* W1    = (const float*)d_in[19];
    const float* b1    = (const float*)d_in[20];
    const float* W2    = (const float*)d_in[21];
    const float* b2    = (const float*)d_in[22];
    float* out = (float*)d_out;

    cudaFuncSetAttribute(k_gates, cudaFuncAttributeMaxDynamicSharedMemorySize, SMEM_DYN_G);
    cudaFuncSetAttribute(k_gx,    cudaFuncAttributeMaxDynamicSharedMemorySize, SMEM_DYN_G);
    cudaFuncSetAttribute(k_head,  cudaFuncAttributeMaxDynamicSharedMemorySize, SMEM_DYN_H);

    k_init<<<B, INP>>>(x, out);

    const int tot = NG * (KA / 8) + NH_PAD * (HID / 8) + NG + OMID + 1;
    k_pack<<<(tot + 255) / 256, 256>>>(Wxi, Whi, bxi, bhi,
                                       Wxf, Whf, bxf, bhf,
                                       Wxc, Whc, bxc, bhc,
                                       Wxo, Who, bxo, bho,
                                       W1, b1, Whalt, bhalt);

    k_gx<<<dim3(NTILES, B / BM), 256, SMEM_DYN_G>>>();
    k_t0<<<B, 256>>>();
    k_head<<<B / HBM, 256, SMEM_DYN_H>>>(0, W2, b2, out);

    for (int t = 1; t < MAX_IT; t++) {
        k_gates<<<dim3(NTILES, B / BM), 256, SMEM_DYN_G>>>(t);
        k_head<<<B / HBM, 256, SMEM_DYN_H>>>(t, W2, b2, out);
    }
}

// round 13
// speedup vs baseline: 4.4670x; 1.3937x over previous
#include <cuda_runtime.h>
#include <cuda_fp16.h>
#include <math.h>
#include <stdint.h>

#define B       8192
#define INP     64
#define HID     1024
#define KA      1088
#define NG      4096          // 4 gates * HID, interleaved n = j*4 + g
#define OMID    128
#define MAX_IT  8

#define BM 256
#define BN 128
#define CHUNKS 16             // state K chunks of 64
#define NTILES (NG / BN)      // 32
#define G_STAGE 65536         // A 32K + Wh 16K + Wl 16K
#define SMEM_DYN_G 136192     // max(2 stages 128K, C tile 135168) + pad
#define CSTRIDE 132

// head geometry
#define HBM 128
#define NH_PAD 144
#define H_CHUNKS 16
#define H_STAGE 53248         // A 16K + Wh 18K + Wl 18K
#define SMEM_DYN_H 107520
#define HCS 148

// ---------------- device scratch ---------------------------------------------
__device__ __half g_A0[B * HID];            // state ping-pong (single fp16)
__device__ __half g_A1[B * HID];
__device__ __half g_x[B * INP];
__device__ float  g_cell[B * HID];
__device__ __half g_Wimg[NTILES * CHUNKS * 16384];   // state-K image: [T][C][hi 16KB | lo 16KB]
__device__ __half g_Wx_img[NTILES * 16384];          // x-K image: [T][hi|lo]
__device__ __half g_W1img[H_CHUNKS * 2 * (NH_PAD * 64)];
__device__ float  g_gx[(size_t)B * NG];
__device__ float  g_bias[NG];
__device__ float  g_b1h[OMID + 2];
__device__ float  g_psum[B];
__device__ int    g_mapA[B];
__device__ int    g_mapB[B];
__device__ int    g_cnt[MAX_IT + 1];

__device__ __forceinline__ float sigf(float z) { return 1.0f / (1.0f + expf(-z)); }

// ---------------- PTX helpers (base ISA only) ---------------------------------
__device__ __forceinline__ uint32_t smem_u32(const void* p) {
    uint32_t a;
    asm("{ .reg .u64 t; cvta.to.shared.u64 t, %1; cvt.u32.u64 %0, t; }" : "=r"(a) : "l"(p));
    return a;
}
__device__ __forceinline__ void cp16(uint32_t dst, const void* src) {
    asm volatile("cp.async.cg.shared.global [%0], [%1], 16;" :: "r"(dst), "l"(src));
}
#define CP_COMMIT() asm volatile("cp.async.commit_group;" ::: "memory")
#define CP_WAIT(n)  asm volatile("cp.async.wait_group %0;" :: "n"(n) : "memory")

#define LDM4(r, addr) \
    asm volatile("ldmatrix.sync.aligned.m8n8.x4.shared.b16 {%0,%1,%2,%3}, [%4];" \
        : "=r"((r)[0]), "=r"((r)[1]), "=r"((r)[2]), "=r"((r)[3]) : "r"(addr))

#define MMA16816(acc, a, b0v, b1v) \
    asm volatile("mma.sync.aligned.m16n8k16.row.col.f32.f16.f16.f32 " \
        "{%0,%1,%2,%3}, {%4,%5,%6,%7}, {%8,%9}, {%0,%1,%2,%3};" \
        : "+f"((acc)[0]), "+f"((acc)[1]), "+f"((acc)[2]), "+f"((acc)[3]) \
        : "r"((a)[0]), "r"((a)[1]), "r"((a)[2]), "r"((a)[3]), "r"(b0v), "r"(b1v))

__device__ __forceinline__ unsigned short hfu(__half v) {
    return *reinterpret_cast<unsigned short*>(&v);
}
// split fp32 -> fp16 hi + fp16 lo (hi + lo accurate to ~2^-22)
__device__ __forceinline__ void split8h(const float* w, uint4& hv, uint4& lv) {
    unsigned short hs[8], ls[8];
#pragma unroll
    for (int u = 0; u < 8; u++) {
        __half hi = __float2half_rn(w[u]);
        __half lo = __float2half_rn(w[u] - __half2float(hi));
        hs[u] = hfu(hi); ls[u] = hfu(lo);
    }
    hv = make_uint4((uint32_t)hs[0] | ((uint32_t)hs[1] << 16),
                    (uint32_t)hs[2] | ((uint32_t)hs[3] << 16),
                    (uint32_t)hs[4] | ((uint32_t)hs[5] << 16),
                    (uint32_t)hs[6] | ((uint32_t)hs[7] << 16));
    lv = make_uint4((uint32_t)ls[0] | ((uint32_t)ls[1] << 16),
                    (uint32_t)ls[2] | ((uint32_t)ls[3] << 16),
                    (uint32_t)ls[4] | ((uint32_t)ls[5] << 16),
                    (uint32_t)ls[6] | ((uint32_t)ls[7] << 16));
}

// ---------------- init --------------------------------------------------------
__global__ void k_init(const float* __restrict__ x, float* __restrict__ out) {
    const int row = blockIdx.x;
    const int t = threadIdx.x;                 // 64 threads
    g_x[row * INP + t] = __float2half_rn(x[row * INP + t]);
    if (t == 0) {
        g_psum[row] = 0.0f;
        g_mapA[row] = row;
        out[row] = 0.0f;
    }
    if (row == 0 && t <= MAX_IT) g_cnt[t] = (t == 0) ? B : 0;
}

// ---------------- pack weights (W split fp16 hi/lo) ---------------------------
__global__ void k_pack(
    const float* __restrict__ Wxi, const float* __restrict__ Whi,
    const float* __restrict__ bxi, const float* __restrict__ bhi,
    const float* __restrict__ Wxf, const float* __restrict__ Whf,
    const float* __restrict__ bxf, const float* __restrict__ bhf,
    const float* __restrict__ Wxc, const float* __restrict__ Whc,
    const float* __restrict__ bxc, const float* __restrict__ bhc,
    const float* __restrict__ Wxo, const float* __restrict__ Who,
    const float* __restrict__ bxo, const float* __restrict__ bho,
    const float* __restrict__ W1,  const float* __restrict__ b1,
    const float* __restrict__ Whalt, const float* __restrict__ bhalt)
{
    int idx = blockIdx.x * blockDim.x + threadIdx.x;
    if (idx < NG * (KA / 8)) {
        const int n = idx / (KA / 8);
        const int kb = idx % (KA / 8);
        const int g = n & 3;
        const int j = n >> 2;
        const float* Wx = (g == 0) ? Wxi : (g == 1) ? Wxf : (g == 2) ? Wxc : Wxo;
        const float* Wh = (g == 0) ? Whi : (g == 1) ? Whf : (g == 2) ? Whc : Who;
        float w[8];
        if (kb < 8) {
            const float* s = Wx + j * INP + kb * 8;
#pragma unroll
            for (int u = 0; u < 8; u++) w[u] = s[u];
        } else {
            const float* s = Wh + j * HID + (kb - 8) * 8;
#pragma unroll
            for (int u = 0; u < 8; u++) w[u] = s[u];
        }
        uint4 hv, lv;
        split8h(w, hv, lv);
        const int T = n >> 7, nr = n & 127;
        if (kb < 8) {   // x-part image
            const unsigned byte = ((unsigned)(nr * 128 + kb * 16)) ^ (((unsigned)(nr & 7)) << 4);
            const unsigned off_b = (unsigned)(T * 32768) + byte;
            *(uint4*)((char*)g_Wx_img + off_b) = hv;
            *(uint4*)((char*)g_Wx_img + off_b + 16384) = lv;
        } else {        // state-part image
            const int C = (kb - 8) >> 3, kq = (kb - 8) & 7;
            const unsigned byte = ((unsigned)(nr * 128 + kq * 16)) ^ (((unsigned)(nr & 7)) << 4);
            const unsigned off_b = (unsigned)((T * CHUNKS + C) * 32768) + byte;
            *(uint4*)((char*)g_Wimg + off_b) = hv;
            *(uint4*)((char*)g_Wimg + off_b + 16384) = lv;
        }
        return;
    }
    idx -= NG * (KA / 8);
    if (idx < NH_PAD * (HID / 8)) {            // head W1/Whalt image
        const int n = idx / (HID / 8);
        const int kb = idx % (HID / 8);
        float w[8];
#pragma unroll
        for (int u = 0; u < 8; u++) {
            const int k = kb * 8 + u;
            w[u] = (n < OMID) ? W1[n * HID + k] : (n == OMID ? Whalt[k] : 0.0f);
        }
        uint4 hv, lv;
        split8h(w, hv, lv);
        const int C = kb >> 3;
        const unsigned byte = ((unsigned)(n * 128 + (kb & 7) * 16)) ^ (((unsigned)(n & 7)) << 4);
        const unsigned off_b = (unsigned)(C * 36864) + byte;
        *(uint4*)((char*)g_W1img + off_b) = hv;
        *(uint4*)((char*)g_W1img + off_b + 18432) = lv;
        return;
    }
    idx -= NH_PAD * (HID / 8);
    if (idx < NG) {
        const int g = idx & 3;
        const int j = idx >> 2;
        const float* bx = (g == 0) ? bxi : (g == 1) ? bxf : (g == 2) ? bxc : bxo;
        const float* bh = (g == 0) ? bhi : (g == 1) ? bhf : (g == 2) ? bhc : bho;
        g_bias[idx] = bx[j] + bh[j];
        return;
    }
    idx -= NG;
    if (idx < OMID) { g_b1h[idx] = b1[idx]; return; }
    idx -= OMID;
    if (idx == 0) g_b1h[OMID] = bhalt[0];
}

// ---------------- k_gx: gx = x @ Wx^T (K=64, one chunk, 2-term fp16) ----------
__global__ __launch_bounds__(256, 1) void k_gx() {
    extern __shared__ char smem[];
    const int m0 = blockIdx.y * BM;
    const int n0 = blockIdx.x * BN;
    const int tid = threadIdx.x;
    const int wrp = tid >> 5;
    const int lane = tid & 31;

    const uint32_t sb0 = smem_u32(smem);
    const uint32_t tiles = (sb0 + 1023) & ~1023u;
    char* tilesPtr = smem + (tiles - sb0);

    const int myrow = m0 + tid;
    const char* pA = (const char*)(g_x + (size_t)myrow * INP);
    const uint32_t aswz = (uint32_t)(tid & 7) << 4;
    const uint32_t aDstRow = (uint32_t)tid * 128;
    const char* pW = (const char*)g_Wx_img + (size_t)blockIdx.x * 32768;

    {
#pragma unroll
        for (int u = 0; u < 8; u++)
            cp16(tiles + aDstRow + (((uint32_t)(u * 16)) ^ aswz), pA + u * 16);
#pragma unroll
        for (int q = 0; q < 8; q++) {
            const uint32_t o = (uint32_t)(tid + q * 256) << 4;
            cp16(tiles + 32768 + o, pW + o);
        }
        CP_COMMIT();
    }

    const int wm = (wrp & 3) * 64;
    const int wn = (wrp >> 2) * 64;
    const uint32_t fswz = (uint32_t)(lane & 7) << 4;
    const uint32_t aRowOff = (uint32_t)(wm + (lane & 15)) * 128;
    const uint32_t aKsel = (uint32_t)(lane >> 4) * 16;
    const uint32_t bRowOff = (uint32_t)(wn + (lane & 7) + ((lane >> 4) << 3)) * 128;
    const uint32_t bKsel = (uint32_t)((lane >> 3) & 1) * 16;

    float acc[4][8][4];
#pragma unroll
    for (int mi = 0; mi < 4; mi++)
#pragma unroll
        for (int nj = 0; nj < 8; nj++)
#pragma unroll
            for (int e = 0; e < 4; e++) acc[mi][nj][e] = 0.0f;

    CP_WAIT(0);
    __syncthreads();
    {
        const uint32_t ahB = tiles + aRowOff;
        const uint32_t whB = tiles + 32768 + bRowOff;
        const uint32_t wlB = tiles + 49152 + bRowOff;
#pragma unroll
        for (int ks = 0; ks < 4; ks++) {
            const uint32_t ak = ((uint32_t)(ks * 32) + aKsel) ^ fswz;
            const uint32_t bk = ((uint32_t)(ks * 32) + bKsel) ^ fswz;
            uint32_t bh[4][4], bl[4][4];
#pragma unroll
            for (int ni = 0; ni < 4; ni++) {
                LDM4(bh[ni], whB + ni * 2048 + bk);
                LDM4(bl[ni], wlB + ni * 2048 + bk);
            }
#pragma unroll
            for (int mi = 0; mi < 4; mi++) {
                uint32_t ah[4];
                LDM4(ah, ahB + mi * 2048 + ak);
#pragma unroll
                for (int nj = 0; nj < 8; nj++) {
                    const int ni = nj >> 1, pr = (nj & 1) * 2;
                    MMA16816(acc[mi][nj], ah, bh[ni][pr], bh[ni][pr + 1]);
                    MMA16816(acc[mi][nj], ah, bl[ni][pr], bl[ni][pr + 1]);
                }
            }
        }
    }
    __syncthreads();

    float* C = (float*)tilesPtr;
    {
        const int r0 = wm + (lane >> 2);
        const int c0 = wn + 2 * (lane & 3);
#pragma unroll
        for (int mi = 0; mi < 4; mi++)
#pragma unroll
            for (int nj = 0; nj < 8; nj++) {
                float* p = C + (r0 + mi * 16) * CSTRIDE + c0 + nj * 8;
                p[0] = acc[mi][nj][0];
                p[1] = acc[mi][nj][1];
                p[8 * CSTRIDE]     = acc[mi][nj][2];
                p[8 * CSTRIDE + 1] = acc[mi][nj][3];
            }
    }
    __syncthreads();

    float* gxo = g_gx + (size_t)myrow * NG + n0;
    const float* Crow = C + tid * CSTRIDE;
#pragma unroll
    for (int u = 0; u < 32; u++)
        *(float4*)(gxo + u * 4) = *(const float4*)(Crow + u * 4);
}

// ---------------- k_t0: pointwise t=0 LSTM ------------------------------------
__global__ __launch_bounds__(256) void k_t0() {
    const int row = blockIdx.x;
    const int q = threadIdx.x;
    const int j0 = q * 4;
    const float* gx = g_gx + (size_t)row * NG + j0 * 4;
    const float* bb = g_bias + j0 * 4;
    float cc[4];
    uint32_t sp[2];
#pragma unroll
    for (int u = 0; u < 4; u++) {
        const float4 gv = *(const float4*)(gx + u * 4);
        const float4 bv = *(const float4*)(bb + u * 4);
        const float ig = sigf (gv.x + bv.x);
        const float cg = tanhf(gv.z + bv.z);
        const float og = sigf (gv.w + bv.w);
        const float c2 = ig * cg;
        cc[u] = c2;
        const float s = og * tanhf(c2);
        const uint32_t su = hfu(__float2half_rn(s));
        if (u & 1) sp[u >> 1] |= su << 16;
        else       sp[u >> 1] = su;
    }
    *(float4*)(g_cell + (size_t)row * HID + j0) = make_float4(cc[0], cc[1], cc[2], cc[3]);
    *(uint2*)((char*)g_A1 + ((size_t)row * HID + j0) * 2) = make_uint2(sp[0], sp[1]);
}

// ---------------- gates (t>=1): 2-term fp16 GEMM + gx-folded epilogue ---------
__global__ __launch_bounds__(256, 1) void k_gates(int t) {
    extern __shared__ char smem[];
    __shared__ int sRow[BM];

    const int count = g_cnt[t];
    const int m0 = blockIdx.y * BM;
    if (m0 >= count) return;
    const int n0 = blockIdx.x * BN;
    const int tid = threadIdx.x;
    const int wrp = tid >> 5;
    const int lane = tid & 31;

    const uint32_t sb0 = smem_u32(smem);
    const uint32_t tiles = (sb0 + 1023) & ~1023u;
    char* tilesPtr = smem + (tiles - sb0);

    const int* map = (t & 1) ? g_mapB : g_mapA;
    sRow[tid] = map[min(m0 + tid, count - 1)];
    __syncthreads();

    const __half* Ain = (t & 1) ? g_A1 : g_A0;
    __half*       Aout = (t & 1) ? g_A0 : g_A1;

    const int myrow = sRow[tid];
    const char* pA = (const char*)(Ain + (size_t)myrow * HID);
    const uint32_t aswz = (uint32_t)(tid & 7) << 4;
    const uint32_t aDstRow = (uint32_t)tid * 128;
    const char* pW = (const char*)g_Wimg + (size_t)blockIdx.x * (CHUNKS * 32768);

    auto load_chunk = [&](int c, int stage) {
        const uint32_t tb = tiles + (uint32_t)stage * G_STAGE;
        const char* sa = pA + c * 128;
#pragma unroll
        for (int u = 0; u < 8; u++)
            cp16(tb + aDstRow + (((uint32_t)(u * 16)) ^ aswz), sa + u * 16);
        const char* wc = pW + c * 32768;
#pragma unroll
        for (int q = 0; q < 8; q++) {
            const uint32_t o = (uint32_t)(tid + q * 256) << 4;
            cp16(tb + 32768 + o, wc + o);
        }
        CP_COMMIT();
    };

    const int wm = (wrp & 3) * 64;
    const int wn = (wrp >> 2) * 64;
    const uint32_t fswz = (uint32_t)(lane & 7) << 4;
    const uint32_t aRowOff = (uint32_t)(wm + (lane & 15)) * 128;
    const uint32_t aKsel = (uint32_t)(lane >> 4) * 16;
    const uint32_t bRowOff = (uint32_t)(wn + (lane & 7) + ((lane >> 4) << 3)) * 128;
    const uint32_t bKsel = (uint32_t)((lane >> 3) & 1) * 16;

    float acc[4][8][4];
#pragma unroll
    for (int mi = 0; mi < 4; mi++)
#pragma unroll
        for (int nj = 0; nj < 8; nj++)
#pragma unroll
            for (int e = 0; e < 4; e++) acc[mi][nj][e] = 0.0f;

    load_chunk(0, 0);
    for (int c = 0; c < CHUNKS; c++) {
        const int stage = c & 1;
        CP_WAIT(0);
        __syncthreads();
        if (c + 1 < CHUNKS) load_chunk(c + 1, stage ^ 1);

        const uint32_t tb = tiles + (uint32_t)stage * G_STAGE;
        const uint32_t ahB = tb + aRowOff;
        const uint32_t whB = tb + 32768 + bRowOff;
        const uint32_t wlB = tb + 49152 + bRowOff;

#pragma unroll
        for (int ks = 0; ks < 4; ks++) {
            const uint32_t ak = ((uint32_t)(ks * 32) + aKsel) ^ fswz;
            const uint32_t bk = ((uint32_t)(ks * 32) + bKsel) ^ fswz;
            uint32_t bh[4][4], bl[4][4];
#pragma unroll
            for (int ni = 0; ni < 4; ni++) {
                LDM4(bh[ni], whB + ni * 2048 + bk);
                LDM4(bl[ni], wlB + ni * 2048 + bk);
            }
#pragma unroll
            for (int mi = 0; mi < 4; mi++) {
                uint32_t ah[4];
                LDM4(ah, ahB + mi * 2048 + ak);
#pragma unroll
                for (int nj = 0; nj < 8; nj++) {
                    const int ni = nj >> 1, pr = (nj & 1) * 2;
                    MMA16816(acc[mi][nj], ah, bh[ni][pr], bh[ni][pr + 1]);
                    MMA16816(acc[mi][nj], ah, bl[ni][pr], bl[ni][pr + 1]);
                }
            }
        }
    }
    __syncthreads();

    float* C = (float*)tilesPtr;
    {
        const int r0 = wm + (lane >> 2);
        const int c0 = wn + 2 * (lane & 3);
#pragma unroll
        for (int mi = 0; mi < 4; mi++)
#pragma unroll
            for (int nj = 0; nj < 8; nj++) {
                float* p = C + (r0 + mi * 16) * CSTRIDE + c0 + nj * 8;
                p[0] = acc[mi][nj][0];
                p[1] = acc[mi][nj][1];
                p[8 * CSTRIDE]     = acc[mi][nj][2];
                p[8 * CSTRIDE + 1] = acc[mi][nj][3];
            }
    }
    __syncthreads();

    // ---- LSTM epilogue: logits = acc + gx + bias ----
    if (m0 + tid < count) {
        const int rowg = sRow[tid];
        const float* Crow = C + tid * CSTRIDE;
        const float* bb = g_bias + n0;
        const float* gxp = g_gx + (size_t)rowg * NG + n0;
        const int j0 = n0 >> 2;
        float* cellp = g_cell + (size_t)rowg * HID + j0;
        uint32_t sp[16];
#pragma unroll
        for (int u = 0; u < 32; u++) {
            const float4 gv = *(const float4*)(Crow + u * 4);
            const float4 xv = *(const float4*)(gxp + u * 4);
            const float ig = sigf (gv.x + xv.x + bb[u * 4 + 0]);
            const float fg = sigf (gv.y + xv.y + bb[u * 4 + 1]);
            const float cg = tanhf(gv.z + xv.z + bb[u * 4 + 2]);
            const float og = sigf (gv.w + xv.w + bb[u * 4 + 3]);
            const float c2 = fg * cellp[u] + ig * cg;
            cellp[u] = c2;
            const float s = og * tanhf(c2);
            const uint32_t su = hfu(__float2half_rn(s));
            if (u & 1) sp[u >> 1] |= su << 16;
            else       sp[u >> 1] = su;
        }
        uint4* sh = (uint4*)(Aout + (size_t)rowg * HID + j0);
#pragma unroll
        for (int v = 0; v < 4; v++)
            sh[v] = make_uint4(sp[v * 4], sp[v * 4 + 1], sp[v * 4 + 2], sp[v * 4 + 3]);
    }
}

// ---------------- head: 2-term fp16 GEMM (state @ [W1;Whalt]^T) + finalize ----
__global__ __launch_bounds__(256, 1) void k_head(int t,
                                                 const float* __restrict__ W2,
                                                 const float* __restrict__ b2,
                                                 float* __restrict__ out) {
    extern __shared__ char smem[];
    __shared__ int sRow[HBM];

    const int count = g_cnt[t];
    const int base = blockIdx.x * HBM;
    if (base >= count) return;
    const int tid = threadIdx.x;
    const int wrp = tid >> 5;
    const int lane = tid & 31;

    const uint32_t sb0 = smem_u32(smem);
    const uint32_t tiles = (sb0 + 1023) & ~1023u;
    char* tilesPtr = smem + (tiles - sb0);

    const int* map = (t & 1) ? g_mapB : g_mapA;
    int* map_next  = (t & 1) ? g_mapA : g_mapB;
    if (tid < HBM) sRow[tid] = map[min(base + tid, count - 1)];
    __syncthreads();

    // state after iter t: t even -> A1, t odd -> A0
    const __half* Astate = (t & 1) ? g_A0 : g_A1;

    const int arow = tid & 127;
    const int ug = (tid >> 7) * 4;             // two threads per row, 4x16B each
    const char* pA = (const char*)(Astate + (size_t)sRow[arow] * HID);
    const uint32_t aswz = (uint32_t)(arow & 7) << 4;
    const uint32_t aDstRow = (uint32_t)arow * 128;
    const char* pW = (const char*)g_W1img;

    auto load_chunk = [&](int c, int stage) {
        const uint32_t tb = tiles + (uint32_t)stage * H_STAGE;
        const char* src = pA + c * 128;
#pragma unroll
        for (int u = 0; u < 4; u++)
            cp16(tb + aDstRow + (((uint32_t)((ug + u) * 16)) ^ aswz), src + (ug + u) * 16);
        const char* w = pW + c * 36864;        // hi 18432 then lo 18432
#pragma unroll
        for (int q = 0; q < 9; q++) {          // 2304 lines = 9 * 256
            const uint32_t i = (uint32_t)(tid + q * 256);
            cp16(tb + 16384 + i * 16, w + (size_t)i * 16);
        }
        CP_COMMIT();
    };

    const int wm = wrp * 16;
    const uint32_t fswz = (uint32_t)(lane & 7) << 4;
    const uint32_t aRowOff = (uint32_t)(wm + (lane & 15)) * 128;
    const uint32_t aKsel = (uint32_t)(lane >> 4) * 16;
    const uint32_t bRowOff = (uint32_t)((lane & 7) + ((lane >> 4) << 3)) * 128;
    const uint32_t bKsel = (uint32_t)((lane >> 3) & 1) * 16;

    float acc[18][4];
#pragma unroll
    for (int nj = 0; nj < 18; nj++)
#pragma unroll
        for (int e = 0; e < 4; e++) acc[nj][e] = 0.0f;

    load_chunk(0, 0);
    for (int c = 0; c < H_CHUNKS; c++) {
        const int stage = c & 1;
        CP_WAIT(0);
        __syncthreads();
        if (c + 1 < H_CHUNKS) load_chunk(c + 1, stage ^ 1);

        const uint32_t tb = tiles + (uint32_t)stage * H_STAGE;
        const uint32_t ahB = tb + aRowOff;
        const uint32_t whB = tb + 16384 + bRowOff;
        const uint32_t wlB = tb + 34816 + bRowOff;

#pragma unroll
        for (int ks = 0; ks < 4; ks++) {
            const uint32_t ak = ((uint32_t)(ks * 32) + aKsel) ^ fswz;
            const uint32_t bk = ((uint32_t)(ks * 32) + bKsel) ^ fswz;
            uint32_t ah[4], bh[9][4], bl[9][4];
            LDM4(ah, ahB + ak);
#pragma unroll
            for (int ni = 0; ni < 9; ni++) {
                LDM4(bh[ni], whB + ni * 2048 + bk);
                LDM4(bl[ni], wlB + ni * 2048 + bk);
            }
#pragma unroll
            for (int nj = 0; nj < 18; nj++) {
                const int ni = nj >> 1, pr = (nj & 1) * 2;
                MMA16816(acc[nj], ah, bh[ni][pr], bh[ni][pr + 1]);
                MMA16816(acc[nj], ah, bl[ni][pr], bl[ni][pr + 1]);
            }
        }
    }
    __syncthreads();

    float* C = (float*)tilesPtr;
    {
        const int r0 = wm + (lane >> 2);
        const int c0 = 2 * (lane & 3);
#pragma unroll
        for (int nj = 0; nj < 18; nj++) {
            float* p = C + r0 * HCS + c0 + nj * 8;
            p[0] = acc[nj][0];
            p[1] = acc[nj][1];
            p[8 * HCS]     = acc[nj][2];
            p[8 * HCS + 1] = acc[nj][3];
        }
    }
    __syncthreads();

    const float4 w2v = *(const float4*)(W2 + lane * 4);
    const float4 b1v = *(const float4*)(g_b1h + lane * 4);
    const float bhalt = g_b1h[OMID];

    for (int i = 0; i < 16; i++) {
        const int r = wm + i;
        const int mm = base + r;
        if (mm >= count) continue;
        const int rowg = sRow[r];

        const float4 mv = *(const float4*)&C[r * HCS + lane * 4];
        float acc2 = fmaxf(mv.x + b1v.x, 0.0f) * w2v.x
                   + fmaxf(mv.y + b1v.y, 0.0f) * w2v.y
                   + fmaxf(mv.z + b1v.z, 0.0f) * w2v.z
                   + fmaxf(mv.w + b1v.w, 0.0f) * w2v.w;
#pragma unroll
        for (int off = 16; off; off >>= 1)
            acc2 += __shfl_xor_sync(0xffffffffu, acc2, off);

        if (lane == 0) {
            const float o = sigf(acc2 + b2[0]);
            const float h = sigf(C[r * HCS + OMID] + bhalt);
            const float p = g_psum[rowg];
            const float pn = p + h;
            const bool fin = (pn >= 1.0f - 0.001f) || (t == MAX_IT - 1);
            const float hr = fin ? (1.0f - p) : h;
            out[rowg] += o * hr;
            g_psum[rowg] = fin ? 1.0f : pn;
            if (!fin) {
                int slot = atomicAdd(&g_cnt[t + 1], 1);
                map_next[slot] = rowg;
            }
        }
    }
}

// ---------------- launch ------------------------------------------------------
extern "C" void kernel_launch(void* const* d_in, const int* in_sizes, int n_in,
                              void* d_out, int out_size) {
    const float* x     = (const float*)d_in[0];
    const float* Wxi   = (const float*)d_in[1];
    const float* bxi   = (const float*)d_in[2];
    const float* Whi   = (const float*)d_in[3];
    const float* bhi   = (const float*)d_in[4];
    const float* Wxf   = (const float*)d_in[5];
    const float* bxf   = (const float*)d_in[6];
    const float* Whf   = (const float*)d_in[7];
    const float* bhf   = (const float*)d_in[8];
    const float* Wxc   = (const float*)d_in[9];
    const float* bxc   = (const float*)d_in[10];
    const float* Whc   = (const float*)d_in[11];
    const float* bhc   = (const float*)d_in[12];
    const float* Wxo   = (const float*)d_in[13];
    const float* bxo   = (const float*)d_in[14];
    const float* Who   = (const float*)d_in[15];
    const float* bho   = (const float*)d_in[16];
    const float* Whalt = (const float*)d_in[17];
    const float* bhalt = (const float*)d_in[18];
    const float* W1    = (const float*)d_in[19];
    const float* b1    = (const float*)d_in[20];
    const float* W2    = (const float*)d_in[21];
    const float* b2    = (const float*)d_in[22];
    float* out = (float*)d_out;

    cudaFuncSetAttribute(k_gates, cudaFuncAttributeMaxDynamicSharedMemorySize, SMEM_DYN_G);
    cudaFuncSetAttribute(k_gx,    cudaFuncAttributeMaxDynamicSharedMemorySize, SMEM_DYN_G);
    cudaFuncSetAttribute(k_head,  cudaFuncAttributeMaxDynamicSharedMemorySize, SMEM_DYN_H);

    k_init<<<B, INP>>>(x, out);

    const int tot = NG * (KA / 8) + NH_PAD * (HID / 8) + NG + OMID + 1;
    k_pack<<<(tot + 255) / 256, 256>>>(Wxi, Whi, bxi, bhi,
                                       Wxf, Whf, bxf, bhf,
                                       Wxc, Whc, bxc, bhc,
                                       Wxo, Who, bxo, bho,
                                       W1, b1, Whalt, bhalt);

    k_gx<<<dim3(NTILES, B / BM), 256, SMEM_DYN_G>>>();
    k_t0<<<B, 256>>>();
    k_head<<<B / HBM, 256, SMEM_DYN_H>>>(0, W2, b2, out);

    for (int t = 1; t < MAX_IT; t++) {
        k_gates<<<dim3(NTILES, B / BM), 256, SMEM_DYN_G>>>(t);
        k_head<<<B / HBM, 256, SMEM_DYN_H>>>(t, W2, b2, out);
    }
}

// round 14
// speedup vs baseline: 4.9843x; 1.1158x over previous
#include <cuda_runtime.h>
#include <cuda_fp16.h>
#include <math.h>
#include <stdint.h>

#define B       8192
#define INP     64
#define HID     1024
#define KA      1088
#define NG      4096          // 4 gates * HID, interleaved n = j*4 + g
#define OMID    128
#define MAX_IT  8

#define BM 256
#define BN 128
#define CHUNKS 16             // state K chunks of 64
#define NTILES (NG / BN)      // 32
#define G_STAGE 49152         // A 32K + W 16K (single fp16 W)
#define SMEM_DYN_G 136192     // C tile 135168 dominates
#define CSTRIDE 132

// head geometry (2-term fp16 W: protects halt logit)
#define HBM 128
#define NH_PAD 144
#define H_CHUNKS 16
#define H_STAGE 53248         // A 16K + Wh 18K + Wl 18K
#define SMEM_DYN_H 107520
#define HCS 148

// ---------------- device scratch ---------------------------------------------
__device__ __half g_A0[B * HID];            // state ping-pong (single fp16)
__device__ __half g_A1[B * HID];
__device__ __half g_x[B * INP];
__device__ float  g_cell[B * HID];
__device__ __half g_Wimg[NTILES * CHUNKS * 8192];    // state-K image, single fp16
__device__ __half g_Wx_img[NTILES * 16384];          // x-K image: [T][hi|lo] (2-term)
__device__ __half g_W1img[H_CHUNKS * 2 * (NH_PAD * 64)];
__device__ float  g_gx[(size_t)B * NG];
__device__ float  g_bias[NG];
__device__ float  g_b1h[OMID + 2];
__device__ float  g_psum[B];
__device__ int    g_mapA[B];
__device__ int    g_mapB[B];
__device__ int    g_cnt[MAX_IT + 1];

__device__ __forceinline__ float sigf(float z) { return 1.0f / (1.0f + expf(-z)); }

// ---------------- PTX helpers (base ISA only) ---------------------------------
__device__ __forceinline__ uint32_t smem_u32(const void* p) {
    uint32_t a;
    asm("{ .reg .u64 t; cvta.to.shared.u64 t, %1; cvt.u32.u64 %0, t; }" : "=r"(a) : "l"(p));
    return a;
}
__device__ __forceinline__ void cp16(uint32_t dst, const void* src) {
    asm volatile("cp.async.cg.shared.global [%0], [%1], 16;" :: "r"(dst), "l"(src));
}
#define CP_COMMIT() asm volatile("cp.async.commit_group;" ::: "memory")
#define CP_WAIT(n)  asm volatile("cp.async.wait_group %0;" :: "n"(n) : "memory")

#define LDM4(r, addr) \
    asm volatile("ldmatrix.sync.aligned.m8n8.x4.shared.b16 {%0,%1,%2,%3}, [%4];" \
        : "=r"((r)[0]), "=r"((r)[1]), "=r"((r)[2]), "=r"((r)[3]) : "r"(addr))

#define MMA16816(acc, a, b0v, b1v) \
    asm volatile("mma.sync.aligned.m16n8k16.row.col.f32.f16.f16.f32 " \
        "{%0,%1,%2,%3}, {%4,%5,%6,%7}, {%8,%9}, {%0,%1,%2,%3};" \
        : "+f"((acc)[0]), "+f"((acc)[1]), "+f"((acc)[2]), "+f"((acc)[3]) \
        : "r"((a)[0]), "r"((a)[1]), "r"((a)[2]), "r"((a)[3]), "r"(b0v), "r"(b1v))

__device__ __forceinline__ unsigned short hfu(__half v) {
    return *reinterpret_cast<unsigned short*>(&v);
}
__device__ __forceinline__ uint4 pack8h(const float* w) {
    unsigned short hs[8];
#pragma unroll
    for (int u = 0; u < 8; u++) hs[u] = hfu(__float2half_rn(w[u]));
    return make_uint4((uint32_t)hs[0] | ((uint32_t)hs[1] << 16),
                      (uint32_t)hs[2] | ((uint32_t)hs[3] << 16),
                      (uint32_t)hs[4] | ((uint32_t)hs[5] << 16),
                      (uint32_t)hs[6] | ((uint32_t)hs[7] << 16));
}
__device__ __forceinline__ void split8h(const float* w, uint4& hv, uint4& lv) {
    unsigned short hs[8], ls[8];
#pragma unroll
    for (int u = 0; u < 8; u++) {
        __half hi = __float2half_rn(w[u]);
        __half lo = __float2half_rn(w[u] - __half2float(hi));
        hs[u] = hfu(hi); ls[u] = hfu(lo);
    }
    hv = make_uint4((uint32_t)hs[0] | ((uint32_t)hs[1] << 16),
                    (uint32_t)hs[2] | ((uint32_t)hs[3] << 16),
                    (uint32_t)hs[4] | ((uint32_t)hs[5] << 16),
                    (uint32_t)hs[6] | ((uint32_t)hs[7] << 16));
    lv = make_uint4((uint32_t)ls[0] | ((uint32_t)ls[1] << 16),
                    (uint32_t)ls[2] | ((uint32_t)ls[3] << 16),
                    (uint32_t)ls[4] | ((uint32_t)ls[5] << 16),
                    (uint32_t)ls[6] | ((uint32_t)ls[7] << 16));
}

// ---------------- init --------------------------------------------------------
__global__ void k_init(const float* __restrict__ x, float* __restrict__ out) {
    const int row = blockIdx.x;
    const int t = threadIdx.x;                 // 64 threads
    g_x[row * INP + t] = __float2half_rn(x[row * INP + t]);
    if (t == 0) {
        g_psum[row] = 0.0f;
        g_mapA[row] = row;
        out[row] = 0.0f;
    }
    if (row == 0 && t <= MAX_IT) g_cnt[t] = (t == 0) ? B : 0;
}

// ---------------- pack weights ------------------------------------------------
__global__ void k_pack(
    const float* __restrict__ Wxi, const float* __restrict__ Whi,
    const float* __restrict__ bxi, const float* __restrict__ bhi,
    const float* __restrict__ Wxf, const float* __restrict__ Whf,
    const float* __restrict__ bxf, const float* __restrict__ bhf,
    const float* __restrict__ Wxc, const float* __restrict__ Whc,
    const float* __restrict__ bxc, const float* __restrict__ bhc,
    const float* __restrict__ Wxo, const float* __restrict__ Who,
    const float* __restrict__ bxo, const float* __restrict__ bho,
    const float* __restrict__ W1,  const float* __restrict__ b1,
    const float* __restrict__ Whalt, const float* __restrict__ bhalt)
{
    int idx = blockIdx.x * blockDim.x + threadIdx.x;
    if (idx < NG * (KA / 8)) {
        const int n = idx / (KA / 8);
        const int kb = idx % (KA / 8);
        const int g = n & 3;
        const int j = n >> 2;
        const float* Wx = (g == 0) ? Wxi : (g == 1) ? Wxf : (g == 2) ? Wxc : Wxo;
        const float* Wh = (g == 0) ? Whi : (g == 1) ? Whf : (g == 2) ? Whc : Who;
        float w[8];
        if (kb < 8) {
            const float* s = Wx + j * INP + kb * 8;
#pragma unroll
            for (int u = 0; u < 8; u++) w[u] = s[u];
        } else {
            const float* s = Wh + j * HID + (kb - 8) * 8;
#pragma unroll
            for (int u = 0; u < 8; u++) w[u] = s[u];
        }
        const int T = n >> 7, nr = n & 127;
        if (kb < 8) {   // x-part image: 2-term (hi|lo)
            uint4 hv, lv;
            split8h(w, hv, lv);
            const unsigned byte = ((unsigned)(nr * 128 + kb * 16)) ^ (((unsigned)(nr & 7)) << 4);
            const unsigned off_b = (unsigned)(T * 32768) + byte;
            *(uint4*)((char*)g_Wx_img + off_b) = hv;
            *(uint4*)((char*)g_Wx_img + off_b + 16384) = lv;
        } else {        // state-part image: single fp16
            const int C = (kb - 8) >> 3, kq = (kb - 8) & 7;
            const unsigned byte = ((unsigned)(nr * 128 + kq * 16)) ^ (((unsigned)(nr & 7)) << 4);
            const unsigned off_b = (unsigned)((T * CHUNKS + C) * 16384) + byte;
            *(uint4*)((char*)g_Wimg + off_b) = pack8h(w);
        }
        return;
    }
    idx -= NG * (KA / 8);
    if (idx < NH_PAD * (HID / 8)) {            // head W1/Whalt image (2-term)
        const int n = idx / (HID / 8);
        const int kb = idx % (HID / 8);
        float w[8];
#pragma unroll
        for (int u = 0; u < 8; u++) {
            const int k = kb * 8 + u;
            w[u] = (n < OMID) ? W1[n * HID + k] : (n == OMID ? Whalt[k] : 0.0f);
        }
        uint4 hv, lv;
        split8h(w, hv, lv);
        const int C = kb >> 3;
        const unsigned byte = ((unsigned)(n * 128 + (kb & 7) * 16)) ^ (((unsigned)(n & 7)) << 4);
        const unsigned off_b = (unsigned)(C * 36864) + byte;
        *(uint4*)((char*)g_W1img + off_b) = hv;
        *(uint4*)((char*)g_W1img + off_b + 18432) = lv;
        return;
    }
    idx -= NH_PAD * (HID / 8);
    if (idx < NG) {
        const int g = idx & 3;
        const int j = idx >> 2;
        const float* bx = (g == 0) ? bxi : (g == 1) ? bxf : (g == 2) ? bxc : bxo;
        const float* bh = (g == 0) ? bhi : (g == 1) ? bhf : (g == 2) ? bhc : bho;
        g_bias[idx] = bx[j] + bh[j];
        return;
    }
    idx -= NG;
    if (idx < OMID) { g_b1h[idx] = b1[idx]; return; }
    idx -= OMID;
    if (idx == 0) g_b1h[OMID] = bhalt[0];
}

// ---------------- k_gx: gx = x @ Wx^T (2-term) + fused t=0 LSTM epilogue ------
__global__ __launch_bounds__(256, 1) void k_gx() {
    extern __shared__ char smem[];
    const int m0 = blockIdx.y * BM;
    const int n0 = blockIdx.x * BN;
    const int tid = threadIdx.x;
    const int wrp = tid >> 5;
    const int lane = tid & 31;

    const uint32_t sb0 = smem_u32(smem);
    const uint32_t tiles = (sb0 + 1023) & ~1023u;
    char* tilesPtr = smem + (tiles - sb0);

    const int myrow = m0 + tid;
    const char* pA = (const char*)(g_x + (size_t)myrow * INP);
    const uint32_t aswz = (uint32_t)(tid & 7) << 4;
    const uint32_t aDstRow = (uint32_t)tid * 128;
    const char* pW = (const char*)g_Wx_img + (size_t)blockIdx.x * 32768;

    {
#pragma unroll
        for (int u = 0; u < 8; u++)
            cp16(tiles + aDstRow + (((uint32_t)(u * 16)) ^ aswz), pA + u * 16);
#pragma unroll
        for (int q = 0; q < 8; q++) {
            const uint32_t o = (uint32_t)(tid + q * 256) << 4;
            cp16(tiles + 32768 + o, pW + o);
        }
        CP_COMMIT();
    }

    const int wm = (wrp & 3) * 64;
    const int wn = (wrp >> 2) * 64;
    const uint32_t fswz = (uint32_t)(lane & 7) << 4;
    const uint32_t aRowOff = (uint32_t)(wm + (lane & 15)) * 128;
    const uint32_t aKsel = (uint32_t)(lane >> 4) * 16;
    const uint32_t bRowOff = (uint32_t)(wn + (lane & 7) + ((lane >> 4) << 3)) * 128;
    const uint32_t bKsel = (uint32_t)((lane >> 3) & 1) * 16;

    float acc[4][8][4];
#pragma unroll
    for (int mi = 0; mi < 4; mi++)
#pragma unroll
        for (int nj = 0; nj < 8; nj++)
#pragma unroll
            for (int e = 0; e < 4; e++) acc[mi][nj][e] = 0.0f;

    CP_WAIT(0);
    __syncthreads();
    {
        const uint32_t ahB = tiles + aRowOff;
        const uint32_t whB = tiles + 32768 + bRowOff;
        const uint32_t wlB = tiles + 49152 + bRowOff;
#pragma unroll
        for (int ks = 0; ks < 4; ks++) {
            const uint32_t ak = ((uint32_t)(ks * 32) + aKsel) ^ fswz;
            const uint32_t bk = ((uint32_t)(ks * 32) + bKsel) ^ fswz;
            uint32_t bh[4][4], bl[4][4];
#pragma unroll
            for (int ni = 0; ni < 4; ni++) {
                LDM4(bh[ni], whB + ni * 2048 + bk);
                LDM4(bl[ni], wlB + ni * 2048 + bk);
            }
#pragma unroll
            for (int mi = 0; mi < 4; mi++) {
                uint32_t ah[4];
                LDM4(ah, ahB + mi * 2048 + ak);
#pragma unroll
                for (int nj = 0; nj < 8; nj++) {
                    const int ni = nj >> 1, pr = (nj & 1) * 2;
                    MMA16816(acc[mi][nj], ah, bh[ni][pr], bh[ni][pr + 1]);
                    MMA16816(acc[mi][nj], ah, bl[ni][pr], bl[ni][pr + 1]);
                }
            }
        }
    }
    __syncthreads();

    float* C = (float*)tilesPtr;
    {
        const int r0 = wm + (lane >> 2);
        const int c0 = wn + 2 * (lane & 3);
#pragma unroll
        for (int mi = 0; mi < 4; mi++)
#pragma unroll
            for (int nj = 0; nj < 8; nj++) {
                float* p = C + (r0 + mi * 16) * CSTRIDE + c0 + nj * 8;
                p[0] = acc[mi][nj][0];
                p[1] = acc[mi][nj][1];
                p[8 * CSTRIDE]     = acc[mi][nj][2];
                p[8 * CSTRIDE + 1] = acc[mi][nj][3];
            }
    }
    __syncthreads();

    // ---- epilogue: store gx AND do the t=0 LSTM pointwise (state=cell=0) ----
    {
        float* gxo = g_gx + (size_t)myrow * NG + n0;
        const float* Crow = C + tid * CSTRIDE;
        const float* bb = g_bias + n0;
        const int j0 = n0 >> 2;
        float* cellp = g_cell + (size_t)myrow * HID + j0;
        uint32_t sp[16];
#pragma unroll
        for (int u = 0; u < 32; u++) {
            const float4 gv = *(const float4*)(Crow + u * 4);
            *(float4*)(gxo + u * 4) = gv;
            const float ig = sigf (gv.x + bb[u * 4 + 0]);
            const float cg = tanhf(gv.z + bb[u * 4 + 2]);
            const float og = sigf (gv.w + bb[u * 4 + 3]);
            const float c2 = ig * cg;           // f*0 + i*c
            cellp[u] = c2;
            const float s = og * tanhf(c2);
            const uint32_t su = hfu(__float2half_rn(s));
            if (u & 1) sp[u >> 1] |= su << 16;
            else       sp[u >> 1] = su;
        }
        uint4* sh = (uint4*)(g_A1 + (size_t)myrow * HID + j0);
#pragma unroll
        for (int v = 0; v < 4; v++)
            sh[v] = make_uint4(sp[v * 4], sp[v * 4 + 1], sp[v * 4 + 2], sp[v * 4 + 3]);
    }
}

// ---------------- gates (t>=1): 1-term fp16 GEMM + gx-folded epilogue ---------
__global__ __launch_bounds__(256, 1) void k_gates(int t) {
    extern __shared__ char smem[];
    __shared__ int sRow[BM];

    const int count = g_cnt[t];
    const int m0 = blockIdx.y * BM;
    if (m0 >= count) return;
    const int n0 = blockIdx.x * BN;
    const int tid = threadIdx.x;
    const int wrp = tid >> 5;
    const int lane = tid & 31;

    const uint32_t sb0 = smem_u32(smem);
    const uint32_t tiles = (sb0 + 1023) & ~1023u;
    char* tilesPtr = smem + (tiles - sb0);

    const int* map = (t & 1) ? g_mapB : g_mapA;
    sRow[tid] = map[min(m0 + tid, count - 1)];
    __syncthreads();

    const __half* Ain = (t & 1) ? g_A1 : g_A0;
    __half*       Aout = (t & 1) ? g_A0 : g_A1;

    const int myrow = sRow[tid];
    const char* pA = (const char*)(Ain + (size_t)myrow * HID);
    const uint32_t aswz = (uint32_t)(tid & 7) << 4;
    const uint32_t aDstRow = (uint32_t)tid * 128;
    const char* pW = (const char*)g_Wimg + (size_t)blockIdx.x * (CHUNKS * 16384);

    auto load_chunk = [&](int c, int stage) {
        const uint32_t tb = tiles + (uint32_t)stage * G_STAGE;
        const char* sa = pA + c * 128;
#pragma unroll
        for (int u = 0; u < 8; u++)
            cp16(tb + aDstRow + (((uint32_t)(u * 16)) ^ aswz), sa + u * 16);
        const char* wc = pW + c * 16384;
#pragma unroll
        for (int q = 0; q < 4; q++) {
            const uint32_t o = (uint32_t)(tid + q * 256) << 4;
            cp16(tb + 32768 + o, wc + o);
        }
        CP_COMMIT();
    };

    const int wm = (wrp & 3) * 64;
    const int wn = (wrp >> 2) * 64;
    const uint32_t fswz = (uint32_t)(lane & 7) << 4;
    const uint32_t aRowOff = (uint32_t)(wm + (lane & 15)) * 128;
    const uint32_t aKsel = (uint32_t)(lane >> 4) * 16;
    const uint32_t bRowOff = (uint32_t)(wn + (lane & 7) + ((lane >> 4) << 3)) * 128;
    const uint32_t bKsel = (uint32_t)((lane >> 3) & 1) * 16;

    float acc[4][8][4];
#pragma unroll
    for (int mi = 0; mi < 4; mi++)
#pragma unroll
        for (int nj = 0; nj < 8; nj++)
#pragma unroll
            for (int e = 0; e < 4; e++) acc[mi][nj][e] = 0.0f;

    load_chunk(0, 0);
    for (int c = 0; c < CHUNKS; c++) {
        const int stage = c & 1;
        CP_WAIT(0);
        __syncthreads();
        if (c + 1 < CHUNKS) load_chunk(c + 1, stage ^ 1);

        const uint32_t tb = tiles + (uint32_t)stage * G_STAGE;
        const uint32_t ahB = tb + aRowOff;
        const uint32_t whB = tb + 32768 + bRowOff;

#pragma unroll
        for (int ks = 0; ks < 4; ks++) {
            const uint32_t ak = ((uint32_t)(ks * 32) + aKsel) ^ fswz;
            const uint32_t bk = ((uint32_t)(ks * 32) + bKsel) ^ fswz;
            uint32_t bh[4][4];
#pragma unroll
            for (int ni = 0; ni < 4; ni++)
                LDM4(bh[ni], whB + ni * 2048 + bk);
#pragma unroll
            for (int mi = 0; mi < 4; mi++) {
                uint32_t ah[4];
                LDM4(ah, ahB + mi * 2048 + ak);
#pragma unroll
                for (int nj = 0; nj < 8; nj++) {
                    const int ni = nj >> 1, pr = (nj & 1) * 2;
                    MMA16816(acc[mi][nj], ah, bh[ni][pr], bh[ni][pr + 1]);
                }
            }
        }
    }
    __syncthreads();

    float* C = (float*)tilesPtr;
    {
        const int r0 = wm + (lane >> 2);
        const int c0 = wn + 2 * (lane & 3);
#pragma unroll
        for (int mi = 0; mi < 4; mi++)
#pragma unroll
            for (int nj = 0; nj < 8; nj++) {
                float* p = C + (r0 + mi * 16) * CSTRIDE + c0 + nj * 8;
                p[0] = acc[mi][nj][0];
                p[1] = acc[mi][nj][1];
                p[8 * CSTRIDE]     = acc[mi][nj][2];
                p[8 * CSTRIDE + 1] = acc[mi][nj][3];
            }
    }
    __syncthreads();

    // ---- LSTM epilogue: logits = acc + gx + bias ----
    if (m0 + tid < count) {
        const int rowg = sRow[tid];
        const float* Crow = C + tid * CSTRIDE;
        const float* bb = g_bias + n0;
        const float* gxp = g_gx + (size_t)rowg * NG + n0;
        const int j0 = n0 >> 2;
        float* cellp = g_cell + (size_t)rowg * HID + j0;
        uint32_t sp[16];
#pragma unroll
        for (int u = 0; u < 32; u++) {
            const float4 gv = *(const float4*)(Crow + u * 4);
            const float4 xv = *(const float4*)(gxp + u * 4);
            const float ig = sigf (gv.x + xv.x + bb[u * 4 + 0]);
            const float fg = sigf (gv.y + xv.y + bb[u * 4 + 1]);
            const float cg = tanhf(gv.z + xv.z + bb[u * 4 + 2]);
            const float og = sigf (gv.w + xv.w + bb[u * 4 + 3]);
            const float c2 = fg * cellp[u] + ig * cg;
            cellp[u] = c2;
            const float s = og * tanhf(c2);
            const uint32_t su = hfu(__float2half_rn(s));
            if (u & 1) sp[u >> 1] |= su << 16;
            else       sp[u >> 1] = su;
        }
        uint4* sh = (uint4*)(Aout + (size_t)rowg * HID + j0);
#pragma unroll
        for (int v = 0; v < 4; v++)
            sh[v] = make_uint4(sp[v * 4], sp[v * 4 + 1], sp[v * 4 + 2], sp[v * 4 + 3]);
    }
}

// ---------------- head: 2-term fp16 GEMM (state @ [W1;Whalt]^T) + finalize ----
__global__ __launch_bounds__(256, 1) void k_head(int t,
                                                 const float* __restrict__ W2,
                                                 const float* __restrict__ b2,
                                                 float* __restrict__ out) {
    extern __shared__ char smem[];
    __shared__ int sRow[HBM];

    const int count = g_cnt[t];
    const int base = blockIdx.x * HBM;
    if (base >= count) return;
    const int tid = threadIdx.x;
    const int wrp = tid >> 5;
    const int lane = tid & 31;

    const uint32_t sb0 = smem_u32(smem);
    const uint32_t tiles = (sb0 + 1023) & ~1023u;
    char* tilesPtr = smem + (tiles - sb0);

    const int* map = (t & 1) ? g_mapB : g_mapA;
    int* map_next  = (t & 1) ? g_mapA : g_mapB;
    if (tid < HBM) sRow[tid] = map[min(base + tid, count - 1)];
    __syncthreads();

    // state after iter t: t even -> A1, t odd -> A0
    const __half* Astate = (t & 1) ? g_A0 : g_A1;

    const int arow = tid & 127;
    const int ug = (tid >> 7) * 4;
    const char* pA = (const char*)(Astate + (size_t)sRow[arow] * HID);
    const uint32_t aswz = (uint32_t)(arow & 7) << 4;
    const uint32_t aDstRow = (uint32_t)arow * 128;
    const char* pW = (const char*)g_W1img;

    auto load_chunk = [&](int c, int stage) {
        const uint32_t tb = tiles + (uint32_t)stage * H_STAGE;
        const char* src = pA + c * 128;
#pragma unroll
        for (int u = 0; u < 4; u++)
            cp16(tb + aDstRow + (((uint32_t)((ug + u) * 16)) ^ aswz), src + (ug + u) * 16);
        const char* w = pW + c * 36864;
#pragma unroll
        for (int q = 0; q < 9; q++) {
            const uint32_t i = (uint32_t)(tid + q * 256);
            cp16(tb + 16384 + i * 16, w + (size_t)i * 16);
        }
        CP_COMMIT();
    };

    const int wm = wrp * 16;
    const uint32_t fswz = (uint32_t)(lane & 7) << 4;
    const uint32_t aRowOff = (uint32_t)(wm + (lane & 15)) * 128;
    const uint32_t aKsel = (uint32_t)(lane >> 4) * 16;
    const uint32_t bRowOff = (uint32_t)((lane & 7) + ((lane >> 4) << 3)) * 128;
    const uint32_t bKsel = (uint32_t)((lane >> 3) & 1) * 16;

    float acc[18][4];
#pragma unroll
    for (int nj = 0; nj < 18; nj++)
#pragma unroll
        for (int e = 0; e < 4; e++) acc[nj][e] = 0.0f;

    load_chunk(0, 0);
    for (int c = 0; c < H_CHUNKS; c++) {
        const int stage = c & 1;
        CP_WAIT(0);
        __syncthreads();
        if (c + 1 < H_CHUNKS) load_chunk(c + 1, stage ^ 1);

        const uint32_t tb = tiles + (uint32_t)stage * H_STAGE;
        const uint32_t ahB = tb + aRowOff;
        const uint32_t whB = tb + 16384 + bRowOff;
        const uint32_t wlB = tb + 34816 + bRowOff;

#pragma unroll
        for (int ks = 0; ks < 4; ks++) {
            const uint32_t ak = ((uint32_t)(ks * 32) + aKsel) ^ fswz;
            const uint32_t bk = ((uint32_t)(ks * 32) + bKsel) ^ fswz;
            uint32_t ah[4], bh[9][4], bl[9][4];
            LDM4(ah, ahB + ak);
#pragma unroll
            for (int ni = 0; ni < 9; ni++) {
                LDM4(bh[ni], whB + ni * 2048 + bk);
                LDM4(bl[ni], wlB + ni * 2048 + bk);
            }
#pragma unroll
            for (int nj = 0; nj < 18; nj++) {
                const int ni = nj >> 1, pr = (nj & 1) * 2;
                MMA16816(acc[nj], ah, bh[ni][pr], bh[ni][pr + 1]);
                MMA16816(acc[nj], ah, bl[ni][pr], bl[ni][pr + 1]);
            }
        }
    }
    __syncthreads();

    float* C = (float*)tilesPtr;
    {
        const int r0 = wm + (lane >> 2);
        const int c0 = 2 * (lane & 3);
#pragma unroll
        for (int nj = 0; nj < 18; nj++) {
            float* p = C + r0 * HCS + c0 + nj * 8;
            p[0] = acc[nj][0];
            p[1] = acc[nj][1];
            p[8 * HCS]     = acc[nj][2];
            p[8 * HCS + 1] = acc[nj][3];
        }
    }
    __syncthreads();

    const float4 w2v = *(const float4*)(W2 + lane * 4);
    const float4 b1v = *(const float4*)(g_b1h + lane * 4);
    const float bhalt = g_b1h[OMID];

    for (int i = 0; i < 16; i++) {
        const int r = wm + i;
        const int mm = base + r;
        if (mm >= count) continue;
        const int rowg = sRow[r];

        const float4 mv = *(const float4*)&C[r * HCS + lane * 4];
        float acc2 = fmaxf(mv.x + b1v.x, 0.0f) * w2v.x
                   + fmaxf(mv.y + b1v.y, 0.0f) * w2v.y
                   + fmaxf(mv.z + b1v.z, 0.0f) * w2v.z
                   + fmaxf(mv.w + b1v.w, 0.0f) * w2v.w;
#pragma unroll
        for (int off = 16; off; off >>= 1)
            acc2 += __shfl_xor_sync(0xffffffffu, acc2, off);

        if (lane == 0) {
            const float o = sigf(acc2 + b2[0]);
            const float h = sigf(C[r * HCS + OMID] + bhalt);
            const float p = g_psum[rowg];
            const float pn = p + h;
            const bool fin = (pn >= 1.0f - 0.001f) || (t == MAX_IT - 1);
            const float hr = fin ? (1.0f - p) : h;
            out[rowg] += o * hr;
            g_psum[rowg] = fin ? 1.0f : pn;
            if (!fin) {
                int slot = atomicAdd(&g_cnt[t + 1], 1);
                map_next[slot] = rowg;
            }
        }
    }
}

// ---------------- launch ------------------------------------------------------
extern "C" void kernel_launch(void* const* d_in, const int* in_sizes, int n_in,
                              void* d_out, int out_size) {
    const float* x     = (const float*)d_in[0];
    const float* Wxi   = (const float*)d_in[1];
    const float* bxi   = (const float*)d_in[2];
    const float* Whi   = (const float*)d_in[3];
    const float* bhi   = (const float*)d_in[4];
    const float* Wxf   = (const float*)d_in[5];
    const float* bxf   = (const float*)d_in[6];
    const float* Whf   = (const float*)d_in[7];
    const float* bhf   = (const float*)d_in[8];
    const float* Wxc   = (const float*)d_in[9];
    const float* bxc   = (const float*)d_in[10];
    const float* Whc   = (const float*)d_in[11];
    const float* bhc   = (const float*)d_in[12];
    const float* Wxo   = (const float*)d_in[13];
    const float* bxo   = (const float*)d_in[14];
    const float* Who   = (const float*)d_in[15];
    const float* bho   = (const float*)d_in[16];
    const float* Whalt = (const float*)d_in[17];
    const float* bhalt = (const float*)d_in[18];
    const float* W1    = (const float*)d_in[19];
    const float* b1    = (const float*)d_in[20];
    const float* W2    = (const float*)d_in[21];
    const float* b2    = (const float*)d_in[22];
    float* out = (float*)d_out;

    cudaFuncSetAttribute(k_gates, cudaFuncAttributeMaxDynamicSharedMemorySize, SMEM_DYN_G);
    cudaFuncSetAttribute(k_gx,    cudaFuncAttributeMaxDynamicSharedMemorySize, SMEM_DYN_G);
    cudaFuncSetAttribute(k_head,  cudaFuncAttributeMaxDynamicSharedMemorySize, SMEM_DYN_H);

    k_init<<<B, INP>>>(x, out);

    const int tot = NG * (KA / 8) + NH_PAD * (HID / 8) + NG + OMID + 1;
    k_pack<<<(tot + 255) / 256, 256>>>(Wxi, Whi, bxi, bhi,
                                       Wxf, Whf, bxf, bhf,
                                       Wxc, Whc, bxc, bhc,
                                       Wxo, Who, bxo, bho,
                                       W1, b1, Whalt, bhalt);

    k_gx<<<dim3(NTILES, B / BM), 256, SMEM_DYN_G>>>();
    k_head<<<B / HBM, 256, SMEM_DYN_H>>>(0, W2, b2, out);

    for (int t = 1; t < MAX_IT; t++) {
        k_gates<<<dim3(NTILES, B / BM), 256, SMEM_DYN_G>>>(t);
        k_head<<<B / HBM, 256, SMEM_DYN_H>>>(t, W2, b2, out);
    }
}

// round 15
// speedup vs baseline: 5.5302x; 1.1095x over previous
#include <cuda_runtime.h>
#include <cuda_fp16.h>
#include <math.h>
#include <stdint.h>

#define B       8192
#define INP     64
#define HID     1024
#define KA      1088
#define NG      4096          // 4 gates * HID, interleaved n = j*4 + g
#define OMID    128
#define MAX_IT  8

#define BM 256
#define BN 128
#define CHUNKS 16             // state K chunks of 64
#define NTILES (NG / BN)      // 32
#define G_STAGE 49152         // A 32K + W 16K (single fp16 W)
#define SMEM_DYN_G 136192     // C tile 135168 dominates
#define CSTRIDE 132

// head geometry (2-term fp16 W: protects halt logit)
#define HBM 128
#define NH_PAD 144
#define H_CHUNKS 16
#define H_STAGE 53248         // A 16K + Wh 18K + Wl 18K
#define SMEM_DYN_H 107520
#define HCS 148

// ---------------- device scratch ---------------------------------------------
__device__ __half g_A0[B * HID];            // state ping-pong (single fp16)
__device__ __half g_A1[B * HID];
__device__ __half g_x[B * INP];
__device__ float  g_cell[B * HID];
__device__ __half g_Wimg[NTILES * CHUNKS * 8192];    // state-K image, single fp16
__device__ __half g_Wx_img[NTILES * 16384];          // x-K image: [T][hi|lo] (2-term)
__device__ __half g_W1img[H_CHUNKS * 2 * (NH_PAD * 64)];
__device__ float  g_gx[(size_t)B * NG];              // x @ Wx^T + bias (fp32)
__device__ float  g_bias[NG];
__device__ float  g_b1h[OMID + 2];
__device__ float  g_psum[B];
__device__ int    g_mapA[B];
__device__ int    g_mapB[B];
__device__ int    g_cnt[MAX_IT + 1];

__device__ __forceinline__ float sigf(float z) { return 1.0f / (1.0f + expf(-z)); }

// ---------------- PTX helpers (base ISA only) ---------------------------------
__device__ __forceinline__ uint32_t smem_u32(const void* p) {
    uint32_t a;
    asm("{ .reg .u64 t; cvta.to.shared.u64 t, %1; cvt.u32.u64 %0, t; }" : "=r"(a) : "l"(p));
    return a;
}
__device__ __forceinline__ void cp16(uint32_t dst, const void* src) {
    asm volatile("cp.async.cg.shared.global [%0], [%1], 16;" :: "r"(dst), "l"(src));
}
#define CP_COMMIT() asm volatile("cp.async.commit_group;" ::: "memory")
#define CP_WAIT(n)  asm volatile("cp.async.wait_group %0;" :: "n"(n) : "memory")

#define LDM4(r, addr) \
    asm volatile("ldmatrix.sync.aligned.m8n8.x4.shared.b16 {%0,%1,%2,%3}, [%4];" \
        : "=r"((r)[0]), "=r"((r)[1]), "=r"((r)[2]), "=r"((r)[3]) : "r"(addr))

#define MMA16816(acc, a, b0v, b1v) \
    asm volatile("mma.sync.aligned.m16n8k16.row.col.f32.f16.f16.f32 " \
        "{%0,%1,%2,%3}, {%4,%5,%6,%7}, {%8,%9}, {%0,%1,%2,%3};" \
        : "+f"((acc)[0]), "+f"((acc)[1]), "+f"((acc)[2]), "+f"((acc)[3]) \
        : "r"((a)[0]), "r"((a)[1]), "r"((a)[2]), "r"((a)[3]), "r"(b0v), "r"(b1v))

__device__ __forceinline__ unsigned short hfu(__half v) {
    return *reinterpret_cast<unsigned short*>(&v);
}
__device__ __forceinline__ uint4 pack8h(const float* w) {
    unsigned short hs[8];
#pragma unroll
    for (int u = 0; u < 8; u++) hs[u] = hfu(__float2half_rn(w[u]));
    return make_uint4((uint32_t)hs[0] | ((uint32_t)hs[1] << 16),
                      (uint32_t)hs[2] | ((uint32_t)hs[3] << 16),
                      (uint32_t)hs[4] | ((uint32_t)hs[5] << 16),
                      (uint32_t)hs[6] | ((uint32_t)hs[7] << 16));
}
__device__ __forceinline__ void split8h(const float* w, uint4& hv, uint4& lv) {
    unsigned short hs[8], ls[8];
#pragma unroll
    for (int u = 0; u < 8; u++) {
        __half hi = __float2half_rn(w[u]);
        __half lo = __float2half_rn(w[u] - __half2float(hi));
        hs[u] = hfu(hi); ls[u] = hfu(lo);
    }
    hv = make_uint4((uint32_t)hs[0] | ((uint32_t)hs[1] << 16),
                    (uint32_t)hs[2] | ((uint32_t)hs[3] << 16),
                    (uint32_t)hs[4] | ((uint32_t)hs[5] << 16),
                    (uint32_t)hs[6] | ((uint32_t)hs[7] << 16));
    lv = make_uint4((uint32_t)ls[0] | ((uint32_t)ls[1] << 16),
                    (uint32_t)ls[2] | ((uint32_t)ls[3] << 16),
                    (uint32_t)ls[4] | ((uint32_t)ls[5] << 16),
                    (uint32_t)ls[6] | ((uint32_t)ls[7] << 16));
}

// ---------------- init --------------------------------------------------------
__global__ void k_init(const float* __restrict__ x, float* __restrict__ out) {
    const int row = blockIdx.x;
    const int t = threadIdx.x;                 // 64 threads
    g_x[row * INP + t] = __float2half_rn(x[row * INP + t]);
    if (t == 0) {
        g_psum[row] = 0.0f;
        g_mapA[row] = row;
        out[row] = 0.0f;
    }
    if (row == 0 && t <= MAX_IT) g_cnt[t] = (t == 0) ? B : 0;
}

// ---------------- pack weights ------------------------------------------------
__global__ void k_pack(
    const float* __restrict__ Wxi, const float* __restrict__ Whi,
    const float* __restrict__ bxi, const float* __restrict__ bhi,
    const float* __restrict__ Wxf, const float* __restrict__ Whf,
    const float* __restrict__ bxf, const float* __restrict__ bhf,
    const float* __restrict__ Wxc, const float* __restrict__ Whc,
    const float* __restrict__ bxc, const float* __restrict__ bhc,
    const float* __restrict__ Wxo, const float* __restrict__ Who,
    const float* __restrict__ bxo, const float* __restrict__ bho,
    const float* __restrict__ W1,  const float* __restrict__ b1,
    const float* __restrict__ Whalt, const float* __restrict__ bhalt)
{
    int idx = blockIdx.x * blockDim.x + threadIdx.x;
    if (idx < NG * (KA / 8)) {
        const int n = idx / (KA / 8);
        const int kb = idx % (KA / 8);
        const int g = n & 3;
        const int j = n >> 2;
        const float* Wx = (g == 0) ? Wxi : (g == 1) ? Wxf : (g == 2) ? Wxc : Wxo;
        const float* Wh = (g == 0) ? Whi : (g == 1) ? Whf : (g == 2) ? Whc : Who;
        float w[8];
        if (kb < 8) {
            const float* s = Wx + j * INP + kb * 8;
#pragma unroll
            for (int u = 0; u < 8; u++) w[u] = s[u];
        } else {
            const float* s = Wh + j * HID + (kb - 8) * 8;
#pragma unroll
            for (int u = 0; u < 8; u++) w[u] = s[u];
        }
        const int T = n >> 7, nr = n & 127;
        if (kb < 8) {   // x-part image: 2-term (hi|lo)
            uint4 hv, lv;
            split8h(w, hv, lv);
            const unsigned byte = ((unsigned)(nr * 128 + kb * 16)) ^ (((unsigned)(nr & 7)) << 4);
            const unsigned off_b = (unsigned)(T * 32768) + byte;
            *(uint4*)((char*)g_Wx_img + off_b) = hv;
            *(uint4*)((char*)g_Wx_img + off_b + 16384) = lv;
        } else {        // state-part image: single fp16
            const int C = (kb - 8) >> 3, kq = (kb - 8) & 7;
            const unsigned byte = ((unsigned)(nr * 128 + kq * 16)) ^ (((unsigned)(nr & 7)) << 4);
            const unsigned off_b = (unsigned)((T * CHUNKS + C) * 16384) + byte;
            *(uint4*)((char*)g_Wimg + off_b) = pack8h(w);
        }
        return;
    }
    idx -= NG * (KA / 8);
    if (idx < NH_PAD * (HID / 8)) {            // head W1/Whalt image (2-term)
        const int n = idx / (HID / 8);
        const int kb = idx % (HID / 8);
        float w[8];
#pragma unroll
        for (int u = 0; u < 8; u++) {
            const int k = kb * 8 + u;
            w[u] = (n < OMID) ? W1[n * HID + k] : (n == OMID ? Whalt[k] : 0.0f);
        }
        uint4 hv, lv;
        split8h(w, hv, lv);
        const int C = kb >> 3;
        const unsigned byte = ((unsigned)(n * 128 + (kb & 7) * 16)) ^ (((unsigned)(n & 7)) << 4);
        const unsigned off_b = (unsigned)(C * 36864) + byte;
        *(uint4*)((char*)g_W1img + off_b) = hv;
        *(uint4*)((char*)g_W1img + off_b + 18432) = lv;
        return;
    }
    idx -= NH_PAD * (HID / 8);
    if (idx < NG) {
        const int g = idx & 3;
        const int j = idx >> 2;
        const float* bx = (g == 0) ? bxi : (g == 1) ? bxf : (g == 2) ? bxc : bxo;
        const float* bh = (g == 0) ? bhi : (g == 1) ? bhf : (g == 2) ? bhc : bho;
        g_bias[idx] = bx[j] + bh[j];
        return;
    }
    idx -= NG;
    if (idx < OMID) { g_b1h[idx] = b1[idx]; return; }
    idx -= OMID;
    if (idx == 0) g_b1h[OMID] = bhalt[0];
}

// ---------------- k_gx: gx = x @ Wx^T + bias (2-term) + fused t=0 LSTM --------
__global__ __launch_bounds__(256, 1) void k_gx() {
    extern __shared__ char smem[];
    const int m0 = blockIdx.y * BM;
    const int n0 = blockIdx.x * BN;
    const int tid = threadIdx.x;
    const int wrp = tid >> 5;
    const int lane = tid & 31;

    const uint32_t sb0 = smem_u32(smem);
    const uint32_t tiles = (sb0 + 1023) & ~1023u;
    char* tilesPtr = smem + (tiles - sb0);

    const int myrow = m0 + tid;
    const char* pA = (const char*)(g_x + (size_t)myrow * INP);
    const uint32_t aswz = (uint32_t)(tid & 7) << 4;
    const uint32_t aDstRow = (uint32_t)tid * 128;
    const char* pW = (const char*)g_Wx_img + (size_t)blockIdx.x * 32768;

    {
#pragma unroll
        for (int u = 0; u < 8; u++)
            cp16(tiles + aDstRow + (((uint32_t)(u * 16)) ^ aswz), pA + u * 16);
#pragma unroll
        for (int q = 0; q < 8; q++) {
            const uint32_t o = (uint32_t)(tid + q * 256) << 4;
            cp16(tiles + 32768 + o, pW + o);
        }
        CP_COMMIT();
    }

    const int wm = (wrp & 3) * 64;
    const int wn = (wrp >> 2) * 64;
    const uint32_t fswz = (uint32_t)(lane & 7) << 4;
    const uint32_t aRowOff = (uint32_t)(wm + (lane & 15)) * 128;
    const uint32_t aKsel = (uint32_t)(lane >> 4) * 16;
    const uint32_t bRowOff = (uint32_t)(wn + (lane & 7) + ((lane >> 4) << 3)) * 128;
    const uint32_t bKsel = (uint32_t)((lane >> 3) & 1) * 16;

    float acc[4][8][4];
#pragma unroll
    for (int mi = 0; mi < 4; mi++)
#pragma unroll
        for (int nj = 0; nj < 8; nj++)
#pragma unroll
            for (int e = 0; e < 4; e++) acc[mi][nj][e] = 0.0f;

    CP_WAIT(0);
    __syncthreads();
    {
        const uint32_t ahB = tiles + aRowOff;
        const uint32_t whB = tiles + 32768 + bRowOff;
        const uint32_t wlB = tiles + 49152 + bRowOff;
#pragma unroll
        for (int ks = 0; ks < 4; ks++) {
            const uint32_t ak = ((uint32_t)(ks * 32) + aKsel) ^ fswz;
            const uint32_t bk = ((uint32_t)(ks * 32) + bKsel) ^ fswz;
            uint32_t bh[4][4], bl[4][4];
#pragma unroll
            for (int ni = 0; ni < 4; ni++) {
                LDM4(bh[ni], whB + ni * 2048 + bk);
                LDM4(bl[ni], wlB + ni * 2048 + bk);
            }
#pragma unroll
            for (int mi = 0; mi < 4; mi++) {
                uint32_t ah[4];
                LDM4(ah, ahB + mi * 2048 + ak);
#pragma unroll
                for (int nj = 0; nj < 8; nj++) {
                    const int ni = nj >> 1, pr = (nj & 1) * 2;
                    MMA16816(acc[mi][nj], ah, bh[ni][pr], bh[ni][pr + 1]);
                    MMA16816(acc[mi][nj], ah, bl[ni][pr], bl[ni][pr + 1]);
                }
            }
        }
    }
    __syncthreads();

    float* C = (float*)tilesPtr;
    {
        const int r0 = wm + (lane >> 2);
        const int c0 = wn + 2 * (lane & 3);
#pragma unroll
        for (int mi = 0; mi < 4; mi++)
#pragma unroll
            for (int nj = 0; nj < 8; nj++) {
                float* p = C + (r0 + mi * 16) * CSTRIDE + c0 + nj * 8;
                p[0] = acc[mi][nj][0];
                p[1] = acc[mi][nj][1];
                p[8 * CSTRIDE]     = acc[mi][nj][2];
                p[8 * CSTRIDE + 1] = acc[mi][nj][3];
            }
    }
    __syncthreads();

    // ---- epilogue: store gx+bias AND t=0 LSTM pointwise (state=cell=0) ----
    {
        float* gxo = g_gx + (size_t)myrow * NG + n0;
        const float* Crow = C + tid * CSTRIDE;
        const float* bb = g_bias + n0;
        const int j0 = n0 >> 2;
        float* cellp = g_cell + (size_t)myrow * HID + j0;
        uint32_t sp[16];
#pragma unroll
        for (int u = 0; u < 32; u++) {
            float4 gv = *(const float4*)(Crow + u * 4);
            gv.x += bb[u * 4 + 0];
            gv.y += bb[u * 4 + 1];
            gv.z += bb[u * 4 + 2];
            gv.w += bb[u * 4 + 3];
            *(float4*)(gxo + u * 4) = gv;      // gx with bias folded in
            const float ig = sigf (gv.x);
            const float cg = tanhf(gv.z);
            const float og = sigf (gv.w);
            const float c2 = ig * cg;           // f*0 + i*c
            cellp[u] = c2;
            const float s = og * tanhf(c2);
            const uint32_t su = hfu(__float2half_rn(s));
            if (u & 1) sp[u >> 1] |= su << 16;
            else       sp[u >> 1] = su;
        }
        uint4* sh = (uint4*)(g_A1 + (size_t)myrow * HID + j0);
#pragma unroll
        for (int v = 0; v < 4; v++)
            sh[v] = make_uint4(sp[v * 4], sp[v * 4 + 1], sp[v * 4 + 2], sp[v * 4 + 3]);
    }
}

// ---------------- gates (t>=1): 512-thread 1-term fp16 GEMM -------------------
__global__ __launch_bounds__(512, 1) void k_gates(int t) {
    extern __shared__ char smem[];
    __shared__ int sRow[BM];

    const int count = g_cnt[t];
    const int m0 = blockIdx.y * BM;
    if (m0 >= count) return;
    const int n0 = blockIdx.x * BN;
    const int tid = threadIdx.x;
    const int wrp = tid >> 5;          // 0..15
    const int lane = tid & 31;

    const uint32_t sb0 = smem_u32(smem);
    const uint32_t tiles = (sb0 + 1023) & ~1023u;
    char* tilesPtr = smem + (tiles - sb0);

    const int* map = (t & 1) ? g_mapB : g_mapA;
    if (tid < BM) sRow[tid] = map[min(m0 + tid, count - 1)];
    __syncthreads();

    const __half* Ain = (t & 1) ? g_A1 : g_A0;
    __half*       Aout = (t & 1) ? g_A0 : g_A1;

    // loader split: tid<256 -> A row tid; tid>=256 -> W lines
    const int arow = tid & 255;
    const int myrow = sRow[arow];
    const char* pA = (const char*)(Ain + (size_t)myrow * HID);
    const uint32_t aswz = (uint32_t)(arow & 7) << 4;
    const uint32_t aDstRow = (uint32_t)arow * 128;
    const char* pW = (const char*)g_Wimg + (size_t)blockIdx.x * (CHUNKS * 16384);
    const int wline = tid - 256;

    auto load_chunk = [&](int c, int stage) {
        const uint32_t tb = tiles + (uint32_t)stage * G_STAGE;
        if (tid < 256) {
            const char* sa = pA + c * 128;
#pragma unroll
            for (int u = 0; u < 8; u++)
                cp16(tb + aDstRow + (((uint32_t)(u * 16)) ^ aswz), sa + u * 16);
        } else {
            const char* wc = pW + c * 16384;
#pragma unroll
            for (int q = 0; q < 4; q++) {
                const uint32_t o = (uint32_t)(wline + q * 256) << 4;
                cp16(tb + 32768 + o, wc + o);
            }
        }
        CP_COMMIT();
    };

    // warp tiling: 4m x 4n warps, warp tile 64m x 32n
    const int wm = (wrp & 3) * 64;
    const int wn = (wrp >> 2) * 32;
    const uint32_t fswz = (uint32_t)(lane & 7) << 4;
    const uint32_t aRowOff = (uint32_t)(wm + (lane & 15)) * 128;
    const uint32_t aKsel = (uint32_t)(lane >> 4) * 16;
    const uint32_t bRowOff = (uint32_t)(wn + (lane & 7) + ((lane >> 4) << 3)) * 128;
    const uint32_t bKsel = (uint32_t)((lane >> 3) & 1) * 16;

    float acc[4][4][4];
#pragma unroll
    for (int mi = 0; mi < 4; mi++)
#pragma unroll
        for (int nj = 0; nj < 4; nj++)
#pragma unroll
            for (int e = 0; e < 4; e++) acc[mi][nj][e] = 0.0f;

    load_chunk(0, 0);
    for (int c = 0; c < CHUNKS; c++) {
        const int stage = c & 1;
        CP_WAIT(0);
        __syncthreads();
        if (c + 1 < CHUNKS) load_chunk(c + 1, stage ^ 1);

        const uint32_t tb = tiles + (uint32_t)stage * G_STAGE;
        const uint32_t ahB = tb + aRowOff;
        const uint32_t whB = tb + 32768 + bRowOff;

#pragma unroll
        for (int ks = 0; ks < 4; ks++) {
            const uint32_t ak = ((uint32_t)(ks * 32) + aKsel) ^ fswz;
            const uint32_t bk = ((uint32_t)(ks * 32) + bKsel) ^ fswz;
            uint32_t bh[2][4];
#pragma unroll
            for (int ni = 0; ni < 2; ni++)
                LDM4(bh[ni], whB + ni * 2048 + bk);
#pragma unroll
            for (int mi = 0; mi < 4; mi++) {
                uint32_t ah[4];
                LDM4(ah, ahB + mi * 2048 + ak);
#pragma unroll
                for (int nj = 0; nj < 4; nj++) {
                    const int ni = nj >> 1, pr = (nj & 1) * 2;
                    MMA16816(acc[mi][nj], ah, bh[ni][pr], bh[ni][pr + 1]);
                }
            }
        }
    }
    __syncthreads();

    float* C = (float*)tilesPtr;
    {
        const int r0 = wm + (lane >> 2);
        const int c0 = wn + 2 * (lane & 3);
#pragma unroll
        for (int mi = 0; mi < 4; mi++)
#pragma unroll
            for (int nj = 0; nj < 4; nj++) {
                float* p = C + (r0 + mi * 16) * CSTRIDE + c0 + nj * 8;
                p[0] = acc[mi][nj][0];
                p[1] = acc[mi][nj][1];
                p[8 * CSTRIDE]     = acc[mi][nj][2];
                p[8 * CSTRIDE + 1] = acc[mi][nj][3];
            }
    }
    __syncthreads();

    // ---- LSTM epilogue: thread = (row = tid&255, half = tid>>8), 16 units ----
    {
        const int row = tid & 255;
        const int hlf = tid >> 8;
        if (m0 + row < count) {
            const int rowg = sRow[row];
            const float* Crow = C + row * CSTRIDE + hlf * 64;
            const float* gxp = g_gx + (size_t)rowg * NG + n0 + hlf * 64;   // bias folded
            const int j0 = (n0 >> 2) + hlf * 16;
            float* cellp = g_cell + (size_t)rowg * HID + j0;
            uint32_t sp[8];
#pragma unroll
            for (int u = 0; u < 16; u++) {
                const float4 gv = *(const float4*)(Crow + u * 4);
                const float4 xv = *(const float4*)(gxp + u * 4);
                const float ig = sigf (gv.x + xv.x);
                const float fg = sigf (gv.y + xv.y);
                const float cg = tanhf(gv.z + xv.z);
                const float og = sigf (gv.w + xv.w);
                const float c2 = fg * cellp[u] + ig * cg;
                cellp[u] = c2;
                const float s = og * tanhf(c2);
                const uint32_t su = hfu(__float2half_rn(s));
                if (u & 1) sp[u >> 1] |= su << 16;
                else       sp[u >> 1] = su;
            }
            uint4* sh = (uint4*)(Aout + (size_t)rowg * HID + j0);
            sh[0] = make_uint4(sp[0], sp[1], sp[2], sp[3]);
            sh[1] = make_uint4(sp[4], sp[5], sp[6], sp[7]);
        }
    }
}

// ---------------- head: 2-term fp16 GEMM (state @ [W1;Whalt]^T) + finalize ----
__global__ __launch_bounds__(256, 1) void k_head(int t,
                                                 const float* __restrict__ W2,
                                                 const float* __restrict__ b2,
                                                 float* __restrict__ out) {
    extern __shared__ char smem[];
    __shared__ int sRow[HBM];

    const int count = g_cnt[t];
    const int base = blockIdx.x * HBM;
    if (base >= count) return;
    const int tid = threadIdx.x;
    const int wrp = tid >> 5;
    const int lane = tid & 31;

    const uint32_t sb0 = smem_u32(smem);
    const uint32_t tiles = (sb0 + 1023) & ~1023u;
    char* tilesPtr = smem + (tiles - sb0);

    const int* map = (t & 1) ? g_mapB : g_mapA;
    int* map_next  = (t & 1) ? g_mapA : g_mapB;
    if (tid < HBM) sRow[tid] = map[min(base + tid, count - 1)];
    __syncthreads();

    // state after iter t: t even -> A1, t odd -> A0
    const __half* Astate = (t & 1) ? g_A0 : g_A1;

    const int arow = tid & 127;
    const int ug = (tid >> 7) * 4;
    const char* pA = (const char*)(Astate + (size_t)sRow[arow] * HID);
    const uint32_t aswz = (uint32_t)(arow & 7) << 4;
    const uint32_t aDstRow = (uint32_t)arow * 128;
    const char* pW = (const char*)g_W1img;

    auto load_chunk = [&](int c, int stage) {
        const uint32_t tb = tiles + (uint32_t)stage * H_STAGE;
        const char* src = pA + c * 128;
#pragma unroll
        for (int u = 0; u < 4; u++)
            cp16(tb + aDstRow + (((uint32_t)((ug + u) * 16)) ^ aswz), src + (ug + u) * 16);
        const char* w = pW + c * 36864;
#pragma unroll
        for (int q = 0; q < 9; q++) {
            const uint32_t i = (uint32_t)(tid + q * 256);
            cp16(tb + 16384 + i * 16, w + (size_t)i * 16);
        }
        CP_COMMIT();
    };

    const int wm = wrp * 16;
    const uint32_t fswz = (uint32_t)(lane & 7) << 4;
    const uint32_t aRowOff = (uint32_t)(wm + (lane & 15)) * 128;
    const uint32_t aKsel = (uint32_t)(lane >> 4) * 16;
    const uint32_t bRowOff = (uint32_t)((lane & 7) + ((lane >> 4) << 3)) * 128;
    const uint32_t bKsel = (uint32_t)((lane >> 3) & 1) * 16;

    float acc[18][4];
#pragma unroll
    for (int nj = 0; nj < 18; nj++)
#pragma unroll
        for (int e = 0; e < 4; e++) acc[nj][e] = 0.0f;

    load_chunk(0, 0);
    for (int c = 0; c < H_CHUNKS; c++) {
        const int stage = c & 1;
        CP_WAIT(0);
        __syncthreads();
        if (c + 1 < H_CHUNKS) load_chunk(c + 1, stage ^ 1);

        const uint32_t tb = tiles + (uint32_t)stage * H_STAGE;
        const uint32_t ahB = tb + aRowOff;
        const uint32_t whB = tb + 16384 + bRowOff;
        const uint32_t wlB = tb + 34816 + bRowOff;

#pragma unroll
        for (int ks = 0; ks < 4; ks++) {
            const uint32_t ak = ((uint32_t)(ks * 32) + aKsel) ^ fswz;
            const uint32_t bk = ((uint32_t)(ks * 32) + bKsel) ^ fswz;
            uint32_t ah[4], bh[9][4], bl[9][4];
            LDM4(ah, ahB + ak);
#pragma unroll
            for (int ni = 0; ni < 9; ni++) {
                LDM4(bh[ni], whB + ni * 2048 + bk);
                LDM4(bl[ni], wlB + ni * 2048 + bk);
            }
#pragma unroll
            for (int nj = 0; nj < 18; nj++) {
                const int ni = nj >> 1, pr = (nj & 1) * 2;
                MMA16816(acc[nj], ah, bh[ni][pr], bh[ni][pr + 1]);
                MMA16816(acc[nj], ah, bl[ni][pr], bl[ni][pr + 1]);
            }
        }
    }
    __syncthreads();

    float* C = (float*)tilesPtr;
    {
        const int r0 = wm + (lane >> 2);
        const int c0 = 2 * (lane & 3);
#pragma unroll
        for (int nj = 0; nj < 18; nj++) {
            float* p = C + r0 * HCS + c0 + nj * 8;
            p[0] = acc[nj][0];
            p[1] = acc[nj][1];
            p[8 * HCS]     = acc[nj][2];
            p[8 * HCS + 1] = acc[nj][3];
        }
    }
    __syncthreads();

    const float4 w2v = *(const float4*)(W2 + lane * 4);
    const float4 b1v = *(const float4*)(g_b1h + lane * 4);
    const float bhalt = g_b1h[OMID];

    for (int i = 0; i < 16; i++) {
        const int r = wm + i;
        const int mm = base + r;
        if (mm >= count) continue;
        const int rowg = sRow[r];

        const float4 mv = *(const float4*)&C[r * HCS + lane * 4];
        float acc2 = fmaxf(mv.x + b1v.x, 0.0f) * w2v.x
                   + fmaxf(mv.y + b1v.y, 0.0f) * w2v.y
                   + fmaxf(mv.z + b1v.z, 0.0f) * w2v.z
                   + fmaxf(mv.w + b1v.w, 0.0f) * w2v.w;
#pragma unroll
        for (int off = 16; off; off >>= 1)
            acc2 += __shfl_xor_sync(0xffffffffu, acc2, off);

        if (lane == 0) {
            const float o = sigf(acc2 + b2[0]);
            const float h = sigf(C[r * HCS + OMID] + bhalt);
            const float p = g_psum[rowg];
            const float pn = p + h;
            const bool fin = (pn >= 1.0f - 0.001f) || (t == MAX_IT - 1);
            const float hr = fin ? (1.0f - p) : h;
            out[rowg] += o * hr;
            g_psum[rowg] = fin ? 1.0f : pn;
            if (!fin) {
                int slot = atomicAdd(&g_cnt[t + 1], 1);
                map_next[slot] = rowg;
            }
        }
    }
}

// ---------------- launch ------------------------------------------------------
extern "C" void kernel_launch(void* const* d_in, const int* in_sizes, int n_in,
                              void* d_out, int out_size) {
    const float* x     = (const float*)d_in[0];
    const float* Wxi   = (const float*)d_in[1];
    const float* bxi   = (const float*)d_in[2];
    const float* Whi   = (const float*)d_in[3];
    const float* bhi   = (const float*)d_in[4];
    const float* Wxf   = (const float*)d_in[5];
    const float* bxf   = (const float*)d_in[6];
    const float* Whf   = (const float*)d_in[7];
    const float* bhf   = (const float*)d_in[8];
    const float* Wxc   = (const float*)d_in[9];
    const float* bxc   = (const float*)d_in[10];
    const float* Whc   = (const float*)d_in[11];
    const float* bhc   = (const float*)d_in[12];
    const float* Wxo   = (const float*)d_in[13];
    const float* bxo   = (const float*)d_in[14];
    const float* Who   = (const float*)d_in[15];
    const float* bho   = (const float*)d_in[16];
    const float* Whalt = (const float*)d_in[17];
    const float* bhalt = (const float*)d_in[18];
    const float* W1    = (const float*)d_in[19];
    const float* b1    = (const float*)d_in[20];
    const float* W2    = (const float*)d_in[21];
    const float* b2    = (const float*)d_in[22];
    float* out = (float*)d_out;

    cudaFuncSetAttribute(k_gates, cudaFuncAttributeMaxDynamicSharedMemorySize, SMEM_DYN_G);
    cudaFuncSetAttribute(k_gx,    cudaFuncAttributeMaxDynamicSharedMemorySize, SMEM_DYN_G);
    cudaFuncSetAttribute(k_head,  cudaFuncAttributeMaxDynamicSharedMemorySize, SMEM_DYN_H);

    k_init<<<B, INP>>>(x, out);

    const int tot = NG * (KA / 8) + NH_PAD * (HID / 8) + NG + OMID + 1;
    k_pack<<<(tot + 255) / 256, 256>>>(Wxi, Whi, bxi, bhi,
                                       Wxf, Whf, bxf, bhf,
                                       Wxc, Whc, bxc, bhc,
                                       Wxo, Who, bxo, bho,
                                       W1, b1, Whalt, bhalt);

    k_gx<<<dim3(NTILES, B / BM), 256, SMEM_DYN_G>>>();
    k_head<<<B / HBM, 256, SMEM_DYN_H>>>(0, W2, b2, out);

    for (int t = 1; t < MAX_IT; t++) {
        k_gates<<<dim3(NTILES, B / BM), 512, SMEM_DYN_G>>>(t);
        k_head<<<B / HBM, 256, SMEM_DYN_H>>>(t, W2, b2, out);
    }
}

// round 16
// speedup vs baseline: 5.8971x; 1.0663x over previous
#include <cuda_runtime.h>
#include <cuda_fp16.h>
#include <math.h>
#include <stdint.h>

#define B       8192
#define INP     64
#define HID     1024
#define KA      1088
#define NG      4096          // 4 gates * HID, interleaved n = j*4 + g
#define OMID    128
#define MAX_IT  8

#define BM 256
#define BN 128
#define CHUNKS 16             // state K chunks of 64
#define NTILES (NG / BN)      // 32
#define G_STAGE 49152         // A 32K + W 16K (single fp16 W)
#define SMEM_DYN_G 148480     // 3 stages 147456 dominates (C tile 135168 overlays)
#define CSTRIDE 132

// head geometry: 64 rows/CTA, 1-term fp16 W1, 3 CTAs/SM
#define HBM 64
#define NH_PAD 144
#define H_CHUNKS 16
#define H_STAGE 26624         // A 8K + W 18K
#define SMEM_DYN_H 54272      // 2 stages 53248 (C tile 37888 overlays)
#define HCS 148

// ---------------- device scratch ---------------------------------------------
__device__ __half g_A0[B * HID];            // state ping-pong (single fp16)
__device__ __half g_A1[B * HID];
__device__ __half g_x[B * INP];
__device__ float  g_cell[B * HID];
__device__ __half g_Wimg[NTILES * CHUNKS * 8192];    // state-K image, single fp16
__device__ __half g_Wx_img[NTILES * 16384];          // x-K image: [T][hi|lo] (2-term)
__device__ __half g_W1img[H_CHUNKS * NH_PAD * 64];   // head image, single fp16
__device__ float  g_gx[(size_t)B * NG];              // x @ Wx^T + bias (fp32)
__device__ float  g_bias[NG];
__device__ float  g_b1h[OMID + 2];
__device__ float  g_psum[B];
__device__ int    g_mapA[B];
__device__ int    g_mapB[B];
__device__ int    g_cnt[MAX_IT + 1];

__device__ __forceinline__ float sigf(float z) { return 1.0f / (1.0f + expf(-z)); }

// ---------------- PTX helpers (base ISA only) ---------------------------------
__device__ __forceinline__ uint32_t smem_u32(const void* p) {
    uint32_t a;
    asm("{ .reg .u64 t; cvta.to.shared.u64 t, %1; cvt.u32.u64 %0, t; }" : "=r"(a) : "l"(p));
    return a;
}
__device__ __forceinline__ void cp16(uint32_t dst, const void* src) {
    asm volatile("cp.async.cg.shared.global [%0], [%1], 16;" :: "r"(dst), "l"(src));
}
#define CP_COMMIT() asm volatile("cp.async.commit_group;" ::: "memory")
#define CP_WAIT(n)  asm volatile("cp.async.wait_group %0;" :: "n"(n) : "memory")

#define LDM4(r, addr) \
    asm volatile("ldmatrix.sync.aligned.m8n8.x4.shared.b16 {%0,%1,%2,%3}, [%4];" \
        : "=r"((r)[0]), "=r"((r)[1]), "=r"((r)[2]), "=r"((r)[3]) : "r"(addr))

#define MMA16816(acc, a, b0v, b1v) \
    asm volatile("mma.sync.aligned.m16n8k16.row.col.f32.f16.f16.f32 " \
        "{%0,%1,%2,%3}, {%4,%5,%6,%7}, {%8,%9}, {%0,%1,%2,%3};" \
        : "+f"((acc)[0]), "+f"((acc)[1]), "+f"((acc)[2]), "+f"((acc)[3]) \
        : "r"((a)[0]), "r"((a)[1]), "r"((a)[2]), "r"((a)[3]), "r"(b0v), "r"(b1v))

__device__ __forceinline__ unsigned short hfu(__half v) {
    return *reinterpret_cast<unsigned short*>(&v);
}
__device__ __forceinline__ uint4 pack8h(const float* w) {
    unsigned short hs[8];
#pragma unroll
    for (int u = 0; u < 8; u++) hs[u] = hfu(__float2half_rn(w[u]));
    return make_uint4((uint32_t)hs[0] | ((uint32_t)hs[1] << 16),
                      (uint32_t)hs[2] | ((uint32_t)hs[3] << 16),
                      (uint32_t)hs[4] | ((uint32_t)hs[5] << 16),
                      (uint32_t)hs[6] | ((uint32_t)hs[7] << 16));
}
__device__ __forceinline__ void split8h(const float* w, uint4& hv, uint4& lv) {
    unsigned short hs[8], ls[8];
#pragma unroll
    for (int u = 0; u < 8; u++) {
        __half hi = __float2half_rn(w[u]);
        __half lo = __float2half_rn(w[u] - __half2float(hi));
        hs[u] = hfu(hi); ls[u] = hfu(lo);
    }
    hv = make_uint4((uint32_t)hs[0] | ((uint32_t)hs[1] << 16),
                    (uint32_t)hs[2] | ((uint32_t)hs[3] << 16),
                    (uint32_t)hs[4] | ((uint32_t)hs[5] << 16),
                    (uint32_t)hs[6] | ((uint32_t)hs[7] << 16));
    lv = make_uint4((uint32_t)ls[0] | ((uint32_t)ls[1] << 16),
                    (uint32_t)ls[2] | ((uint32_t)ls[3] << 16),
                    (uint32_t)ls[4] | ((uint32_t)ls[5] << 16),
                    (uint32_t)ls[6] | ((uint32_t)ls[7] << 16));
}

// ---------------- init --------------------------------------------------------
__global__ void k_init(const float* __restrict__ x, float* __restrict__ out) {
    const int row = blockIdx.x;
    const int t = threadIdx.x;                 // 64 threads
    g_x[row * INP + t] = __float2half_rn(x[row * INP + t]);
    if (t == 0) {
        g_psum[row] = 0.0f;
        g_mapA[row] = row;
        out[row] = 0.0f;
    }
    if (row == 0 && t <= MAX_IT) g_cnt[t] = (t == 0) ? B : 0;
}

// ---------------- pack weights ------------------------------------------------
__global__ void k_pack(
    const float* __restrict__ Wxi, const float* __restrict__ Whi,
    const float* __restrict__ bxi, const float* __restrict__ bhi,
    const float* __restrict__ Wxf, const float* __restrict__ Whf,
    const float* __restrict__ bxf, const float* __restrict__ bhf,
    const float* __restrict__ Wxc, const float* __restrict__ Whc,
    const float* __restrict__ bxc, const float* __restrict__ bhc,
    const float* __restrict__ Wxo, const float* __restrict__ Who,
    const float* __restrict__ bxo, const float* __restrict__ bho,
    const float* __restrict__ W1,  const float* __restrict__ b1,
    const float* __restrict__ Whalt, const float* __restrict__ bhalt)
{
    int idx = blockIdx.x * blockDim.x + threadIdx.x;
    if (idx < NG * (KA / 8)) {
        const int n = idx / (KA / 8);
        const int kb = idx % (KA / 8);
        const int g = n & 3;
        const int j = n >> 2;
        const float* Wx = (g == 0) ? Wxi : (g == 1) ? Wxf : (g == 2) ? Wxc : Wxo;
        const float* Wh = (g == 0) ? Whi : (g == 1) ? Whf : (g == 2) ? Whc : Who;
        float w[8];
        if (kb < 8) {
            const float* s = Wx + j * INP + kb * 8;
#pragma unroll
            for (int u = 0; u < 8; u++) w[u] = s[u];
        } else {
            const float* s = Wh + j * HID + (kb - 8) * 8;
#pragma unroll
            for (int u = 0; u < 8; u++) w[u] = s[u];
        }
        const int T = n >> 7, nr = n & 127;
        if (kb < 8) {   // x-part image: 2-term (hi|lo)
            uint4 hv, lv;
            split8h(w, hv, lv);
            const unsigned byte = ((unsigned)(nr * 128 + kb * 16)) ^ (((unsigned)(nr & 7)) << 4);
            const unsigned off_b = (unsigned)(T * 32768) + byte;
            *(uint4*)((char*)g_Wx_img + off_b) = hv;
            *(uint4*)((char*)g_Wx_img + off_b + 16384) = lv;
        } else {        // state-part image: single fp16
            const int C = (kb - 8) >> 3, kq = (kb - 8) & 7;
            const unsigned byte = ((unsigned)(nr * 128 + kq * 16)) ^ (((unsigned)(nr & 7)) << 4);
            const unsigned off_b = (unsigned)((T * CHUNKS + C) * 16384) + byte;
            *(uint4*)((char*)g_Wimg + off_b) = pack8h(w);
        }
        return;
    }
    idx -= NG * (KA / 8);
    if (idx < NH_PAD * (HID / 8)) {            // head W1/Whalt image (single fp16)
        const int n = idx / (HID / 8);
        const int kb = idx % (HID / 8);
        float w[8];
#pragma unroll
        for (int u = 0; u < 8; u++) {
            const int k = kb * 8 + u;
            w[u] = (n < OMID) ? W1[n * HID + k] : (n == OMID ? Whalt[k] : 0.0f);
        }
        const int C = kb >> 3;
        const unsigned byte = ((unsigned)(n * 128 + (kb & 7) * 16)) ^ (((unsigned)(n & 7)) << 4);
        const unsigned off_b = (unsigned)(C * 18432) + byte;
        *(uint4*)((char*)g_W1img + off_b) = pack8h(w);
        return;
    }
    idx -= NH_PAD * (HID / 8);
    if (idx < NG) {
        const int g = idx & 3;
        const int j = idx >> 2;
        const float* bx = (g == 0) ? bxi : (g == 1) ? bxf : (g == 2) ? bxc : bxo;
        const float* bh = (g == 0) ? bhi : (g == 1) ? bhf : (g == 2) ? bhc : bho;
        g_bias[idx] = bx[j] + bh[j];
        return;
    }
    idx -= NG;
    if (idx < OMID) { g_b1h[idx] = b1[idx]; return; }
    idx -= OMID;
    if (idx == 0) g_b1h[OMID] = bhalt[0];
}

// ---------------- k_gx: gx = x @ Wx^T + bias (2-term) + fused t=0 LSTM --------
__global__ __launch_bounds__(256, 1) void k_gx() {
    extern __shared__ char smem[];
    const int m0 = blockIdx.y * BM;
    const int n0 = blockIdx.x * BN;
    const int tid = threadIdx.x;
    const int wrp = tid >> 5;
    const int lane = tid & 31;

    const uint32_t sb0 = smem_u32(smem);
    const uint32_t tiles = (sb0 + 1023) & ~1023u;
    char* tilesPtr = smem + (tiles - sb0);

    const int myrow = m0 + tid;
    const char* pA = (const char*)(g_x + (size_t)myrow * INP);
    const uint32_t aswz = (uint32_t)(tid & 7) << 4;
    const uint32_t aDstRow = (uint32_t)tid * 128;
    const char* pW = (const char*)g_Wx_img + (size_t)blockIdx.x * 32768;

    {
#pragma unroll
        for (int u = 0; u < 8; u++)
            cp16(tiles + aDstRow + (((uint32_t)(u * 16)) ^ aswz), pA + u * 16);
#pragma unroll
        for (int q = 0; q < 8; q++) {
            const uint32_t o = (uint32_t)(tid + q * 256) << 4;
            cp16(tiles + 32768 + o, pW + o);
        }
        CP_COMMIT();
    }

    const int wm = (wrp & 3) * 64;
    const int wn = (wrp >> 2) * 64;
    const uint32_t fswz = (uint32_t)(lane & 7) << 4;
    const uint32_t aRowOff = (uint32_t)(wm + (lane & 15)) * 128;
    const uint32_t aKsel = (uint32_t)(lane >> 4) * 16;
    const uint32_t bRowOff = (uint32_t)(wn + (lane & 7) + ((lane >> 4) << 3)) * 128;
    const uint32_t bKsel = (uint32_t)((lane >> 3) & 1) * 16;

    float acc[4][8][4];
#pragma unroll
    for (int mi = 0; mi < 4; mi++)
#pragma unroll
        for (int nj = 0; nj < 8; nj++)
#pragma unroll
            for (int e = 0; e < 4; e++) acc[mi][nj][e] = 0.0f;

    CP_WAIT(0);
    __syncthreads();
    {
        const uint32_t ahB = tiles + aRowOff;
        const uint32_t whB = tiles + 32768 + bRowOff;
        const uint32_t wlB = tiles + 49152 + bRowOff;
#pragma unroll
        for (int ks = 0; ks < 4; ks++) {
            const uint32_t ak = ((uint32_t)(ks * 32) + aKsel) ^ fswz;
            const uint32_t bk = ((uint32_t)(ks * 32) + bKsel) ^ fswz;
            uint32_t bh[4][4], bl[4][4];
#pragma unroll
            for (int ni = 0; ni < 4; ni++) {
                LDM4(bh[ni], whB + ni * 2048 + bk);
                LDM4(bl[ni], wlB + ni * 2048 + bk);
            }
#pragma unroll
            for (int mi = 0; mi < 4; mi++) {
                uint32_t ah[4];
                LDM4(ah, ahB + mi * 2048 + ak);
#pragma unroll
                for (int nj = 0; nj < 8; nj++) {
                    const int ni = nj >> 1, pr = (nj & 1) * 2;
                    MMA16816(acc[mi][nj], ah, bh[ni][pr], bh[ni][pr + 1]);
                    MMA16816(acc[mi][nj], ah, bl[ni][pr], bl[ni][pr + 1]);
                }
            }
        }
    }
    __syncthreads();

    float* C = (float*)tilesPtr;
    {
        const int r0 = wm + (lane >> 2);
        const int c0 = wn + 2 * (lane & 3);
#pragma unroll
        for (int mi = 0; mi < 4; mi++)
#pragma unroll
            for (int nj = 0; nj < 8; nj++) {
                float* p = C + (r0 + mi * 16) * CSTRIDE + c0 + nj * 8;
                p[0] = acc[mi][nj][0];
                p[1] = acc[mi][nj][1];
                p[8 * CSTRIDE]     = acc[mi][nj][2];
                p[8 * CSTRIDE + 1] = acc[mi][nj][3];
            }
    }
    __syncthreads();

    // ---- epilogue: store gx+bias AND t=0 LSTM pointwise (state=cell=0) ----
    {
        float* gxo = g_gx + (size_t)myrow * NG + n0;
        const float* Crow = C + tid * CSTRIDE;
        const float* bb = g_bias + n0;
        const int j0 = n0 >> 2;
        float* cellp = g_cell + (size_t)myrow * HID + j0;
        uint32_t sp[16];
#pragma unroll
        for (int u = 0; u < 32; u++) {
            float4 gv = *(const float4*)(Crow + u * 4);
            gv.x += bb[u * 4 + 0];
            gv.y += bb[u * 4 + 1];
            gv.z += bb[u * 4 + 2];
            gv.w += bb[u * 4 + 3];
            *(float4*)(gxo + u * 4) = gv;      // gx with bias folded in
            const float ig = sigf (gv.x);
            const float cg = tanhf(gv.z);
            const float og = sigf (gv.w);
            const float c2 = ig * cg;           // f*0 + i*c
            cellp[u] = c2;
            const float s = og * tanhf(c2);
            const uint32_t su = hfu(__float2half_rn(s));
            if (u & 1) sp[u >> 1] |= su << 16;
            else       sp[u >> 1] = su;
        }
        uint4* sh = (uint4*)(g_A1 + (size_t)myrow * HID + j0);
#pragma unroll
        for (int v = 0; v < 4; v++)
            sh[v] = make_uint4(sp[v * 4], sp[v * 4 + 1], sp[v * 4 + 2], sp[v * 4 + 3]);
    }
}

// ---------------- gates (t>=1): 512-thread 1-term fp16 GEMM, 3-stage ----------
__global__ __launch_bounds__(512, 1) void k_gates(int t) {
    extern __shared__ char smem[];
    __shared__ int sRow[BM];

    const int count = g_cnt[t];
    const int m0 = blockIdx.y * BM;
    if (m0 >= count) return;
    const int n0 = blockIdx.x * BN;
    const int tid = threadIdx.x;
    const int wrp = tid >> 5;          // 0..15
    const int lane = tid & 31;

    const uint32_t sb0 = smem_u32(smem);
    const uint32_t tiles = (sb0 + 1023) & ~1023u;
    char* tilesPtr = smem + (tiles - sb0);

    const int* map = (t & 1) ? g_mapB : g_mapA;
    if (tid < BM) sRow[tid] = map[min(m0 + tid, count - 1)];
    __syncthreads();

    const __half* Ain = (t & 1) ? g_A1 : g_A0;
    __half*       Aout = (t & 1) ? g_A0 : g_A1;

    // loader split: tid<256 -> A row tid; tid>=256 -> W lines
    const int arow = tid & 255;
    const int myrow = sRow[arow];
    const char* pA = (const char*)(Ain + (size_t)myrow * HID);
    const uint32_t aswz = (uint32_t)(arow & 7) << 4;
    const uint32_t aDstRow = (uint32_t)arow * 128;
    const char* pW = (const char*)g_Wimg + (size_t)blockIdx.x * (CHUNKS * 16384);
    const int wline = tid - 256;

    auto load_chunk = [&](int c, int stage) {
        const uint32_t tb = tiles + (uint32_t)stage * G_STAGE;
        if (tid < 256) {
            const char* sa = pA + c * 128;
#pragma unroll
            for (int u = 0; u < 8; u++)
                cp16(tb + aDstRow + (((uint32_t)(u * 16)) ^ aswz), sa + u * 16);
        } else {
            const char* wc = pW + c * 16384;
#pragma unroll
            for (int q = 0; q < 4; q++) {
                const uint32_t o = (uint32_t)(wline + q * 256) << 4;
                cp16(tb + 32768 + o, wc + o);
            }
        }
        CP_COMMIT();
    };

    // warp tiling: 4m x 4n warps, warp tile 64m x 32n
    const int wm = (wrp & 3) * 64;
    const int wn = (wrp >> 2) * 32;
    const uint32_t fswz = (uint32_t)(lane & 7) << 4;
    const uint32_t aRowOff = (uint32_t)(wm + (lane & 15)) * 128;
    const uint32_t aKsel = (uint32_t)(lane >> 4) * 16;
    const uint32_t bRowOff = (uint32_t)(wn + (lane & 7) + ((lane >> 4) << 3)) * 128;
    const uint32_t bKsel = (uint32_t)((lane >> 3) & 1) * 16;

    float acc[4][4][4];
#pragma unroll
    for (int mi = 0; mi < 4; mi++)
#pragma unroll
        for (int nj = 0; nj < 4; nj++)
#pragma unroll
            for (int e = 0; e < 4; e++) acc[mi][nj][e] = 0.0f;

    // 3-stage pipeline
    load_chunk(0, 0);
    load_chunk(1, 1);
    for (int c = 0; c < CHUNKS; c++) {
        const int stage = c % 3;
        if (c + 1 < CHUNKS) { CP_WAIT(1); } else { CP_WAIT(0); }
        __syncthreads();
        if (c + 2 < CHUNKS) load_chunk(c + 2, (c + 2) % 3);

        const uint32_t tb = tiles + (uint32_t)stage * G_STAGE;
        const uint32_t ahB = tb + aRowOff;
        const uint32_t whB = tb + 32768 + bRowOff;

#pragma unroll
        for (int ks = 0; ks < 4; ks++) {
            const uint32_t ak = ((uint32_t)(ks * 32) + aKsel) ^ fswz;
            const uint32_t bk = ((uint32_t)(ks * 32) + bKsel) ^ fswz;
            uint32_t bh[2][4];
#pragma unroll
            for (int ni = 0; ni < 2; ni++)
                LDM4(bh[ni], whB + ni * 2048 + bk);
#pragma unroll
            for (int mi = 0; mi < 4; mi++) {
                uint32_t ah[4];
                LDM4(ah, ahB + mi * 2048 + ak);
#pragma unroll
                for (int nj = 0; nj < 4; nj++) {
                    const int ni = nj >> 1, pr = (nj & 1) * 2;
                    MMA16816(acc[mi][nj], ah, bh[ni][pr], bh[ni][pr + 1]);
                }
            }
        }
    }
    __syncthreads();

    float* C = (float*)tilesPtr;
    {
        const int r0 = wm + (lane >> 2);
        const int c0 = wn + 2 * (lane & 3);
#pragma unroll
        for (int mi = 0; mi < 4; mi++)
#pragma unroll
            for (int nj = 0; nj < 4; nj++) {
                float* p = C + (r0 + mi * 16) * CSTRIDE + c0 + nj * 8;
                p[0] = acc[mi][nj][0];
                p[1] = acc[mi][nj][1];
                p[8 * CSTRIDE]     = acc[mi][nj][2];
                p[8 * CSTRIDE + 1] = acc[mi][nj][3];
            }
    }
    __syncthreads();

    // ---- LSTM epilogue: thread = (row = tid&255, half = tid>>8), 16 units ----
    {
        const int row = tid & 255;
        const int hlf = tid >> 8;
        if (m0 + row < count) {
            const int rowg = sRow[row];
            const float* Crow = C + row * CSTRIDE + hlf * 64;
            const float* gxp = g_gx + (size_t)rowg * NG + n0 + hlf * 64;   // bias folded
            const int j0 = (n0 >> 2) + hlf * 16;
            float* cellp = g_cell + (size_t)rowg * HID + j0;
            uint32_t sp[8];
#pragma unroll
            for (int u = 0; u < 16; u++) {
                const float4 gv = *(const float4*)(Crow + u * 4);
                const float4 xv = *(const float4*)(gxp + u * 4);
                const float ig = sigf (gv.x + xv.x);
                const float fg = sigf (gv.y + xv.y);
                const float cg = tanhf(gv.z + xv.z);
                const float og = sigf (gv.w + xv.w);
                const float c2 = fg * cellp[u] + ig * cg;
                cellp[u] = c2;
                const float s = og * tanhf(c2);
                const uint32_t su = hfu(__float2half_rn(s));
                if (u & 1) sp[u >> 1] |= su << 16;
                else       sp[u >> 1] = su;
            }
            uint4* sh = (uint4*)(Aout + (size_t)rowg * HID + j0);
            sh[0] = make_uint4(sp[0], sp[1], sp[2], sp[3]);
            sh[1] = make_uint4(sp[4], sp[5], sp[6], sp[7]);
        }
    }
}

// ---------------- head v2: 64 rows/CTA, 128 thr, 1-term fp16 W1 ---------------
__global__ __launch_bounds__(128, 3) void k_head(int t,
                                                 const float* __restrict__ W2,
                                                 const float* __restrict__ b2,
                                                 float* __restrict__ out) {
    extern __shared__ char smem[];
    __shared__ int sRow[HBM];

    const int count = g_cnt[t];
    const int base = blockIdx.x * HBM;
    if (base >= count) return;
    const int tid = threadIdx.x;       // 128
    const int wrp = tid >> 5;          // 0..3
    const int lane = tid & 31;

    const uint32_t sb0 = smem_u32(smem);
    const uint32_t tiles = (sb0 + 1023) & ~1023u;
    char* tilesPtr = smem + (tiles - sb0);

    const int* map = (t & 1) ? g_mapB : g_mapA;
    int* map_next  = (t & 1) ? g_mapA : g_mapB;
    if (tid < HBM) sRow[tid] = map[min(base + tid, count - 1)];
    __syncthreads();

    // state after iter t: t even -> A1, t odd -> A0
    const __half* Astate = (t & 1) ? g_A0 : g_A1;

    const int arow = tid & 63;
    const int ahalf = tid >> 6;        // 0,1 -> 4 lines each
    const char* pA = (const char*)(Astate + (size_t)sRow[arow] * HID);
    const uint32_t aswz = (uint32_t)(arow & 7) << 4;
    const uint32_t aDstRow = (uint32_t)arow * 128;
    const char* pW = (const char*)g_W1img;

    auto load_chunk = [&](int c, int stage) {
        const uint32_t tb = tiles + (uint32_t)stage * H_STAGE;
        const char* src = pA + c * 128;
#pragma unroll
        for (int u = 0; u < 4; u++) {
            const int line = ahalf * 4 + u;
            cp16(tb + aDstRow + (((uint32_t)(line * 16)) ^ aswz), src + line * 16);
        }
        const char* w = pW + c * 18432;
#pragma unroll
        for (int q = 0; q < 9; q++) {          // 1152 lines = 9 * 128
            const uint32_t i = (uint32_t)(tid + q * 128);
            cp16(tb + 8192 + i * 16, w + (size_t)i * 16);
        }
        CP_COMMIT();
    };

    const int wm = wrp * 16;
    const uint32_t fswz = (uint32_t)(lane & 7) << 4;
    const uint32_t aRowOff = (uint32_t)(wm + (lane & 15)) * 128;
    const uint32_t aKsel = (uint32_t)(lane >> 4) * 16;
    const uint32_t bRowOff = (uint32_t)((lane & 7) + ((lane >> 4) << 3)) * 128;
    const uint32_t bKsel = (uint32_t)((lane >> 3) & 1) * 16;

    float acc[18][4];
#pragma unroll
    for (int nj = 0; nj < 18; nj++)
#pragma unroll
        for (int e = 0; e < 4; e++) acc[nj][e] = 0.0f;

    load_chunk(0, 0);
    for (int c = 0; c < H_CHUNKS; c++) {
        const int stage = c & 1;
        CP_WAIT(0);
        __syncthreads();
        if (c + 1 < H_CHUNKS) load_chunk(c + 1, stage ^ 1);

        const uint32_t tb = tiles + (uint32_t)stage * H_STAGE;
        const uint32_t ahB = tb + aRowOff;
        const uint32_t whB = tb + 8192 + bRowOff;

#pragma unroll
        for (int ks = 0; ks < 4; ks++) {
            const uint32_t ak = ((uint32_t)(ks * 32) + aKsel) ^ fswz;
            const uint32_t bk = ((uint32_t)(ks * 32) + bKsel) ^ fswz;
            uint32_t ah[4], bh[9][4];
            LDM4(ah, ahB + ak);
#pragma unroll
            for (int ni = 0; ni < 9; ni++)
                LDM4(bh[ni], whB + ni * 2048 + bk);
#pragma unroll
            for (int nj = 0; nj < 18; nj++) {
                const int ni = nj >> 1, pr = (nj & 1) * 2;
                MMA16816(acc[nj], ah, bh[ni][pr], bh[ni][pr + 1]);
            }
        }
    }
    __syncthreads();

    float* C = (float*)tilesPtr;
    {
        const int r0 = wm + (lane >> 2);
        const int c0 = 2 * (lane & 3);
#pragma unroll
        for (int nj = 0; nj < 18; nj++) {
            float* p = C + r0 * HCS + c0 + nj * 8;
            p[0] = acc[nj][0];
            p[1] = acc[nj][1];
            p[8 * HCS]     = acc[nj][2];
            p[8 * HCS + 1] = acc[nj][3];
        }
    }
    __syncthreads();

    const float4 w2v = *(const float4*)(W2 + lane * 4);
    const float4 b1v = *(const float4*)(g_b1h + lane * 4);
    const float bhalt = g_b1h[OMID];

    for (int i = 0; i < 16; i++) {
        const int r = wm + i;
        const int mm = base + r;
        if (mm >= count) continue;
        const int rowg = sRow[r];

        const float4 mv = *(const float4*)&C[r * HCS + lane * 4];
        float acc2 = fmaxf(mv.x + b1v.x, 0.0f) * w2v.x
                   + fmaxf(mv.y + b1v.y, 0.0f) * w2v.y
                   + fmaxf(mv.z + b1v.z, 0.0f) * w2v.z
                   + fmaxf(mv.w + b1v.w, 0.0f) * w2v.w;
#pragma unroll
        for (int off = 16; off; off >>= 1)
            acc2 += __shfl_xor_sync(0xffffffffu, acc2, off);

        if (lane == 0) {
            const float o = sigf(acc2 + b2[0]);
            const float h = sigf(C[r * HCS + OMID] + bhalt);
            const float p = g_psum[rowg];
            const float pn = p + h;
            const bool fin = (pn >= 1.0f - 0.001f) || (t == MAX_IT - 1);
            const float hr = fin ? (1.0f - p) : h;
            out[rowg] += o * hr;
            g_psum[rowg] = fin ? 1.0f : pn;
            if (!fin) {
                int slot = atomicAdd(&g_cnt[t + 1], 1);
                map_next[slot] = rowg;
            }
        }
    }
}

// ---------------- launch ------------------------------------------------------
extern "C" void kernel_launch(void* const* d_in, const int* in_sizes, int n_in,
                              void* d_out, int out_size) {
    const float* x     = (const float*)d_in[0];
    const float* Wxi   = (const float*)d_in[1];
    const float* bxi   = (const float*)d_in[2];
    const float* Whi   = (const float*)d_in[3];
    const float* bhi   = (const float*)d_in[4];
    const float* Wxf   = (const float*)d_in[5];
    const float* bxf   = (const float*)d_in[6];
    const float* Whf   = (const float*)d_in[7];
    const float* bhf   = (const float*)d_in[8];
    const float* Wxc   = (const float*)d_in[9];
    const float* bxc   = (const float*)d_in[10];
    const float* Whc   = (const float*)d_in[11];
    const float* bhc   = (const float*)d_in[12];
    const float* Wxo   = (const float*)d_in[13];
    const float* bxo   = (const float*)d_in[14];
    const float* Who   = (const float*)d_in[15];
    const float* bho   = (const float*)d_in[16];
    const float* Whalt = (const float*)d_in[17];
    const float* bhalt = (const float*)d_in[18];
    const float* W1    = (const float*)d_in[19];
    const float* b1    = (const float*)d_in[20];
    const float* W2    = (const float*)d_in[21];
    const float* b2    = (const float*)d_in[22];
    float* out = (float*)d_out;

    cudaFuncSetAttribute(k_gates, cudaFuncAttributeMaxDynamicSharedMemorySize, SMEM_DYN_G);
    cudaFuncSetAttribute(k_gx,    cudaFuncAttributeMaxDynamicSharedMemorySize, SMEM_DYN_G);
    cudaFuncSetAttribute(k_head,  cudaFuncAttributeMaxDynamicSharedMemorySize, SMEM_DYN_H);

    k_init<<<B, INP>>>(x, out);

    const int tot = NG * (KA / 8) + NH_PAD * (HID / 8) + NG + OMID + 1;
    k_pack<<<(tot + 255) / 256, 256>>>(Wxi, Whi, bxi, bhi,
                                       Wxf, Whf, bxf, bhf,
                                       Wxc, Whc, bxc, bhc,
                                       Wxo, Who, bxo, bho,
                                       W1, b1, Whalt, bhalt);

    k_gx<<<dim3(NTILES, B / BM), 256, SMEM_DYN_G>>>();
    k_head<<<B / HBM, 128, SMEM_DYN_H>>>(0, W2, b2, out);

    for (int t = 1; t < MAX_IT; t++) {
        k_gates<<<dim3(NTILES, B / BM), 512, SMEM_DYN_G>>>(t);
        k_head<<<B / HBM, 128, SMEM_DYN_H>>>(t, W2, b2, out);
    }
}